// round 10
// baseline (speedup 1.0000x reference)
#include <cuda_runtime.h>
#include <cuda_bf16.h>
#include <math.h>
#include <stdint.h>

#define BATCH 4
#define CC 256
#define CI 128
#define NPIX 2304
#define BNEPS 1e-5f
#define NCHUNK 18
#define ETSPLIT 18

// ---------------- scratch ----------------
__device__ float g_PRE[4][BATCH][CI*NPIX];
__device__ float g_ETpart[BATCH][ETSPLIT][CI*CI];
__device__ uint32_t g_Apack[2][BATCH][2][CI*64];   // [zi][b][hi/lo][m*64+k2]
__device__ float g_E[BATCH][NPIX*NPIX];
__device__ float g_Z[2][BATCH][CI*NPIX];
__device__ float g_rowmax[BATCH][NPIX];
__device__ float g_rowrsum[BATCH][NPIX];
__device__ float g_pmax[BATCH][NCHUNK][NPIX];
__device__ float g_psum[BATCH][NCHUNK][NPIX];
__device__ float g_WpreH[4][CI*CC];
__device__ float g_WpreL[4][CI*CC];
__device__ float g_bpre[4][CI];
__device__ float g_Wpost[2][CC*CI];
__device__ float g_bpost[2][CC];

// ---------------- helpers ----------------
__device__ __forceinline__ uint32_t pack_bf(float e, float o) {
    uint32_t r;
    asm("cvt.rn.bf16x2.f32 %0, %1, %2;" : "=r"(r) : "f"(o), "f"(e));
    return r;
}
__device__ __forceinline__ float bf_round(float x) {
    return __bfloat162float(__float2bfloat16(x));
}
__device__ __forceinline__ void mma16bf(float c[4], const uint32_t a[4], const uint32_t b[2]) {
    asm volatile(
        "mma.sync.aligned.m16n8k16.row.col.f32.bf16.bf16.f32 "
        "{%0,%1,%2,%3}, {%4,%5,%6,%7}, {%8,%9}, {%0,%1,%2,%3};"
        : "+f"(c[0]), "+f"(c[1]), "+f"(c[2]), "+f"(c[3])
        : "r"(a[0]), "r"(a[1]), "r"(a[2]), "r"(a[3]), "r"(b[0]), "r"(b[1]));
}
__device__ __forceinline__ void split_pack(float e, float o, uint32_t& hp, uint32_t& lp) {
    float eh = bf_round(e), oh = bf_round(o);
    hp = pack_bf(eh, oh);
    lp = pack_bf(e - eh, o - oh);
}

// ======================================================================
// k_fold (R9)
// ======================================================================
__global__ void __launch_bounds__(256) k_fold(
    const float* __restrict__ bn_pre, const float* __restrict__ w_pre,
    const float* __restrict__ b_pre, const float* __restrict__ w_post,
    const float* __restrict__ b_post, const float* __restrict__ bn_post)
{
    int w = blockIdx.x * 8 + (threadIdx.x >> 5);
    int lane = threadIdx.x & 31;
    if (w < 512) {
        int i = w >> 7, o = w & 127;
        const float* bp = bn_pre + i * 4 * CC;
        const float* wr = w_pre + (i * CI + o) * CC;
        float acc = 0.f;
        for (int c = lane; c < CC; c += 32) {
            float s = bp[c] * rsqrtf(bp[3 * CC + c] + BNEPS);
            float t = bp[CC + c] - bp[2 * CC + c] * s;
            float wv = wr[c] * s;
            float h = bf_round(wv);
            g_WpreH[i][o * CC + c] = h;
            g_WpreL[i][o * CC + c] = wv - h;
            acc = fmaf(wr[c], t, acc);
        }
#pragma unroll
        for (int off = 16; off; off >>= 1) acc += __shfl_xor_sync(0xffffffffu, acc, off);
        if (lane == 0) g_bpre[i][o] = acc + b_pre[i * CI + o];
    } else {
        int w2 = w - 512;
        int i = w2 >> 8, o = w2 & 255;
        const float* bp = bn_post + i * 4 * CC;
        float s = bp[o] * rsqrtf(bp[3 * CC + o] + BNEPS);
        const float* wr = w_post + (i * CC + o) * CI;
        for (int c = lane; c < CI; c += 32)
            g_Wpost[i][o * CI + c] = wr[c] * s;
        if (lane == 0)
            g_bpost[i][o] = b_post[i * CC + o] * s + bp[CC + o] - bp[2 * CC + o] * s;
    }
}

// ======================================================================
// pre body (R9)
// ======================================================================
__device__ __forceinline__ void pre_body(uint32_t* pool, int i, int b, int n0,
                                         const float* __restrict__ x1,
                                         const float* __restrict__ x2)
{
    uint32_t* Ah = pool;
    uint32_t* Al = pool + 2560;
    uint32_t* Bh = pool + 5120;
    uint32_t* Bl = pool + 6272;
    const float* __restrict__ AHf = g_WpreH[i];
    const float* __restrict__ ALf = g_WpreL[i];
    const float* __restrict__ Bsrc = ((i & 1) ? x2 : x1) + b * CC * NPIX;

    int tid = threadIdx.x;
    int wid = tid >> 5, lane = tid & 31;
    int g = lane >> 2, tig = lane & 3;
    int wm = (wid & 3) * 32, wn = (wid >> 2) * 32;

    int am = tid >> 2, akq = (tid & 3) * 8;
    int bk2 = tid >> 4, bn4 = (tid & 15) * 4;

    float4 sh0[2], sh1[2], sl0[2], sl1[2], sbe, sbo;
    float c[2][4][4] = {};

    auto loadT = [&](int k0) {
#pragma unroll
        for (int it = 0; it < 2; it++) {
            int m = am + it * 64;
            sh0[it] = *(const float4*)&AHf[m * CC + k0 + akq];
            sh1[it] = *(const float4*)&AHf[m * CC + k0 + akq + 4];
            sl0[it] = *(const float4*)&ALf[m * CC + k0 + akq];
            sl1[it] = *(const float4*)&ALf[m * CC + k0 + akq + 4];
        }
        const float* be = &Bsrc[(k0 + 2 * bk2) * NPIX + n0 + bn4];
        sbe = *(const float4*)be;
        sbo = *(const float4*)(be + NPIX);
    };
    auto storeT = [&]() {
#pragma unroll
        for (int it = 0; it < 2; it++) {
            int m = am + it * 64, kq2 = akq >> 1;
            *(uint4*)&Ah[m * 20 + kq2] = make_uint4(
                pack_bf(sh0[it].x, sh0[it].y), pack_bf(sh0[it].z, sh0[it].w),
                pack_bf(sh1[it].x, sh1[it].y), pack_bf(sh1[it].z, sh1[it].w));
            *(uint4*)&Al[m * 20 + kq2] = make_uint4(
                pack_bf(sl0[it].x, sl0[it].y), pack_bf(sl0[it].z, sl0[it].w),
                pack_bf(sl1[it].x, sl1[it].y), pack_bf(sl1[it].z, sl1[it].w));
        }
        uint32_t h0,l0,h1,l1,h2,l2,h3,l3;
        split_pack(sbe.x, sbo.x, h0, l0); split_pack(sbe.y, sbo.y, h1, l1);
        split_pack(sbe.z, sbo.z, h2, l2); split_pack(sbe.w, sbo.w, h3, l3);
        *(uint4*)&Bh[bk2 * 72 + bn4] = make_uint4(h0, h1, h2, h3);
        *(uint4*)&Bl[bk2 * 72 + bn4] = make_uint4(l0, l1, l2, l3);
    };

    loadT(0); storeT(); __syncthreads();
    for (int t = 0; t < 8; t++) {
        if (t < 7) loadT((t + 1) * 32);
#pragma unroll
        for (int kk2 = 0; kk2 < 16; kk2 += 8) {
            uint32_t ah[2][4], al[2][4];
#pragma unroll
            for (int mi = 0; mi < 2; mi++) {
                int mr = wm + mi * 16;
                ah[mi][0]=Ah[(mr+g  )*20+kk2+tig  ]; ah[mi][1]=Ah[(mr+g+8)*20+kk2+tig  ];
                ah[mi][2]=Ah[(mr+g  )*20+kk2+tig+4]; ah[mi][3]=Ah[(mr+g+8)*20+kk2+tig+4];
                al[mi][0]=Al[(mr+g  )*20+kk2+tig  ]; al[mi][1]=Al[(mr+g+8)*20+kk2+tig  ];
                al[mi][2]=Al[(mr+g  )*20+kk2+tig+4]; al[mi][3]=Al[(mr+g+8)*20+kk2+tig+4];
            }
#pragma unroll
            for (int ni = 0; ni < 4; ni++) {
                uint32_t bh[2], bl[2];
                bh[0]=Bh[(kk2+tig  )*72+wn+ni*8+g]; bh[1]=Bh[(kk2+tig+4)*72+wn+ni*8+g];
                bl[0]=Bl[(kk2+tig  )*72+wn+ni*8+g]; bl[1]=Bl[(kk2+tig+4)*72+wn+ni*8+g];
#pragma unroll
                for (int mi = 0; mi < 2; mi++) {
                    mma16bf(c[mi][ni], ah[mi], bh);
                    mma16bf(c[mi][ni], ah[mi], bl);
                    mma16bf(c[mi][ni], al[mi], bh);
                }
            }
        }
        __syncthreads();
        if (t < 7) storeT();
        __syncthreads();
    }

    float* Cout = g_PRE[i][b];
#pragma unroll
    for (int mi = 0; mi < 2; mi++) {
#pragma unroll
        for (int ni = 0; ni < 4; ni++) {
            int row = wm + mi * 16 + g;
            int col = n0 + wn + ni * 8 + tig * 2;
            float b0 = g_bpre[i][row], b1 = g_bpre[i][row + 8];
            *(float2*)&Cout[row * NPIX + col] =
                make_float2(c[mi][ni][0] + b0, c[mi][ni][1] + b0);
            *(float2*)&Cout[(row + 8) * NPIX + col] =
                make_float2(c[mi][ni][2] + b1, c[mi][ni][3] + b1);
        }
    }
}

__global__ void __launch_bounds__(256) k_pre23(const float* __restrict__ x1,
                                               const float* __restrict__ x2)
{
    __shared__ uint32_t pool[7424];
    int i = 2 + (blockIdx.z >> 2), b = blockIdx.z & 3;
    pre_body(pool, i, b, blockIdx.x * 64, x1, x2);
}

// ======================================================================
// etime body (R9)
// ======================================================================
__device__ __forceinline__ void etime_body(uint32_t* pool, int b, int ks, int n0)
{
    uint32_t* Ah = pool;
    uint32_t* Al = pool + 2560;
    uint32_t* Bh = pool + 5120;
    uint32_t* Bl = pool + 6400;
    int kbeg = ks * (NPIX / ETSPLIT);
    const float* __restrict__ Tm = g_PRE[2][b];
    const float* __restrict__ Pm = g_PRE[3][b];

    int tid = threadIdx.x;
    int wid = tid >> 5, lane = tid & 31;
    int g = lane >> 2, tig = lane & 3;
    int wm = (wid & 3) * 32, wn = (wid >> 2) * 32;

    int am = tid >> 1, ak = (tid & 1) * 16;
    int bn = tid >> 2, bk = (tid & 3) * 8;

    float4 sA[4], sB[2];
    float c[2][4][4] = {};

    auto loadT = [&](int k0) {
#pragma unroll
        for (int q = 0; q < 4; q++) sA[q] = *(const float4*)&Tm[am * NPIX + k0 + ak + q * 4];
#pragma unroll
        for (int q = 0; q < 2; q++) sB[q] = *(const float4*)&Pm[(n0 + bn) * NPIX + k0 + bk + q * 4];
    };
    auto storeT = [&]() {
#pragma unroll
        for (int q = 0; q < 4; q++) {
            uint32_t h0,l0,h1,l1;
            split_pack(sA[q].x, sA[q].y, h0, l0);
            split_pack(sA[q].z, sA[q].w, h1, l1);
            int k2 = (ak >> 1) + q * 2;
            Ah[am * 20 + k2] = h0; Ah[am * 20 + k2 + 1] = h1;
            Al[am * 20 + k2] = l0; Al[am * 20 + k2 + 1] = l1;
        }
#pragma unroll
        for (int q = 0; q < 2; q++) {
            uint32_t h0,l0,h1,l1;
            split_pack(sB[q].x, sB[q].y, h0, l0);
            split_pack(sB[q].z, sB[q].w, h1, l1);
            int k2 = (bk >> 1) + q * 2;
            Bh[bn * 20 + k2] = h0; Bh[bn * 20 + k2 + 1] = h1;
            Bl[bn * 20 + k2] = l0; Bl[bn * 20 + k2 + 1] = l1;
        }
    };

    loadT(kbeg); storeT(); __syncthreads();
    for (int t = 0; t < 4; t++) {
        if (t < 3) loadT(kbeg + (t + 1) * 32);
#pragma unroll
        for (int kk2 = 0; kk2 < 16; kk2 += 8) {
            uint32_t ah[2][4], al[2][4];
#pragma unroll
            for (int mi = 0; mi < 2; mi++) {
                int mr = wm + mi * 16;
                ah[mi][0]=Ah[(mr+g  )*20+kk2+tig  ]; ah[mi][1]=Ah[(mr+g+8)*20+kk2+tig  ];
                ah[mi][2]=Ah[(mr+g  )*20+kk2+tig+4]; ah[mi][3]=Ah[(mr+g+8)*20+kk2+tig+4];
                al[mi][0]=Al[(mr+g  )*20+kk2+tig  ]; al[mi][1]=Al[(mr+g+8)*20+kk2+tig  ];
                al[mi][2]=Al[(mr+g  )*20+kk2+tig+4]; al[mi][3]=Al[(mr+g+8)*20+kk2+tig+4];
            }
#pragma unroll
            for (int ni = 0; ni < 4; ni++) {
                int nr = wn + ni * 8 + g;
                uint32_t bh[2], bl[2];
                bh[0]=Bh[nr*20+kk2+tig]; bh[1]=Bh[nr*20+kk2+tig+4];
                bl[0]=Bl[nr*20+kk2+tig]; bl[1]=Bl[nr*20+kk2+tig+4];
#pragma unroll
                for (int mi = 0; mi < 2; mi++) {
                    mma16bf(c[mi][ni], ah[mi], bh);
                    mma16bf(c[mi][ni], ah[mi], bl);
                    mma16bf(c[mi][ni], al[mi], bh);
                }
            }
        }
        __syncthreads();
        if (t < 3) storeT();
        __syncthreads();
    }

    float* outp = g_ETpart[b][ks];
#pragma unroll
    for (int mi = 0; mi < 2; mi++) {
#pragma unroll
        for (int ni = 0; ni < 4; ni++) {
            int row = wm + mi * 16 + g;
            int col = n0 + wn + ni * 8 + tig * 2;
            *(float2*)&outp[row * CI + col]       = make_float2(c[mi][ni][0], c[mi][ni][1]);
            *(float2*)&outp[(row + 8) * CI + col] = make_float2(c[mi][ni][2], c[mi][ni][3]);
        }
    }
}

// ======================================================================
// espace body (R9)
// ======================================================================
__device__ __forceinline__ void espace_body(uint32_t* pool, int b, int row0, int col0)
{
    uint32_t* Ah = pool;
    uint32_t* Al = pool + 2176;
    uint32_t* Bh = pool + 4352;
    uint32_t* Bl = pool + 5504;
    const float* __restrict__ T = g_PRE[2][b];
    const float* __restrict__ P = g_PRE[3][b];

    int tid = threadIdx.x;
    int wid = tid >> 5, lane = tid & 31;
    int g = lane >> 2, tig = lane & 3;
    int wm = (wid & 3) * 32, wn = (wid >> 2) * 32;

    int ak2 = tid >> 5, an4 = (tid & 31) * 4;
    int bk2 = tid >> 4, bm4 = (tid & 15) * 4;

    float4 sAe[2], sAo[2], sBe, sBo;
    float c[2][4][4] = {};

    auto loadT = [&](int k0) {
#pragma unroll
        for (int it = 0; it < 2; it++) {
            const float* te = &T[(k0 + 2 * (ak2 + it * 8)) * NPIX + row0 + an4];
            sAe[it] = *(const float4*)te;
            sAo[it] = *(const float4*)(te + NPIX);
        }
        const float* pe = &P[(k0 + 2 * bk2) * NPIX + col0 + bm4];
        sBe = *(const float4*)pe;
        sBo = *(const float4*)(pe + NPIX);
    };
    auto storeT = [&]() {
#pragma unroll
        for (int it = 0; it < 2; it++) {
            uint32_t h0,l0,h1,l1,h2,l2,h3,l3;
            split_pack(sAe[it].x, sAo[it].x, h0, l0); split_pack(sAe[it].y, sAo[it].y, h1, l1);
            split_pack(sAe[it].z, sAo[it].z, h2, l2); split_pack(sAe[it].w, sAo[it].w, h3, l3);
            int r = ak2 + it * 8;
            *(uint4*)&Ah[r * 136 + an4] = make_uint4(h0, h1, h2, h3);
            *(uint4*)&Al[r * 136 + an4] = make_uint4(l0, l1, l2, l3);
        }
        uint32_t h0,l0,h1,l1,h2,l2,h3,l3;
        split_pack(sBe.x, sBo.x, h0, l0); split_pack(sBe.y, sBo.y, h1, l1);
        split_pack(sBe.z, sBo.z, h2, l2); split_pack(sBe.w, sBo.w, h3, l3);
        *(uint4*)&Bh[bk2 * 72 + bm4] = make_uint4(h0, h1, h2, h3);
        *(uint4*)&Bl[bk2 * 72 + bm4] = make_uint4(l0, l1, l2, l3);
    };

    loadT(0); storeT(); __syncthreads();
    for (int t = 0; t < 4; t++) {
        if (t < 3) loadT((t + 1) * 32);
#pragma unroll
        for (int kk2 = 0; kk2 < 16; kk2 += 8) {
            uint32_t ah[2][4], al[2][4];
#pragma unroll
            for (int mi = 0; mi < 2; mi++) {
                int mr = wm + mi * 16;
                ah[mi][0] = Ah[(kk2+tig  )*136 + mr + g    ];
                ah[mi][1] = Ah[(kk2+tig  )*136 + mr + g + 8];
                ah[mi][2] = Ah[(kk2+tig+4)*136 + mr + g    ];
                ah[mi][3] = Ah[(kk2+tig+4)*136 + mr + g + 8];
                al[mi][0] = Al[(kk2+tig  )*136 + mr + g    ];
                al[mi][1] = Al[(kk2+tig  )*136 + mr + g + 8];
                al[mi][2] = Al[(kk2+tig+4)*136 + mr + g    ];
                al[mi][3] = Al[(kk2+tig+4)*136 + mr + g + 8];
            }
#pragma unroll
            for (int ni = 0; ni < 4; ni++) {
                uint32_t bh[2], bl[2];
                bh[0] = Bh[(kk2+tig  )*72 + wn + ni*8 + g];
                bh[1] = Bh[(kk2+tig+4)*72 + wn + ni*8 + g];
                bl[0] = Bl[(kk2+tig  )*72 + wn + ni*8 + g];
                bl[1] = Bl[(kk2+tig+4)*72 + wn + ni*8 + g];
#pragma unroll
                for (int mi = 0; mi < 2; mi++) {
                    mma16bf(c[mi][ni], ah[mi], bh);
                    mma16bf(c[mi][ni], ah[mi], bl);
                    mma16bf(c[mi][ni], al[mi], bh);
                }
            }
        }
        __syncthreads();
        if (t < 3) storeT();
        __syncthreads();
    }

    float* Ep = g_E[b];
#pragma unroll
    for (int mi = 0; mi < 2; mi++) {
#pragma unroll
        for (int ni = 0; ni < 4; ni++) {
            int row = row0 + wm + mi * 16 + g;
            int col = col0 + wn + ni * 8 + tig * 2;
            *(float2*)&Ep[row * NPIX + col]       = make_float2(c[mi][ni][0], c[mi][ni][1]);
            *(float2*)&Ep[(row + 8) * NPIX + col] = make_float2(c[mi][ni][2], c[mi][ni][3]);
        }
    }
}

// ======================================================================
// BIG3 (longest-first): pre01 (288) | etime (144) | espace (2592)
// ======================================================================
__global__ void __launch_bounds__(256) k_big3(const float* __restrict__ x1,
                                              const float* __restrict__ x2)
{
    __shared__ uint32_t pool[7680];
    int bx = blockIdx.x;
    if (bx < 288) {
        int x = bx % 36, iz = bx / 36;
        pre_body(pool, iz >> 2, iz & 3, x * 64, x1, x2);
    } else if (bx < 432) {
        int idx = bx - 288;
        int x = idx % 2, ks = (idx / 2) % 18, b = idx / 36;
        etime_body(pool, b, ks, x * 64);
    } else {
        int idx = bx - 432;
        int x = idx % 36, y = (idx / 36) % 18, b = idx / 648;
        espace_body(pool, b, y * 128, x * 64);
    }
}

// ======================================================================
// k_softA: fused etreduce + time-softmax, packed bf16 hi/lo output.
// grid (2, BATCH): blockIdx.x==0 -> A2 (row softmax), ==1 -> A1 (col).
// ======================================================================
__global__ void __launch_bounds__(256) k_softA()
{
    int b = blockIdx.y, orient = blockIdx.x;
    int tid = threadIdx.x, wid = tid >> 5, lane = tid & 31;
    __shared__ float ETs[128][33];

    if (orient == 0) {
        // A2[t][d]: row softmax, coalesced reads
        for (int t = wid; t < 128; t += 8) {
            float v[4];
#pragma unroll
            for (int j = 0; j < 4; j++) {
                int d = lane + j * 32;
                float s = 0.f;
#pragma unroll
                for (int p = 0; p < ETSPLIT; p++) s += g_ETpart[b][p][t * CI + d];
                v[j] = s;
            }
            float mx = fmaxf(fmaxf(v[0], v[1]), fmaxf(v[2], v[3]));
#pragma unroll
            for (int off = 16; off; off >>= 1) mx = fmaxf(mx, __shfl_xor_sync(0xffffffffu, mx, off));
            float e[4]; float sum = 0.f;
#pragma unroll
            for (int j = 0; j < 4; j++) { e[j] = __expf(v[j] - mx); sum += e[j]; }
#pragma unroll
            for (int off = 16; off; off >>= 1) sum += __shfl_xor_sync(0xffffffffu, sum, off);
            float rs = 1.f / sum;
#pragma unroll
            for (int j = 0; j < 4; j++) {
                float own = e[j] * rs;
                float part = __shfl_xor_sync(0xffffffffu, own, 1);
                if (!(lane & 1)) {
                    float oh = bf_round(own), ph = bf_round(part);
                    int k2 = (lane >> 1) + 16 * j;
                    g_Apack[1][b][0][t * 64 + k2] = pack_bf(oh, ph);
                    g_Apack[1][b][1][t * 64 + k2] = pack_bf(own - oh, part - ph);
                }
            }
        }
    } else {
        // A1[c][d] = colsoftmax: exp(ET[d][c]-max_d)/sum; tile-transpose via smem
        for (int strip = 0; strip < 4; strip++) {
            int c0 = strip * 32;
            for (int idx = tid; idx < 128 * 32; idx += 256) {
                int d = idx >> 5, cc = idx & 31;
                float s = 0.f;
#pragma unroll
                for (int p = 0; p < ETSPLIT; p++) s += g_ETpart[b][p][d * CI + c0 + cc];
                ETs[d][cc] = s;
            }
            __syncthreads();
            for (int ci = wid; ci < 32; ci += 8) {
                int ccol = c0 + ci;
                float v[4];
#pragma unroll
                for (int j = 0; j < 4; j++) v[j] = ETs[lane + 32 * j][ci];
                float mx = fmaxf(fmaxf(v[0], v[1]), fmaxf(v[2], v[3]));
#pragma unroll
                for (int off = 16; off; off >>= 1) mx = fmaxf(mx, __shfl_xor_sync(0xffffffffu, mx, off));
                float e[4]; float sum = 0.f;
#pragma unroll
                for (int j = 0; j < 4; j++) { e[j] = __expf(v[j] - mx); sum += e[j]; }
#pragma unroll
                for (int off = 16; off; off >>= 1) sum += __shfl_xor_sync(0xffffffffu, sum, off);
                float rs = 1.f / sum;
#pragma unroll
                for (int j = 0; j < 4; j++) {
                    float own = e[j] * rs;
                    float part = __shfl_xor_sync(0xffffffffu, own, 1);
                    if (!(lane & 1)) {
                        float oh = bf_round(own), ph = bf_round(part);
                        int k2 = (lane >> 1) + 16 * j;
                        g_Apack[0][b][0][ccol * 64 + k2] = pack_bf(oh, ph);
                        g_Apack[0][b][1][ccol * 64 + k2] = pack_bf(own - oh, part - ph);
                    }
                }
            }
            __syncthreads();
        }
    }
}

// ======================================================================
// zgemm body: 3-term bf16, packed A from g_Apack, B split from g_PRE
// ======================================================================
__device__ __forceinline__ void zgemm_body(uint32_t* pool, int zi, int b, int n0)
{
    uint32_t* Ah = pool;
    uint32_t* Al = pool + 2560;
    uint32_t* Bh = pool + 5120;
    uint32_t* Bl = pool + 6272;
    const uint32_t* __restrict__ AhG = g_Apack[zi][b][0];
    const uint32_t* __restrict__ AlG = g_Apack[zi][b][1];
    const float* __restrict__ Bsrc = g_PRE[zi][b];

    int tid = threadIdx.x;
    int wid = tid >> 5, lane = tid & 31;
    int g = lane >> 2, tig = lane & 3;
    int wm = (wid & 3) * 32, wn = (wid >> 2) * 32;

    int am = tid >> 1, half8 = (tid & 1) * 8;
    int bk2 = tid >> 4, bn4 = (tid & 15) * 4;

    uint4 sAh0, sAh1, sAl0, sAl1;
    float4 sbe, sbo;
    float c[2][4][4] = {};

    auto loadT = [&](int k0) {
        int k2b = (k0 >> 1) + half8;
        sAh0 = *(const uint4*)&AhG[am * 64 + k2b];
        sAh1 = *(const uint4*)&AhG[am * 64 + k2b + 4];
        sAl0 = *(const uint4*)&AlG[am * 64 + k2b];
        sAl1 = *(const uint4*)&AlG[am * 64 + k2b + 4];
        const float* be = &Bsrc[(k0 + 2 * bk2) * NPIX + n0 + bn4];
        sbe = *(const float4*)be;
        sbo = *(const float4*)(be + NPIX);
    };
    auto storeT = [&]() {
        *(uint4*)&Ah[am * 20 + half8]     = sAh0;
        *(uint4*)&Ah[am * 20 + half8 + 4] = sAh1;
        *(uint4*)&Al[am * 20 + half8]     = sAl0;
        *(uint4*)&Al[am * 20 + half8 + 4] = sAl1;
        uint32_t h0,l0,h1,l1,h2,l2,h3,l3;
        split_pack(sbe.x, sbo.x, h0, l0); split_pack(sbe.y, sbo.y, h1, l1);
        split_pack(sbe.z, sbo.z, h2, l2); split_pack(sbe.w, sbo.w, h3, l3);
        *(uint4*)&Bh[bk2 * 72 + bn4] = make_uint4(h0, h1, h2, h3);
        *(uint4*)&Bl[bk2 * 72 + bn4] = make_uint4(l0, l1, l2, l3);
    };

    loadT(0); storeT(); __syncthreads();
    for (int t = 0; t < 4; t++) {
        if (t < 3) loadT((t + 1) * 32);
#pragma unroll
        for (int kk2 = 0; kk2 < 16; kk2 += 8) {
            uint32_t ah[2][4], al[2][4];
#pragma unroll
            for (int mi = 0; mi < 2; mi++) {
                int mr = wm + mi * 16;
                ah[mi][0]=Ah[(mr+g  )*20+kk2+tig  ]; ah[mi][1]=Ah[(mr+g+8)*20+kk2+tig  ];
                ah[mi][2]=Ah[(mr+g  )*20+kk2+tig+4]; ah[mi][3]=Ah[(mr+g+8)*20+kk2+tig+4];
                al[mi][0]=Al[(mr+g  )*20+kk2+tig  ]; al[mi][1]=Al[(mr+g+8)*20+kk2+tig  ];
                al[mi][2]=Al[(mr+g  )*20+kk2+tig+4]; al[mi][3]=Al[(mr+g+8)*20+kk2+tig+4];
            }
#pragma unroll
            for (int ni = 0; ni < 4; ni++) {
                uint32_t bh[2], bl[2];
                bh[0]=Bh[(kk2+tig  )*72+wn+ni*8+g]; bh[1]=Bh[(kk2+tig+4)*72+wn+ni*8+g];
                bl[0]=Bl[(kk2+tig  )*72+wn+ni*8+g]; bl[1]=Bl[(kk2+tig+4)*72+wn+ni*8+g];
#pragma unroll
                for (int mi = 0; mi < 2; mi++) {
                    mma16bf(c[mi][ni], ah[mi], bh);
                    mma16bf(c[mi][ni], ah[mi], bl);
                    mma16bf(c[mi][ni], al[mi], bh);
                }
            }
        }
        __syncthreads();
        if (t < 3) storeT();
        __syncthreads();
    }

    float* Zout = g_Z[zi][b];
#pragma unroll
    for (int mi = 0; mi < 2; mi++) {
#pragma unroll
        for (int ni = 0; ni < 4; ni++) {
            int row = wm + mi * 16 + g;
            int col = n0 + wn + ni * 8 + tig * 2;
            *(float2*)&Zout[row * NPIX + col]       = make_float2(c[mi][ni][0], c[mi][ni][1]);
            *(float2*)&Zout[(row + 8) * NPIX + col] = make_float2(c[mi][ni][2], c[mi][ni][3]);
        }
    }
}

// ---------------- stats bodies (R9) ----------------
__device__ __forceinline__ void colpart_body(int b, int ch, int m)
{
    const float* Ep = g_E[b];
    float mx = -3.0e38f, s = 0.f;
    int n0 = ch * (NPIX / NCHUNK);
    for (int n = n0; n < n0 + NPIX / NCHUNK; n++) {
        float v = Ep[(size_t)n * NPIX + m];
        if (v > mx) { s = s * __expf(mx - v) + 1.f; mx = v; }
        else        { s += __expf(v - mx); }
    }
    g_pmax[b][ch][m] = mx;
    g_psum[b][ch][m] = s;
}

__device__ __forceinline__ void rowstats_body(int b, int n, int lane)
{
    const float* row = g_E[b] + (size_t)n * NPIX;
    float mx = -3.0e38f, s = 0.f;
    for (int m = lane; m < NPIX; m += 32) {
        float v = row[m];
        if (v > mx) { s = s * __expf(mx - v) + 1.f; mx = v; }
        else        { s += __expf(v - mx); }
    }
#pragma unroll
    for (int off = 16; off; off >>= 1) {
        float om = __shfl_xor_sync(0xffffffffu, mx, off);
        float os = __shfl_xor_sync(0xffffffffu, s, off);
        float nm = fmaxf(mx, om);
        s = s * __expf(mx - nm) + os * __expf(om - nm);
        mx = nm;
    }
    if (lane == 0) { g_rowmax[b][n] = mx; g_rowrsum[b][n] = 1.f / s; }
}

__global__ void __launch_bounds__(256) k_zps()
{
    __shared__ uint32_t pool[7424];
    int bx = blockIdx.x;
    if (bx < 288) {
        int x = bx % 36, iz = bx / 36;
        zgemm_body(pool, iz >> 2, iz & 3, x * 64);
    } else if (bx < 936) {
        int idx = bx - 288;
        int mb = idx % 9, ch = (idx / 9) % 18, b = idx / 162;
        colpart_body(b, ch, mb * 256 + threadIdx.x);
    } else {
        int idx = bx - 936;
        int xb = idx % 288, b = idx / 288;
        rowstats_body(b, xb * 8 + (threadIdx.x >> 5), threadIdx.x & 31);
    }
}

// ======================================================================
// k_ygemm_fused: y = Z @ softmaxed(E) (single-pass bf16, fused exp),
// then out = Wpost @ y + bias + residual (3-term bf16), all in one block.
// Inlines colreduce for yi==0. 128x64 n-tile, 256 thr.
// Pool: [0..2559]=A2 main / WAh+WAl post; [2560..3839]=Bs main;
//       [3840..12031]=Ysf fp32 [128][64] -> Ysh [64][64] + Ysl [64][64]
// ======================================================================
__global__ void __launch_bounds__(256) k_ygemm_fused(const float* __restrict__ x1,
                                                     const float* __restrict__ x2,
                                                     float* __restrict__ out)
{
    __shared__ uint32_t pool[12032];
    __shared__ float s_max[64], s_rs[64];

    uint32_t* A2m = pool;                 // [128][20]
    uint32_t* Bs  = pool + 2560;          // [1280]
    float*    Ysf = (float*)(pool + 3840);// [128][64]
    uint32_t* Ysh = pool + 3840;          // [64][64] (aliases Ysf rows 0-63)
    uint32_t* Ysl = pool + 7936;          // [64][64] (aliases Ysf rows 64-127)
    uint32_t* WAh = pool;                 // post phase: [128][10]
    uint32_t* WAl = pool + 1280;          // post phase: [128][10]

    int yi = blockIdx.z >> 2, b = blockIdx.z & 3;
    int n0 = blockIdx.x * 64;
    const float* __restrict__ Zp = g_Z[yi][b];
    const float* __restrict__ Ep = g_E[b];

    int tid = threadIdx.x;
    int wid = tid >> 5, lane = tid & 31;
    int g = lane >> 2, tig = lane & 3;
    int wm = (wid & 3) * 32, wn = (wid >> 2) * 32;

    // stats: yi==0 inline colreduce from g_pmax/g_psum; yi==1 read rowstats
    if (tid < 64) {
        if (yi == 0) {
            int m = n0 + tid;
            float mx = -3.0e38f, s = 0.f;
#pragma unroll
            for (int ch = 0; ch < NCHUNK; ch++) {
                float pm = g_pmax[b][ch][m], ps = g_psum[b][ch][m];
                float nm = fmaxf(mx, pm);
                s = s * __expf(mx - nm) + ps * __expf(pm - nm);
                mx = nm;
            }
            s_max[tid] = mx; s_rs[tid] = 1.f / s;
        } else {
            s_max[tid] = g_rowmax[b][n0 + tid];
            s_rs[tid]  = g_rowrsum[b][n0 + tid];
        }
    }
    __syncthreads();

    int am = tid >> 1, aks = (tid & 1) * 16;
    int bk2g = tid >> 4, bn4 = (tid & 15) * 4;   // yi=0
    int bj = tid >> 2, bkq = (tid & 3) * 8;      // yi=1

    float4 sA[4], sB0, sB1;
    float c[2][4][4] = {};

    auto loadT = [&](int k0) {
#pragma unroll
        for (int q = 0; q < 4; q++) sA[q] = *(const float4*)&Zp[am * NPIX + k0 + aks + q * 4];
        if (yi == 0) {
            const float* be = &Ep[(size_t)(k0 + 2 * bk2g) * NPIX + n0 + bn4];
            sB0 = *(const float4*)be;
            sB1 = *(const float4*)(be + NPIX);
        } else {
            const float* be = &Ep[(size_t)(n0 + bj) * NPIX + k0 + bkq];
            sB0 = *(const float4*)be;
            sB1 = *(const float4*)(be + 4);
        }
    };
    auto storeT = [&]() {
        int k2b = aks >> 1;
#pragma unroll
        for (int q = 0; q < 4; q++) {
            A2m[am * 20 + k2b + q * 2    ] = pack_bf(sA[q].x, sA[q].y);
            A2m[am * 20 + k2b + q * 2 + 1] = pack_bf(sA[q].z, sA[q].w);
        }
        if (yi == 0) {
            float m0v = s_max[bn4], m1v = s_max[bn4+1], m2v = s_max[bn4+2], m3v = s_max[bn4+3];
            *(uint4*)&Bs[bk2g * 72 + bn4] = make_uint4(
                pack_bf(__expf(sB0.x - m0v), __expf(sB1.x - m0v)),
                pack_bf(__expf(sB0.y - m1v), __expf(sB1.y - m1v)),
                pack_bf(__expf(sB0.z - m2v), __expf(sB1.z - m2v)),
                pack_bf(__expf(sB0.w - m3v), __expf(sB1.w - m3v)));
        } else {
            float mx = s_max[bj];
            *(uint4*)&Bs[bj * 20 + (bkq >> 1)] = make_uint4(
                pack_bf(__expf(sB0.x - mx), __expf(sB0.y - mx)),
                pack_bf(__expf(sB0.z - mx), __expf(sB0.w - mx)),
                pack_bf(__expf(sB1.x - mx), __expf(sB1.y - mx)),
                pack_bf(__expf(sB1.z - mx), __expf(sB1.w - mx)));
        }
    };

    loadT(0); storeT(); __syncthreads();
    for (int t = 0; t < 72; t++) {
        if (t < 71) loadT((t + 1) * 32);
#pragma unroll
        for (int kk2 = 0; kk2 < 16; kk2 += 8) {
            uint32_t a[2][4];
#pragma unroll
            for (int mi = 0; mi < 2; mi++) {
                int mr = wm + mi * 16;
                a[mi][0]=A2m[(mr+g  )*20+kk2+tig  ]; a[mi][1]=A2m[(mr+g+8)*20+kk2+tig  ];
                a[mi][2]=A2m[(mr+g  )*20+kk2+tig+4]; a[mi][3]=A2m[(mr+g+8)*20+kk2+tig+4];
            }
#pragma unroll
            for (int ni = 0; ni < 4; ni++) {
                uint32_t bb[2];
                if (yi == 0) {
                    bb[0] = Bs[(kk2+tig  ) * 72 + wn + ni*8 + g];
                    bb[1] = Bs[(kk2+tig+4) * 72 + wn + ni*8 + g];
                } else {
                    int nr = wn + ni * 8 + g;
                    bb[0] = Bs[nr * 20 + kk2 + tig    ];
                    bb[1] = Bs[nr * 20 + kk2 + tig + 4];
                }
                mma16bf(c[0][ni], a[0], bb);
                mma16bf(c[1][ni], a[1], bb);
            }
        }
        __syncthreads();
        if (t < 71) storeT();
        __syncthreads();
    }

    // Y tile -> smem fp32 (scaled)
#pragma unroll
    for (int mi = 0; mi < 2; mi++) {
#pragma unroll
        for (int ni = 0; ni < 4; ni++) {
            int row = wm + mi * 16 + g;
            int col = wn + ni * 8 + tig * 2;
            Ysf[row * 64 + col]           = c[mi][ni][0] * s_rs[col];
            Ysf[row * 64 + col + 1]       = c[mi][ni][1] * s_rs[col + 1];
            Ysf[(row + 8) * 64 + col]     = c[mi][ni][2] * s_rs[col];
            Ysf[(row + 8) * 64 + col + 1] = c[mi][ni][3] * s_rs[col + 1];
        }
    }
    __syncthreads();

    // pack Y in place: fp32 [128][64] -> bf16 hi/lo [64][64]
    {
        int n = tid & 63, kq = tid >> 6;
        float fe[16], fo[16];
#pragma unroll
        for (int e = 0; e < 16; e++) {
            int k2 = kq * 16 + e;
            fe[e] = Ysf[(2 * k2) * 64 + n];
            fo[e] = Ysf[(2 * k2 + 1) * 64 + n];
        }
        __syncthreads();
#pragma unroll
        for (int e = 0; e < 16; e++) {
            int k2 = kq * 16 + e;
            uint32_t hp, lp;
            split_pack(fe[e], fo[e], hp, lp);
            Ysh[k2 * 64 + n] = hp;
            Ysl[k2 * 64 + n] = lp;
        }
    }
    __syncthreads();

    // post GEMM: out[m][n] = Wpost[yi] @ Y + bias + residual (3-term bf16)
    const float* __restrict__ Wp = g_Wpost[yi];
    const float* xs = (yi ? x2 : x1) + b * CC * NPIX;
    float* op = out + (size_t)yi * BATCH * CC * NPIX + (size_t)b * CC * NPIX;
    int wm2 = tid >> 1, wsel = tid & 1;

    for (int hh = 0; hh < 2; hh++) {
        int m0 = hh * 128;
        float c2[2][4][4] = {};
        for (int kc = 0; kc < 8; kc++) {
            // load Wpost chunk [128 m][16 k] -> packed [128][8] hi/lo
            {
                const float* wr = &Wp[(m0 + wm2) * CI + kc * 16 + wsel * 8];
                float4 w0 = *(const float4*)wr;
                float4 w1 = *(const float4*)(wr + 4);
                uint32_t h0,l0,h1,l1,h2,l2,h3,l3;
                split_pack(w0.x, w0.y, h0, l0); split_pack(w0.z, w0.w, h1, l1);
                split_pack(w1.x, w1.y, h2, l2); split_pack(w1.z, w1.w, h3, l3);
                int base = wm2 * 10 + wsel * 4;
                WAh[base+0]=h0; WAh[base+1]=h1; WAh[base+2]=h2; WAh[base+3]=h3;
                WAl[base+0]=l0; WAl[base+1]=l1; WAl[base+2]=l2; WAl[base+3]=l3;
            }
            __syncthreads();
            uint32_t ah[2][4], al[2][4];
#pragma unroll
            for (int mi = 0; mi < 2; mi++) {
                int mr = wm + mi * 16;
                ah[mi][0]=WAh[(mr+g  )*10+tig  ]; ah[mi][1]=WAh[(mr+g+8)*10+tig  ];
                ah[mi][2]=WAh[(mr+g  )*10+tig+4]; ah[mi][3]=WAh[(mr+g+8)*10+tig+4];
                al[mi][0]=WAl[(mr+g  )*10+tig  ]; al[mi][1]=WAl[(mr+g+8)*10+tig  ];
                al[mi][2]=WAl[(mr+g  )*10+tig+4]; al[mi][3]=WAl[(mr+g+8)*10+tig+4];
            }
#pragma unroll
            for (int ni = 0; ni < 4; ni++) {
                uint32_t bh[2], bl[2];
                bh[0] = Ysh[(kc*8+tig  )*64 + wn + ni*8 + g];
                bh[1] = Ysh[(kc*8+tig+4)*64 + wn + ni*8 + g];
                bl[0] = Ysl[(kc*8+tig  )*64 + wn + ni*8 + g];
                bl[1] = Ysl[(kc*8+tig+4)*64 + wn + ni*8 + g];
#pragma unroll
                for (int mi = 0; mi < 2; mi++) {
                    mma16bf(c2[mi][ni], ah[mi], bh);
                    mma16bf(c2[mi][ni], ah[mi], bl);
                    mma16bf(c2[mi][ni], al[mi], bh);
                }
            }
            __syncthreads();
        }
#pragma unroll
        for (int mi = 0; mi < 2; mi++) {
#pragma unroll
            for (int ni = 0; ni < 4; ni++) {
                int row = m0 + wm + mi * 16 + g;
                int col = n0 + wn + ni * 8 + tig * 2;
                float b0 = g_bpost[yi][row], b1 = g_bpost[yi][row + 8];
                float2 r0 = *(const float2*)&xs[row * NPIX + col];
                float2 r1 = *(const float2*)&xs[(row + 8) * NPIX + col];
                *(float2*)&op[row * NPIX + col] =
                    make_float2(c2[mi][ni][0] + b0 + r0.x, c2[mi][ni][1] + b0 + r0.y);
                *(float2*)&op[(row + 8) * NPIX + col] =
                    make_float2(c2[mi][ni][2] + b1 + r1.x, c2[mi][ni][3] + b1 + r1.y);
            }
        }
    }
}

// ---------------- launcher ----------------
extern "C" void kernel_launch(void* const* d_in, const int* in_sizes, int n_in,
                              void* d_out, int out_size)
{
    const float* x1      = (const float*)d_in[0];
    const float* x2      = (const float*)d_in[1];
    const float* bn_pre  = (const float*)d_in[2];
    const float* w_pre   = (const float*)d_in[3];
    const float* b_pre   = (const float*)d_in[4];
    const float* w_post  = (const float*)d_in[5];
    const float* b_post  = (const float*)d_in[6];
    const float* bn_post = (const float*)d_in[7];
    float* out = (float*)d_out;

    k_fold<<<128, 256>>>(bn_pre, w_pre, b_pre, w_post, b_post, bn_post);
    k_pre23<<<dim3(36, 1, 8), 256>>>(x1, x2);
    k_big3<<<3024, 256>>>(x1, x2);
    k_softA<<<dim3(2, BATCH), 256>>>();
    k_zps<<<2088, 256>>>();
    k_ygemm_fused<<<dim3(36, 1, 8), 256>>>(x1, x2, out);
}

// round 11
// speedup vs baseline: 1.3050x; 1.3050x over previous
#include <cuda_runtime.h>
#include <cuda_bf16.h>
#include <math.h>
#include <stdint.h>

#define BATCH 4
#define CC 256
#define CI 128
#define NPIX 2304
#define NPK2 1152
#define BNEPS 1e-5f
#define NCHUNK 18
#define ETSPLIT 18

// ---------------- scratch ----------------
__device__ float g_PRE[4][BATCH][CI*NPIX];
__device__ float g_ETpart[BATCH][ETSPLIT][CI*CI];
__device__ uint32_t g_Apack[2][BATCH][2][CI*64];     // [zi][b][hi/lo][m*64+k2]
__device__ float g_E[BATCH][NPIX*NPIX];
__device__ uint32_t g_Zpack[2][BATCH][CI*NPK2];      // bf16x2 pairs along n
__device__ float g_rowmax[BATCH][NPIX];
__device__ float g_rowrsum[BATCH][NPIX];
__device__ float g_pmax[BATCH][NCHUNK][NPIX];
__device__ float g_psum[BATCH][NCHUNK][NPIX];
__device__ float g_WpreH[4][CI*CC];
__device__ float g_WpreL[4][CI*CC];
__device__ float g_bpre[4][CI];
__device__ float g_Wpost[2][CC*CI];
__device__ float g_bpost[2][CC];

// ---------------- helpers ----------------
__device__ __forceinline__ uint32_t pack_bf(float e, float o) {
    uint32_t r;
    asm("cvt.rn.bf16x2.f32 %0, %1, %2;" : "=r"(r) : "f"(o), "f"(e));
    return r;
}
__device__ __forceinline__ float bf_round(float x) {
    return __bfloat162float(__float2bfloat16(x));
}
__device__ __forceinline__ void mma16bf(float c[4], const uint32_t a[4], const uint32_t b[2]) {
    asm volatile(
        "mma.sync.aligned.m16n8k16.row.col.f32.bf16.bf16.f32 "
        "{%0,%1,%2,%3}, {%4,%5,%6,%7}, {%8,%9}, {%0,%1,%2,%3};"
        : "+f"(c[0]), "+f"(c[1]), "+f"(c[2]), "+f"(c[3])
        : "r"(a[0]), "r"(a[1]), "r"(a[2]), "r"(a[3]), "r"(b[0]), "r"(b[1]));
}
__device__ __forceinline__ void split_pack(float e, float o, uint32_t& hp, uint32_t& lp) {
    float eh = bf_round(e), oh = bf_round(o);
    hp = pack_bf(eh, oh);
    lp = pack_bf(e - eh, o - oh);
}

// ======================================================================
// k_fold (R9)
// ======================================================================
__global__ void __launch_bounds__(256) k_fold(
    const float* __restrict__ bn_pre, const float* __restrict__ w_pre,
    const float* __restrict__ b_pre, const float* __restrict__ w_post,
    const float* __restrict__ b_post, const float* __restrict__ bn_post)
{
    int w = blockIdx.x * 8 + (threadIdx.x >> 5);
    int lane = threadIdx.x & 31;
    if (w < 512) {
        int i = w >> 7, o = w & 127;
        const float* bp = bn_pre + i * 4 * CC;
        const float* wr = w_pre + (i * CI + o) * CC;
        float acc = 0.f;
        for (int c = lane; c < CC; c += 32) {
            float s = bp[c] * rsqrtf(bp[3 * CC + c] + BNEPS);
            float t = bp[CC + c] - bp[2 * CC + c] * s;
            float wv = wr[c] * s;
            float h = bf_round(wv);
            g_WpreH[i][o * CC + c] = h;
            g_WpreL[i][o * CC + c] = wv - h;
            acc = fmaf(wr[c], t, acc);
        }
#pragma unroll
        for (int off = 16; off; off >>= 1) acc += __shfl_xor_sync(0xffffffffu, acc, off);
        if (lane == 0) g_bpre[i][o] = acc + b_pre[i * CI + o];
    } else {
        int w2 = w - 512;
        int i = w2 >> 8, o = w2 & 255;
        const float* bp = bn_post + i * 4 * CC;
        float s = bp[o] * rsqrtf(bp[3 * CC + o] + BNEPS);
        const float* wr = w_post + (i * CC + o) * CI;
        for (int c = lane; c < CI; c += 32)
            g_Wpost[i][o * CI + c] = wr[c] * s;
        if (lane == 0)
            g_bpost[i][o] = b_post[i * CC + o] * s + bp[CC + o] - bp[2 * CC + o] * s;
    }
}

// ======================================================================
// pre body (R9)
// ======================================================================
__device__ __forceinline__ void pre_body(uint32_t* pool, int i, int b, int n0,
                                         const float* __restrict__ x1,
                                         const float* __restrict__ x2)
{
    uint32_t* Ah = pool;
    uint32_t* Al = pool + 2560;
    uint32_t* Bh = pool + 5120;
    uint32_t* Bl = pool + 6272;
    const float* __restrict__ AHf = g_WpreH[i];
    const float* __restrict__ ALf = g_WpreL[i];
    const float* __restrict__ Bsrc = ((i & 1) ? x2 : x1) + b * CC * NPIX;

    int tid = threadIdx.x;
    int wid = tid >> 5, lane = tid & 31;
    int g = lane >> 2, tig = lane & 3;
    int wm = (wid & 3) * 32, wn = (wid >> 2) * 32;

    int am = tid >> 2, akq = (tid & 3) * 8;
    int bk2 = tid >> 4, bn4 = (tid & 15) * 4;

    float4 sh0[2], sh1[2], sl0[2], sl1[2], sbe, sbo;
    float c[2][4][4] = {};

    auto loadT = [&](int k0) {
#pragma unroll
        for (int it = 0; it < 2; it++) {
            int m = am + it * 64;
            sh0[it] = *(const float4*)&AHf[m * CC + k0 + akq];
            sh1[it] = *(const float4*)&AHf[m * CC + k0 + akq + 4];
            sl0[it] = *(const float4*)&ALf[m * CC + k0 + akq];
            sl1[it] = *(const float4*)&ALf[m * CC + k0 + akq + 4];
        }
        const float* be = &Bsrc[(k0 + 2 * bk2) * NPIX + n0 + bn4];
        sbe = *(const float4*)be;
        sbo = *(const float4*)(be + NPIX);
    };
    auto storeT = [&]() {
#pragma unroll
        for (int it = 0; it < 2; it++) {
            int m = am + it * 64, kq2 = akq >> 1;
            *(uint4*)&Ah[m * 20 + kq2] = make_uint4(
                pack_bf(sh0[it].x, sh0[it].y), pack_bf(sh0[it].z, sh0[it].w),
                pack_bf(sh1[it].x, sh1[it].y), pack_bf(sh1[it].z, sh1[it].w));
            *(uint4*)&Al[m * 20 + kq2] = make_uint4(
                pack_bf(sl0[it].x, sl0[it].y), pack_bf(sl0[it].z, sl0[it].w),
                pack_bf(sl1[it].x, sl1[it].y), pack_bf(sl1[it].z, sl1[it].w));
        }
        uint32_t h0,l0,h1,l1,h2,l2,h3,l3;
        split_pack(sbe.x, sbo.x, h0, l0); split_pack(sbe.y, sbo.y, h1, l1);
        split_pack(sbe.z, sbo.z, h2, l2); split_pack(sbe.w, sbo.w, h3, l3);
        *(uint4*)&Bh[bk2 * 72 + bn4] = make_uint4(h0, h1, h2, h3);
        *(uint4*)&Bl[bk2 * 72 + bn4] = make_uint4(l0, l1, l2, l3);
    };

    loadT(0); storeT(); __syncthreads();
    for (int t = 0; t < 8; t++) {
        if (t < 7) loadT((t + 1) * 32);
#pragma unroll
        for (int kk2 = 0; kk2 < 16; kk2 += 8) {
            uint32_t ah[2][4], al[2][4];
#pragma unroll
            for (int mi = 0; mi < 2; mi++) {
                int mr = wm + mi * 16;
                ah[mi][0]=Ah[(mr+g  )*20+kk2+tig  ]; ah[mi][1]=Ah[(mr+g+8)*20+kk2+tig  ];
                ah[mi][2]=Ah[(mr+g  )*20+kk2+tig+4]; ah[mi][3]=Ah[(mr+g+8)*20+kk2+tig+4];
                al[mi][0]=Al[(mr+g  )*20+kk2+tig  ]; al[mi][1]=Al[(mr+g+8)*20+kk2+tig  ];
                al[mi][2]=Al[(mr+g  )*20+kk2+tig+4]; al[mi][3]=Al[(mr+g+8)*20+kk2+tig+4];
            }
#pragma unroll
            for (int ni = 0; ni < 4; ni++) {
                uint32_t bh[2], bl[2];
                bh[0]=Bh[(kk2+tig  )*72+wn+ni*8+g]; bh[1]=Bh[(kk2+tig+4)*72+wn+ni*8+g];
                bl[0]=Bl[(kk2+tig  )*72+wn+ni*8+g]; bl[1]=Bl[(kk2+tig+4)*72+wn+ni*8+g];
#pragma unroll
                for (int mi = 0; mi < 2; mi++) {
                    mma16bf(c[mi][ni], ah[mi], bh);
                    mma16bf(c[mi][ni], ah[mi], bl);
                    mma16bf(c[mi][ni], al[mi], bh);
                }
            }
        }
        __syncthreads();
        if (t < 7) storeT();
        __syncthreads();
    }

    float* Cout = g_PRE[i][b];
#pragma unroll
    for (int mi = 0; mi < 2; mi++) {
#pragma unroll
        for (int ni = 0; ni < 4; ni++) {
            int row = wm + mi * 16 + g;
            int col = n0 + wn + ni * 8 + tig * 2;
            float b0 = g_bpre[i][row], b1 = g_bpre[i][row + 8];
            *(float2*)&Cout[row * NPIX + col] =
                make_float2(c[mi][ni][0] + b0, c[mi][ni][1] + b0);
            *(float2*)&Cout[(row + 8) * NPIX + col] =
                make_float2(c[mi][ni][2] + b1, c[mi][ni][3] + b1);
        }
    }
}

__global__ void __launch_bounds__(256) k_pre23(const float* __restrict__ x1,
                                               const float* __restrict__ x2)
{
    __shared__ uint32_t pool[7424];
    int i = 2 + (blockIdx.z >> 2), b = blockIdx.z & 3;
    pre_body(pool, i, b, blockIdx.x * 64, x1, x2);
}

// ======================================================================
// etime body (R9)
// ======================================================================
__device__ __forceinline__ void etime_body(uint32_t* pool, int b, int ks, int n0)
{
    uint32_t* Ah = pool;
    uint32_t* Al = pool + 2560;
    uint32_t* Bh = pool + 5120;
    uint32_t* Bl = pool + 6400;
    int kbeg = ks * (NPIX / ETSPLIT);
    const float* __restrict__ Tm = g_PRE[2][b];
    const float* __restrict__ Pm = g_PRE[3][b];

    int tid = threadIdx.x;
    int wid = tid >> 5, lane = tid & 31;
    int g = lane >> 2, tig = lane & 3;
    int wm = (wid & 3) * 32, wn = (wid >> 2) * 32;

    int am = tid >> 1, ak = (tid & 1) * 16;
    int bn = tid >> 2, bk = (tid & 3) * 8;

    float4 sA[4], sB[2];
    float c[2][4][4] = {};

    auto loadT = [&](int k0) {
#pragma unroll
        for (int q = 0; q < 4; q++) sA[q] = *(const float4*)&Tm[am * NPIX + k0 + ak + q * 4];
#pragma unroll
        for (int q = 0; q < 2; q++) sB[q] = *(const float4*)&Pm[(n0 + bn) * NPIX + k0 + bk + q * 4];
    };
    auto storeT = [&]() {
#pragma unroll
        for (int q = 0; q < 4; q++) {
            uint32_t h0,l0,h1,l1;
            split_pack(sA[q].x, sA[q].y, h0, l0);
            split_pack(sA[q].z, sA[q].w, h1, l1);
            int k2 = (ak >> 1) + q * 2;
            Ah[am * 20 + k2] = h0; Ah[am * 20 + k2 + 1] = h1;
            Al[am * 20 + k2] = l0; Al[am * 20 + k2 + 1] = l1;
        }
#pragma unroll
        for (int q = 0; q < 2; q++) {
            uint32_t h0,l0,h1,l1;
            split_pack(sB[q].x, sB[q].y, h0, l0);
            split_pack(sB[q].z, sB[q].w, h1, l1);
            int k2 = (bk >> 1) + q * 2;
            Bh[bn * 20 + k2] = h0; Bh[bn * 20 + k2 + 1] = h1;
            Bl[bn * 20 + k2] = l0; Bl[bn * 20 + k2 + 1] = l1;
        }
    };

    loadT(kbeg); storeT(); __syncthreads();
    for (int t = 0; t < 4; t++) {
        if (t < 3) loadT(kbeg + (t + 1) * 32);
#pragma unroll
        for (int kk2 = 0; kk2 < 16; kk2 += 8) {
            uint32_t ah[2][4], al[2][4];
#pragma unroll
            for (int mi = 0; mi < 2; mi++) {
                int mr = wm + mi * 16;
                ah[mi][0]=Ah[(mr+g  )*20+kk2+tig  ]; ah[mi][1]=Ah[(mr+g+8)*20+kk2+tig  ];
                ah[mi][2]=Ah[(mr+g  )*20+kk2+tig+4]; ah[mi][3]=Ah[(mr+g+8)*20+kk2+tig+4];
                al[mi][0]=Al[(mr+g  )*20+kk2+tig  ]; al[mi][1]=Al[(mr+g+8)*20+kk2+tig  ];
                al[mi][2]=Al[(mr+g  )*20+kk2+tig+4]; al[mi][3]=Al[(mr+g+8)*20+kk2+tig+4];
            }
#pragma unroll
            for (int ni = 0; ni < 4; ni++) {
                int nr = wn + ni * 8 + g;
                uint32_t bh[2], bl[2];
                bh[0]=Bh[nr*20+kk2+tig]; bh[1]=Bh[nr*20+kk2+tig+4];
                bl[0]=Bl[nr*20+kk2+tig]; bl[1]=Bl[nr*20+kk2+tig+4];
#pragma unroll
                for (int mi = 0; mi < 2; mi++) {
                    mma16bf(c[mi][ni], ah[mi], bh);
                    mma16bf(c[mi][ni], ah[mi], bl);
                    mma16bf(c[mi][ni], al[mi], bh);
                }
            }
        }
        __syncthreads();
        if (t < 3) storeT();
        __syncthreads();
    }

    float* outp = g_ETpart[b][ks];
#pragma unroll
    for (int mi = 0; mi < 2; mi++) {
#pragma unroll
        for (int ni = 0; ni < 4; ni++) {
            int row = wm + mi * 16 + g;
            int col = n0 + wn + ni * 8 + tig * 2;
            *(float2*)&outp[row * CI + col]       = make_float2(c[mi][ni][0], c[mi][ni][1]);
            *(float2*)&outp[(row + 8) * CI + col] = make_float2(c[mi][ni][2], c[mi][ni][3]);
        }
    }
}

// ======================================================================
// espace body (R9)
// ======================================================================
__device__ __forceinline__ void espace_body(uint32_t* pool, int b, int row0, int col0)
{
    uint32_t* Ah = pool;
    uint32_t* Al = pool + 2176;
    uint32_t* Bh = pool + 4352;
    uint32_t* Bl = pool + 5504;
    const float* __restrict__ T = g_PRE[2][b];
    const float* __restrict__ P = g_PRE[3][b];

    int tid = threadIdx.x;
    int wid = tid >> 5, lane = tid & 31;
    int g = lane >> 2, tig = lane & 3;
    int wm = (wid & 3) * 32, wn = (wid >> 2) * 32;

    int ak2 = tid >> 5, an4 = (tid & 31) * 4;
    int bk2 = tid >> 4, bm4 = (tid & 15) * 4;

    float4 sAe[2], sAo[2], sBe, sBo;
    float c[2][4][4] = {};

    auto loadT = [&](int k0) {
#pragma unroll
        for (int it = 0; it < 2; it++) {
            const float* te = &T[(k0 + 2 * (ak2 + it * 8)) * NPIX + row0 + an4];
            sAe[it] = *(const float4*)te;
            sAo[it] = *(const float4*)(te + NPIX);
        }
        const float* pe = &P[(k0 + 2 * bk2) * NPIX + col0 + bm4];
        sBe = *(const float4*)pe;
        sBo = *(const float4*)(pe + NPIX);
    };
    auto storeT = [&]() {
#pragma unroll
        for (int it = 0; it < 2; it++) {
            uint32_t h0,l0,h1,l1,h2,l2,h3,l3;
            split_pack(sAe[it].x, sAo[it].x, h0, l0); split_pack(sAe[it].y, sAo[it].y, h1, l1);
            split_pack(sAe[it].z, sAo[it].z, h2, l2); split_pack(sAe[it].w, sAo[it].w, h3, l3);
            int r = ak2 + it * 8;
            *(uint4*)&Ah[r * 136 + an4] = make_uint4(h0, h1, h2, h3);
            *(uint4*)&Al[r * 136 + an4] = make_uint4(l0, l1, l2, l3);
        }
        uint32_t h0,l0,h1,l1,h2,l2,h3,l3;
        split_pack(sBe.x, sBo.x, h0, l0); split_pack(sBe.y, sBo.y, h1, l1);
        split_pack(sBe.z, sBo.z, h2, l2); split_pack(sBe.w, sBo.w, h3, l3);
        *(uint4*)&Bh[bk2 * 72 + bm4] = make_uint4(h0, h1, h2, h3);
        *(uint4*)&Bl[bk2 * 72 + bm4] = make_uint4(l0, l1, l2, l3);
    };

    loadT(0); storeT(); __syncthreads();
    for (int t = 0; t < 4; t++) {
        if (t < 3) loadT((t + 1) * 32);
#pragma unroll
        for (int kk2 = 0; kk2 < 16; kk2 += 8) {
            uint32_t ah[2][4], al[2][4];
#pragma unroll
            for (int mi = 0; mi < 2; mi++) {
                int mr = wm + mi * 16;
                ah[mi][0] = Ah[(kk2+tig  )*136 + mr + g    ];
                ah[mi][1] = Ah[(kk2+tig  )*136 + mr + g + 8];
                ah[mi][2] = Ah[(kk2+tig+4)*136 + mr + g    ];
                ah[mi][3] = Ah[(kk2+tig+4)*136 + mr + g + 8];
                al[mi][0] = Al[(kk2+tig  )*136 + mr + g    ];
                al[mi][1] = Al[(kk2+tig  )*136 + mr + g + 8];
                al[mi][2] = Al[(kk2+tig+4)*136 + mr + g    ];
                al[mi][3] = Al[(kk2+tig+4)*136 + mr + g + 8];
            }
#pragma unroll
            for (int ni = 0; ni < 4; ni++) {
                uint32_t bh[2], bl[2];
                bh[0] = Bh[(kk2+tig  )*72 + wn + ni*8 + g];
                bh[1] = Bh[(kk2+tig+4)*72 + wn + ni*8 + g];
                bl[0] = Bl[(kk2+tig  )*72 + wn + ni*8 + g];
                bl[1] = Bl[(kk2+tig+4)*72 + wn + ni*8 + g];
#pragma unroll
                for (int mi = 0; mi < 2; mi++) {
                    mma16bf(c[mi][ni], ah[mi], bh);
                    mma16bf(c[mi][ni], ah[mi], bl);
                    mma16bf(c[mi][ni], al[mi], bh);
                }
            }
        }
        __syncthreads();
        if (t < 3) storeT();
        __syncthreads();
    }

    float* Ep = g_E[b];
#pragma unroll
    for (int mi = 0; mi < 2; mi++) {
#pragma unroll
        for (int ni = 0; ni < 4; ni++) {
            int row = row0 + wm + mi * 16 + g;
            int col = col0 + wn + ni * 8 + tig * 2;
            *(float2*)&Ep[row * NPIX + col]       = make_float2(c[mi][ni][0], c[mi][ni][1]);
            *(float2*)&Ep[(row + 8) * NPIX + col] = make_float2(c[mi][ni][2], c[mi][ni][3]);
        }
    }
}

// ======================================================================
// BIG3: pre01 (288) | etime (144) | espace (2592)
// ======================================================================
__global__ void __launch_bounds__(256) k_big3(const float* __restrict__ x1,
                                              const float* __restrict__ x2)
{
    __shared__ uint32_t pool[7680];
    int bx = blockIdx.x;
    if (bx < 288) {
        int x = bx % 36, iz = bx / 36;
        pre_body(pool, iz >> 2, iz & 3, x * 64, x1, x2);
    } else if (bx < 432) {
        int idx = bx - 288;
        int x = idx % 2, ks = (idx / 2) % 18, b = idx / 36;
        etime_body(pool, b, ks, x * 64);
    } else {
        int idx = bx - 432;
        int x = idx % 36, y = (idx / 36) % 18, b = idx / 648;
        espace_body(pool, b, y * 128, x * 64);
    }
}

// ======================================================================
// k_softA: fused etreduce + time-softmax, packed bf16 hi/lo output.
// grid (16, BATCH): orient = bx&1 (0->A2 rows, 1->A1 cols), strip = bx>>1.
// ======================================================================
__global__ void __launch_bounds__(256) k_softA()
{
    int b = blockIdx.y;
    int orient = blockIdx.x & 1;
    int strip = blockIdx.x >> 1;       // 0..7, 16 rows/cols each
    int tid = threadIdx.x, wid = tid >> 5, lane = tid & 31;
    __shared__ float ETs[128][17];

    if (orient == 0) {
        // A2[t][d]: row softmax, coalesced reads; 16 rows, warp per 2 rows
        for (int tt = wid; tt < 16; tt += 8) {
            int t = strip * 16 + tt;
            float v[4];
#pragma unroll
            for (int j = 0; j < 4; j++) {
                int d = lane + j * 32;
                float s = 0.f;
#pragma unroll
                for (int p = 0; p < ETSPLIT; p++) s += g_ETpart[b][p][t * CI + d];
                v[j] = s;
            }
            float mx = fmaxf(fmaxf(v[0], v[1]), fmaxf(v[2], v[3]));
#pragma unroll
            for (int off = 16; off; off >>= 1) mx = fmaxf(mx, __shfl_xor_sync(0xffffffffu, mx, off));
            float e[4]; float sum = 0.f;
#pragma unroll
            for (int j = 0; j < 4; j++) { e[j] = __expf(v[j] - mx); sum += e[j]; }
#pragma unroll
            for (int off = 16; off; off >>= 1) sum += __shfl_xor_sync(0xffffffffu, sum, off);
            float rs = 1.f / sum;
#pragma unroll
            for (int j = 0; j < 4; j++) {
                float own = e[j] * rs;
                float part = __shfl_xor_sync(0xffffffffu, own, 1);
                if (!(lane & 1)) {
                    float oh = bf_round(own), ph = bf_round(part);
                    int k2 = (lane >> 1) + 16 * j;
                    g_Apack[1][b][0][t * 64 + k2] = pack_bf(oh, ph);
                    g_Apack[1][b][1][t * 64 + k2] = pack_bf(own - oh, part - ph);
                }
            }
        }
    } else {
        // A1[c][d]: column softmax via smem transpose; 16 columns per block
        int c0 = strip * 16;
        for (int idx = tid; idx < 128 * 16; idx += 256) {
            int d = idx >> 4, cc = idx & 15;
            float s = 0.f;
#pragma unroll
            for (int p = 0; p < ETSPLIT; p++) s += g_ETpart[b][p][d * CI + c0 + cc];
            ETs[d][cc] = s;
        }
        __syncthreads();
        for (int ci = wid; ci < 16; ci += 8) {
            int ccol = c0 + ci;
            float v[4];
#pragma unroll
            for (int j = 0; j < 4; j++) v[j] = ETs[lane + 32 * j][ci];
            float mx = fmaxf(fmaxf(v[0], v[1]), fmaxf(v[2], v[3]));
#pragma unroll
            for (int off = 16; off; off >>= 1) mx = fmaxf(mx, __shfl_xor_sync(0xffffffffu, mx, off));
            float e[4]; float sum = 0.f;
#pragma unroll
            for (int j = 0; j < 4; j++) { e[j] = __expf(v[j] - mx); sum += e[j]; }
#pragma unroll
            for (int off = 16; off; off >>= 1) sum += __shfl_xor_sync(0xffffffffu, sum, off);
            float rs = 1.f / sum;
#pragma unroll
            for (int j = 0; j < 4; j++) {
                float own = e[j] * rs;
                float part = __shfl_xor_sync(0xffffffffu, own, 1);
                if (!(lane & 1)) {
                    float oh = bf_round(own), ph = bf_round(part);
                    int k2 = (lane >> 1) + 16 * j;
                    g_Apack[0][b][0][ccol * 64 + k2] = pack_bf(oh, ph);
                    g_Apack[0][b][1][ccol * 64 + k2] = pack_bf(own - oh, part - ph);
                }
            }
        }
    }
}

// ======================================================================
// zgemm body: 3-term bf16, packed A from g_Apack, output packed bf16 Z
// ======================================================================
__device__ __forceinline__ void zgemm_body(uint32_t* pool, int zi, int b, int n0)
{
    uint32_t* Ah = pool;
    uint32_t* Al = pool + 2560;
    uint32_t* Bh = pool + 5120;
    uint32_t* Bl = pool + 6272;
    const uint32_t* __restrict__ AhG = g_Apack[zi][b][0];
    const uint32_t* __restrict__ AlG = g_Apack[zi][b][1];
    const float* __restrict__ Bsrc = g_PRE[zi][b];

    int tid = threadIdx.x;
    int wid = tid >> 5, lane = tid & 31;
    int g = lane >> 2, tig = lane & 3;
    int wm = (wid & 3) * 32, wn = (wid >> 2) * 32;

    int am = tid >> 1, half8 = (tid & 1) * 8;
    int bk2 = tid >> 4, bn4 = (tid & 15) * 4;

    uint4 sAh0, sAh1, sAl0, sAl1;
    float4 sbe, sbo;
    float c[2][4][4] = {};

    auto loadT = [&](int k0) {
        int k2b = (k0 >> 1) + half8;
        sAh0 = *(const uint4*)&AhG[am * 64 + k2b];
        sAh1 = *(const uint4*)&AhG[am * 64 + k2b + 4];
        sAl0 = *(const uint4*)&AlG[am * 64 + k2b];
        sAl1 = *(const uint4*)&AlG[am * 64 + k2b + 4];
        const float* be = &Bsrc[(k0 + 2 * bk2) * NPIX + n0 + bn4];
        sbe = *(const float4*)be;
        sbo = *(const float4*)(be + NPIX);
    };
    auto storeT = [&]() {
        *(uint4*)&Ah[am * 20 + half8]     = sAh0;
        *(uint4*)&Ah[am * 20 + half8 + 4] = sAh1;
        *(uint4*)&Al[am * 20 + half8]     = sAl0;
        *(uint4*)&Al[am * 20 + half8 + 4] = sAl1;
        uint32_t h0,l0,h1,l1,h2,l2,h3,l3;
        split_pack(sbe.x, sbo.x, h0, l0); split_pack(sbe.y, sbo.y, h1, l1);
        split_pack(sbe.z, sbo.z, h2, l2); split_pack(sbe.w, sbo.w, h3, l3);
        *(uint4*)&Bh[bk2 * 72 + bn4] = make_uint4(h0, h1, h2, h3);
        *(uint4*)&Bl[bk2 * 72 + bn4] = make_uint4(l0, l1, l2, l3);
    };

    loadT(0); storeT(); __syncthreads();
    for (int t = 0; t < 4; t++) {
        if (t < 3) loadT((t + 1) * 32);
#pragma unroll
        for (int kk2 = 0; kk2 < 16; kk2 += 8) {
            uint32_t ah[2][4], al[2][4];
#pragma unroll
            for (int mi = 0; mi < 2; mi++) {
                int mr = wm + mi * 16;
                ah[mi][0]=Ah[(mr+g  )*20+kk2+tig  ]; ah[mi][1]=Ah[(mr+g+8)*20+kk2+tig  ];
                ah[mi][2]=Ah[(mr+g  )*20+kk2+tig+4]; ah[mi][3]=Ah[(mr+g+8)*20+kk2+tig+4];
                al[mi][0]=Al[(mr+g  )*20+kk2+tig  ]; al[mi][1]=Al[(mr+g+8)*20+kk2+tig  ];
                al[mi][2]=Al[(mr+g  )*20+kk2+tig+4]; al[mi][3]=Al[(mr+g+8)*20+kk2+tig+4];
            }
#pragma unroll
            for (int ni = 0; ni < 4; ni++) {
                uint32_t bh[2], bl[2];
                bh[0]=Bh[(kk2+tig  )*72+wn+ni*8+g]; bh[1]=Bh[(kk2+tig+4)*72+wn+ni*8+g];
                bl[0]=Bl[(kk2+tig  )*72+wn+ni*8+g]; bl[1]=Bl[(kk2+tig+4)*72+wn+ni*8+g];
#pragma unroll
                for (int mi = 0; mi < 2; mi++) {
                    mma16bf(c[mi][ni], ah[mi], bh);
                    mma16bf(c[mi][ni], ah[mi], bl);
                    mma16bf(c[mi][ni], al[mi], bh);
                }
            }
        }
        __syncthreads();
        if (t < 3) storeT();
        __syncthreads();
    }

    uint32_t* Zout = g_Zpack[zi][b];
#pragma unroll
    for (int mi = 0; mi < 2; mi++) {
#pragma unroll
        for (int ni = 0; ni < 4; ni++) {
            int row = wm + mi * 16 + g;
            int colh = ((n0 + wn + ni * 8) >> 1) + tig;
            Zout[row * NPK2 + colh]       = pack_bf(c[mi][ni][0], c[mi][ni][1]);
            Zout[(row + 8) * NPK2 + colh] = pack_bf(c[mi][ni][2], c[mi][ni][3]);
        }
    }
}

// ---------------- stats bodies ----------------
__device__ __forceinline__ void colpart_body(int b, int ch, int m)
{
    const float* Ep = g_E[b];
    float mx = -3.0e38f, s = 0.f;
    int n0 = ch * (NPIX / NCHUNK);
    for (int n = n0; n < n0 + NPIX / NCHUNK; n++) {
        float v = Ep[(size_t)n * NPIX + m];
        if (v > mx) { s = s * __expf(mx - v) + 1.f; mx = v; }
        else        { s += __expf(v - mx); }
    }
    g_pmax[b][ch][m] = mx;
    g_psum[b][ch][m] = s;
}

__device__ __forceinline__ void rowstats_body(int b, int n, int lane)
{
    const float* row = g_E[b] + (size_t)n * NPIX;
    float mx = -3.0e38f, s = 0.f;
    for (int m = lane; m < NPIX; m += 32) {
        float v = row[m];
        if (v > mx) { s = s * __expf(mx - v) + 1.f; mx = v; }
        else        { s += __expf(v - mx); }
    }
#pragma unroll
    for (int off = 16; off; off >>= 1) {
        float om = __shfl_xor_sync(0xffffffffu, mx, off);
        float os = __shfl_xor_sync(0xffffffffu, s, off);
        float nm = fmaxf(mx, om);
        s = s * __expf(mx - nm) + os * __expf(om - nm);
        mx = nm;
    }
    if (lane == 0) { g_rowmax[b][n] = mx; g_rowrsum[b][n] = 1.f / s; }
}

__global__ void __launch_bounds__(256) k_zps()
{
    __shared__ uint32_t pool[7424];
    int bx = blockIdx.x;
    if (bx < 288) {
        int x = bx % 36, iz = bx / 36;
        zgemm_body(pool, iz >> 2, iz & 3, x * 64);
    } else if (bx < 936) {
        int idx = bx - 288;
        int mb = idx % 9, ch = (idx / 9) % 18, b = idx / 162;
        colpart_body(b, ch, mb * 256 + threadIdx.x);
    } else {
        int idx = bx - 936;
        int xb = idx % 288, b = idx / 288;
        rowstats_body(b, xb * 8 + (threadIdx.x >> 5), threadIdx.x & 31);
    }
}

// ======================================================================
// k_ygemm_fused (R10 + packed-Z A path)
// ======================================================================
__global__ void __launch_bounds__(256) k_ygemm_fused(const float* __restrict__ x1,
                                                     const float* __restrict__ x2,
                                                     float* __restrict__ out)
{
    __shared__ uint32_t pool[12032];
    __shared__ float s_max[64], s_rs[64];

    uint32_t* A2m = pool;                 // [128][20]
    uint32_t* Bs  = pool + 2560;          // [1280]
    float*    Ysf = (float*)(pool + 3840);// [128][64]
    uint32_t* Ysh = pool + 3840;          // [64][64]
    uint32_t* Ysl = pool + 7936;          // [64][64]
    uint32_t* WAh = pool;                 // post phase: [128][10]
    uint32_t* WAl = pool + 1280;          // post phase: [128][10]

    int yi = blockIdx.z >> 2, b = blockIdx.z & 3;
    int n0 = blockIdx.x * 64;
    const uint32_t* __restrict__ Zp = g_Zpack[yi][b];
    const float* __restrict__ Ep = g_E[b];

    int tid = threadIdx.x;
    int wid = tid >> 5, lane = tid & 31;
    int g = lane >> 2, tig = lane & 3;
    int wm = (wid & 3) * 32, wn = (wid >> 2) * 32;

    if (tid < 64) {
        if (yi == 0) {
            int m = n0 + tid;
            float mx = -3.0e38f, s = 0.f;
#pragma unroll
            for (int ch = 0; ch < NCHUNK; ch++) {
                float pm = g_pmax[b][ch][m], ps = g_psum[b][ch][m];
                float nm = fmaxf(mx, pm);
                s = s * __expf(mx - nm) + ps * __expf(pm - nm);
                mx = nm;
            }
            s_max[tid] = mx; s_rs[tid] = 1.f / s;
        } else {
            s_max[tid] = g_rowmax[b][n0 + tid];
            s_rs[tid]  = g_rowrsum[b][n0 + tid];
        }
    }
    __syncthreads();

    int am = tid >> 1, half8 = (tid & 1) * 8;
    int bk2g = tid >> 4, bn4 = (tid & 15) * 4;   // yi=0
    int bj = tid >> 2, bkq = (tid & 3) * 8;      // yi=1

    uint4 sZ0, sZ1;
    float4 sB0, sB1;
    float c[2][4][4] = {};

    auto loadT = [&](int k0) {
        int k2b = (k0 >> 1) + half8;
        sZ0 = *(const uint4*)&Zp[am * NPK2 + k2b];
        sZ1 = *(const uint4*)&Zp[am * NPK2 + k2b + 4];
        if (yi == 0) {
            const float* be = &Ep[(size_t)(k0 + 2 * bk2g) * NPIX + n0 + bn4];
            sB0 = *(const float4*)be;
            sB1 = *(const float4*)(be + NPIX);
        } else {
            const float* be = &Ep[(size_t)(n0 + bj) * NPIX + k0 + bkq];
            sB0 = *(const float4*)be;
            sB1 = *(const float4*)(be + 4);
        }
    };
    auto storeT = [&]() {
        *(uint4*)&A2m[am * 20 + half8]     = sZ0;
        *(uint4*)&A2m[am * 20 + half8 + 4] = sZ1;
        if (yi == 0) {
            float m0v = s_max[bn4], m1v = s_max[bn4+1], m2v = s_max[bn4+2], m3v = s_max[bn4+3];
            *(uint4*)&Bs[bk2g * 72 + bn4] = make_uint4(
                pack_bf(__expf(sB0.x - m0v), __expf(sB1.x - m0v)),
                pack_bf(__expf(sB0.y - m1v), __expf(sB1.y - m1v)),
                pack_bf(__expf(sB0.z - m2v), __expf(sB1.z - m2v)),
                pack_bf(__expf(sB0.w - m3v), __expf(sB1.w - m3v)));
        } else {
            float mx = s_max[bj];
            *(uint4*)&Bs[bj * 20 + (bkq >> 1)] = make_uint4(
                pack_bf(__expf(sB0.x - mx), __expf(sB0.y - mx)),
                pack_bf(__expf(sB0.z - mx), __expf(sB0.w - mx)),
                pack_bf(__expf(sB1.x - mx), __expf(sB1.y - mx)),
                pack_bf(__expf(sB1.z - mx), __expf(sB1.w - mx)));
        }
    };

    loadT(0); storeT(); __syncthreads();
    for (int t = 0; t < 72; t++) {
        if (t < 71) loadT((t + 1) * 32);
#pragma unroll
        for (int kk2 = 0; kk2 < 16; kk2 += 8) {
            uint32_t a[2][4];
#pragma unroll
            for (int mi = 0; mi < 2; mi++) {
                int mr = wm + mi * 16;
                a[mi][0]=A2m[(mr+g  )*20+kk2+tig  ]; a[mi][1]=A2m[(mr+g+8)*20+kk2+tig  ];
                a[mi][2]=A2m[(mr+g  )*20+kk2+tig+4]; a[mi][3]=A2m[(mr+g+8)*20+kk2+tig+4];
            }
#pragma unroll
            for (int ni = 0; ni < 4; ni++) {
                uint32_t bb[2];
                if (yi == 0) {
                    bb[0] = Bs[(kk2+tig  ) * 72 + wn + ni*8 + g];
                    bb[1] = Bs[(kk2+tig+4) * 72 + wn + ni*8 + g];
                } else {
                    int nr = wn + ni * 8 + g;
                    bb[0] = Bs[nr * 20 + kk2 + tig    ];
                    bb[1] = Bs[nr * 20 + kk2 + tig + 4];
                }
                mma16bf(c[0][ni], a[0], bb);
                mma16bf(c[1][ni], a[1], bb);
            }
        }
        __syncthreads();
        if (t < 71) storeT();
        __syncthreads();
    }

    // Y tile -> smem fp32 (scaled)
#pragma unroll
    for (int mi = 0; mi < 2; mi++) {
#pragma unroll
        for (int ni = 0; ni < 4; ni++) {
            int row = wm + mi * 16 + g;
            int col = wn + ni * 8 + tig * 2;
            Ysf[row * 64 + col]           = c[mi][ni][0] * s_rs[col];
            Ysf[row * 64 + col + 1]       = c[mi][ni][1] * s_rs[col + 1];
            Ysf[(row + 8) * 64 + col]     = c[mi][ni][2] * s_rs[col];
            Ysf[(row + 8) * 64 + col + 1] = c[mi][ni][3] * s_rs[col + 1];
        }
    }
    __syncthreads();

    // pack Y in place: fp32 [128][64] -> bf16 hi/lo [64][64]
    {
        int n = tid & 63, kq = tid >> 6;
        float fe[16], fo[16];
#pragma unroll
        for (int e = 0; e < 16; e++) {
            int k2 = kq * 16 + e;
            fe[e] = Ysf[(2 * k2) * 64 + n];
            fo[e] = Ysf[(2 * k2 + 1) * 64 + n];
        }
        __syncthreads();
#pragma unroll
        for (int e = 0; e < 16; e++) {
            int k2 = kq * 16 + e;
            uint32_t hp, lp;
            split_pack(fe[e], fo[e], hp, lp);
            Ysh[k2 * 64 + n] = hp;
            Ysl[k2 * 64 + n] = lp;
        }
    }
    __syncthreads();

    // post GEMM (3-term bf16) + bias + residual
    const float* __restrict__ Wp = g_Wpost[yi];
    const float* xs = (yi ? x2 : x1) + b * CC * NPIX;
    float* op = out + (size_t)yi * BATCH * CC * NPIX + (size_t)b * CC * NPIX;
    int wm2 = tid >> 1, wsel = tid & 1;

    for (int hh = 0; hh < 2; hh++) {
        int m0 = hh * 128;
        float c2[2][4][4] = {};
        for (int kc = 0; kc < 8; kc++) {
            {
                const float* wr = &Wp[(m0 + wm2) * CI + kc * 16 + wsel * 8];
                float4 w0 = *(const float4*)wr;
                float4 w1 = *(const float4*)(wr + 4);
                uint32_t h0,l0,h1,l1,h2,l2,h3,l3;
                split_pack(w0.x, w0.y, h0, l0); split_pack(w0.z, w0.w, h1, l1);
                split_pack(w1.x, w1.y, h2, l2); split_pack(w1.z, w1.w, h3, l3);
                int base = wm2 * 10 + wsel * 4;
                WAh[base+0]=h0; WAh[base+1]=h1; WAh[base+2]=h2; WAh[base+3]=h3;
                WAl[base+0]=l0; WAl[base+1]=l1; WAl[base+2]=l2; WAl[base+3]=l3;
            }
            __syncthreads();
            uint32_t ah[2][4], al[2][4];
#pragma unroll
            for (int mi = 0; mi < 2; mi++) {
                int mr = wm + mi * 16;
                ah[mi][0]=WAh[(mr+g  )*10+tig  ]; ah[mi][1]=WAh[(mr+g+8)*10+tig  ];
                ah[mi][2]=WAh[(mr+g  )*10+tig+4]; ah[mi][3]=WAh[(mr+g+8)*10+tig+4];
                al[mi][0]=WAl[(mr+g  )*10+tig  ]; al[mi][1]=WAl[(mr+g+8)*10+tig  ];
                al[mi][2]=WAl[(mr+g  )*10+tig+4]; al[mi][3]=WAl[(mr+g+8)*10+tig+4];
            }
#pragma unroll
            for (int ni = 0; ni < 4; ni++) {
                uint32_t bh[2], bl[2];
                bh[0] = Ysh[(kc*8+tig  )*64 + wn + ni*8 + g];
                bh[1] = Ysh[(kc*8+tig+4)*64 + wn + ni*8 + g];
                bl[0] = Ysl[(kc*8+tig  )*64 + wn + ni*8 + g];
                bl[1] = Ysl[(kc*8+tig+4)*64 + wn + ni*8 + g];
#pragma unroll
                for (int mi = 0; mi < 2; mi++) {
                    mma16bf(c2[mi][ni], ah[mi], bh);
                    mma16bf(c2[mi][ni], ah[mi], bl);
                    mma16bf(c2[mi][ni], al[mi], bh);
                }
            }
            __syncthreads();
        }
#pragma unroll
        for (int mi = 0; mi < 2; mi++) {
#pragma unroll
            for (int ni = 0; ni < 4; ni++) {
                int row = m0 + wm + mi * 16 + g;
                int col = n0 + wn + ni * 8 + tig * 2;
                float b0 = g_bpost[yi][row], b1 = g_bpost[yi][row + 8];
                float2 r0 = *(const float2*)&xs[row * NPIX + col];
                float2 r1 = *(const float2*)&xs[(row + 8) * NPIX + col];
                *(float2*)&op[row * NPIX + col] =
                    make_float2(c2[mi][ni][0] + b0 + r0.x, c2[mi][ni][1] + b0 + r0.y);
                *(float2*)&op[(row + 8) * NPIX + col] =
                    make_float2(c2[mi][ni][2] + b1 + r1.x, c2[mi][ni][3] + b1 + r1.y);
            }
        }
    }
}

// ---------------- launcher ----------------
extern "C" void kernel_launch(void* const* d_in, const int* in_sizes, int n_in,
                              void* d_out, int out_size)
{
    const float* x1      = (const float*)d_in[0];
    const float* x2      = (const float*)d_in[1];
    const float* bn_pre  = (const float*)d_in[2];
    const float* w_pre   = (const float*)d_in[3];
    const float* b_pre   = (const float*)d_in[4];
    const float* w_post  = (const float*)d_in[5];
    const float* b_post  = (const float*)d_in[6];
    const float* bn_post = (const float*)d_in[7];
    float* out = (float*)d_out;

    k_fold<<<128, 256>>>(bn_pre, w_pre, b_pre, w_post, b_post, bn_post);
    k_pre23<<<dim3(36, 1, 8), 256>>>(x1, x2);
    k_big3<<<3024, 256>>>(x1, x2);
    k_softA<<<dim3(16, BATCH), 256>>>();
    k_zps<<<2088, 256>>>();
    k_ygemm_fused<<<dim3(36, 1, 8), 256>>>(x1, x2, out);
}

// round 12
// speedup vs baseline: 1.3147x; 1.0074x over previous
#include <cuda_runtime.h>
#include <cuda_bf16.h>
#include <math.h>
#include <stdint.h>

#define BATCH 4
#define CC 256
#define CI 128
#define NPIX 2304
#define NPK2 1152
#define BNEPS 1e-5f
#define NCHUNK 18
#define ETSPLIT 18

// ---------------- scratch ----------------
__device__ float g_PRE[4][BATCH][CI*NPIX];
__device__ float g_ETpart[BATCH][ETSPLIT][CI*CI];
__device__ uint32_t g_Apack[2][BATCH][2][CI*64];
__device__ float g_E[BATCH][NPIX*NPIX];
__device__ uint32_t g_Zpack[2][BATCH][CI*NPK2];
__device__ float g_rowmax[BATCH][NPIX];
__device__ float g_rowrsum[BATCH][NPIX];
__device__ float g_pmax[BATCH][NCHUNK][NPIX];
__device__ float g_psum[BATCH][NCHUNK][NPIX];
__device__ float g_WpreH[4][CI*CC];
__device__ float g_WpreL[4][CI*CC];
__device__ float g_bpre[4][CI];
__device__ float g_Wpost[2][CC*CI];
__device__ float g_bpost[2][CC];

// ---------------- helpers ----------------
__device__ __forceinline__ uint32_t pack_bf(float e, float o) {
    uint32_t r;
    asm("cvt.rn.bf16x2.f32 %0, %1, %2;" : "=r"(r) : "f"(o), "f"(e));
    return r;
}
__device__ __forceinline__ float bf_round(float x) {
    return __bfloat162float(__float2bfloat16(x));
}
__device__ __forceinline__ void mma16bf(float c[4], const uint32_t a[4], const uint32_t b[2]) {
    asm volatile(
        "mma.sync.aligned.m16n8k16.row.col.f32.bf16.bf16.f32 "
        "{%0,%1,%2,%3}, {%4,%5,%6,%7}, {%8,%9}, {%0,%1,%2,%3};"
        : "+f"(c[0]), "+f"(c[1]), "+f"(c[2]), "+f"(c[3])
        : "r"(a[0]), "r"(a[1]), "r"(a[2]), "r"(a[3]), "r"(b[0]), "r"(b[1]));
}
__device__ __forceinline__ void split_pack(float e, float o, uint32_t& hp, uint32_t& lp) {
    float eh = bf_round(e), oh = bf_round(o);
    hp = pack_bf(eh, oh);
    lp = pack_bf(e - eh, o - oh);
}

// ======================================================================
// k_fold (R9)
// ======================================================================
__global__ void __launch_bounds__(256) k_fold(
    const float* __restrict__ bn_pre, const float* __restrict__ w_pre,
    const float* __restrict__ b_pre, const float* __restrict__ w_post,
    const float* __restrict__ b_post, const float* __restrict__ bn_post)
{
    int w = blockIdx.x * 8 + (threadIdx.x >> 5);
    int lane = threadIdx.x & 31;
    if (w < 512) {
        int i = w >> 7, o = w & 127;
        const float* bp = bn_pre + i * 4 * CC;
        const float* wr = w_pre + (i * CI + o) * CC;
        float acc = 0.f;
        for (int c = lane; c < CC; c += 32) {
            float s = bp[c] * rsqrtf(bp[3 * CC + c] + BNEPS);
            float t = bp[CC + c] - bp[2 * CC + c] * s;
            float wv = wr[c] * s;
            float h = bf_round(wv);
            g_WpreH[i][o * CC + c] = h;
            g_WpreL[i][o * CC + c] = wv - h;
            acc = fmaf(wr[c], t, acc);
        }
#pragma unroll
        for (int off = 16; off; off >>= 1) acc += __shfl_xor_sync(0xffffffffu, acc, off);
        if (lane == 0) g_bpre[i][o] = acc + b_pre[i * CI + o];
    } else {
        int w2 = w - 512;
        int i = w2 >> 8, o = w2 & 255;
        const float* bp = bn_post + i * 4 * CC;
        float s = bp[o] * rsqrtf(bp[3 * CC + o] + BNEPS);
        const float* wr = w_post + (i * CC + o) * CI;
        for (int c = lane; c < CI; c += 32)
            g_Wpost[i][o * CI + c] = wr[c] * s;
        if (lane == 0)
            g_bpost[i][o] = b_post[i * CC + o] * s + bp[CC + o] - bp[2 * CC + o] * s;
    }
}

// ======================================================================
// pre body (R9)
// ======================================================================
__device__ __forceinline__ void pre_body(uint32_t* pool, int i, int b, int n0,
                                         const float* __restrict__ x1,
                                         const float* __restrict__ x2)
{
    uint32_t* Ah = pool;
    uint32_t* Al = pool + 2560;
    uint32_t* Bh = pool + 5120;
    uint32_t* Bl = pool + 6272;
    const float* __restrict__ AHf = g_WpreH[i];
    const float* __restrict__ ALf = g_WpreL[i];
    const float* __restrict__ Bsrc = ((i & 1) ? x2 : x1) + b * CC * NPIX;

    int tid = threadIdx.x;
    int wid = tid >> 5, lane = tid & 31;
    int g = lane >> 2, tig = lane & 3;
    int wm = (wid & 3) * 32, wn = (wid >> 2) * 32;

    int am = tid >> 2, akq = (tid & 3) * 8;
    int bk2 = tid >> 4, bn4 = (tid & 15) * 4;

    float4 sh0[2], sh1[2], sl0[2], sl1[2], sbe, sbo;
    float c[2][4][4] = {};

    auto loadT = [&](int k0) {
#pragma unroll
        for (int it = 0; it < 2; it++) {
            int m = am + it * 64;
            sh0[it] = *(const float4*)&AHf[m * CC + k0 + akq];
            sh1[it] = *(const float4*)&AHf[m * CC + k0 + akq + 4];
            sl0[it] = *(const float4*)&ALf[m * CC + k0 + akq];
            sl1[it] = *(const float4*)&ALf[m * CC + k0 + akq + 4];
        }
        const float* be = &Bsrc[(k0 + 2 * bk2) * NPIX + n0 + bn4];
        sbe = *(const float4*)be;
        sbo = *(const float4*)(be + NPIX);
    };
    auto storeT = [&]() {
#pragma unroll
        for (int it = 0; it < 2; it++) {
            int m = am + it * 64, kq2 = akq >> 1;
            *(uint4*)&Ah[m * 20 + kq2] = make_uint4(
                pack_bf(sh0[it].x, sh0[it].y), pack_bf(sh0[it].z, sh0[it].w),
                pack_bf(sh1[it].x, sh1[it].y), pack_bf(sh1[it].z, sh1[it].w));
            *(uint4*)&Al[m * 20 + kq2] = make_uint4(
                pack_bf(sl0[it].x, sl0[it].y), pack_bf(sl0[it].z, sl0[it].w),
                pack_bf(sl1[it].x, sl1[it].y), pack_bf(sl1[it].z, sl1[it].w));
        }
        uint32_t h0,l0,h1,l1,h2,l2,h3,l3;
        split_pack(sbe.x, sbo.x, h0, l0); split_pack(sbe.y, sbo.y, h1, l1);
        split_pack(sbe.z, sbo.z, h2, l2); split_pack(sbe.w, sbo.w, h3, l3);
        *(uint4*)&Bh[bk2 * 72 + bn4] = make_uint4(h0, h1, h2, h3);
        *(uint4*)&Bl[bk2 * 72 + bn4] = make_uint4(l0, l1, l2, l3);
    };

    loadT(0); storeT(); __syncthreads();
    for (int t = 0; t < 8; t++) {
        if (t < 7) loadT((t + 1) * 32);
#pragma unroll
        for (int kk2 = 0; kk2 < 16; kk2 += 8) {
            uint32_t ah[2][4], al[2][4];
#pragma unroll
            for (int mi = 0; mi < 2; mi++) {
                int mr = wm + mi * 16;
                ah[mi][0]=Ah[(mr+g  )*20+kk2+tig  ]; ah[mi][1]=Ah[(mr+g+8)*20+kk2+tig  ];
                ah[mi][2]=Ah[(mr+g  )*20+kk2+tig+4]; ah[mi][3]=Ah[(mr+g+8)*20+kk2+tig+4];
                al[mi][0]=Al[(mr+g  )*20+kk2+tig  ]; al[mi][1]=Al[(mr+g+8)*20+kk2+tig  ];
                al[mi][2]=Al[(mr+g  )*20+kk2+tig+4]; al[mi][3]=Al[(mr+g+8)*20+kk2+tig+4];
            }
#pragma unroll
            for (int ni = 0; ni < 4; ni++) {
                uint32_t bh[2], bl[2];
                bh[0]=Bh[(kk2+tig  )*72+wn+ni*8+g]; bh[1]=Bh[(kk2+tig+4)*72+wn+ni*8+g];
                bl[0]=Bl[(kk2+tig  )*72+wn+ni*8+g]; bl[1]=Bl[(kk2+tig+4)*72+wn+ni*8+g];
#pragma unroll
                for (int mi = 0; mi < 2; mi++) {
                    mma16bf(c[mi][ni], ah[mi], bh);
                    mma16bf(c[mi][ni], ah[mi], bl);
                    mma16bf(c[mi][ni], al[mi], bh);
                }
            }
        }
        __syncthreads();
        if (t < 7) storeT();
        __syncthreads();
    }

    float* Cout = g_PRE[i][b];
#pragma unroll
    for (int mi = 0; mi < 2; mi++) {
#pragma unroll
        for (int ni = 0; ni < 4; ni++) {
            int row = wm + mi * 16 + g;
            int col = n0 + wn + ni * 8 + tig * 2;
            float b0 = g_bpre[i][row], b1 = g_bpre[i][row + 8];
            *(float2*)&Cout[row * NPIX + col] =
                make_float2(c[mi][ni][0] + b0, c[mi][ni][1] + b0);
            *(float2*)&Cout[(row + 8) * NPIX + col] =
                make_float2(c[mi][ni][2] + b1, c[mi][ni][3] + b1);
        }
    }
}

__global__ void __launch_bounds__(256) k_pre23(const float* __restrict__ x1,
                                               const float* __restrict__ x2)
{
    __shared__ uint32_t pool[7424];
    int i = 2 + (blockIdx.z >> 2), b = blockIdx.z & 3;
    pre_body(pool, i, b, blockIdx.x * 64, x1, x2);
}

// ======================================================================
// etime body (R9)
// ======================================================================
__device__ __forceinline__ void etime_body(uint32_t* pool, int b, int ks, int n0)
{
    uint32_t* Ah = pool;
    uint32_t* Al = pool + 2560;
    uint32_t* Bh = pool + 5120;
    uint32_t* Bl = pool + 6400;
    int kbeg = ks * (NPIX / ETSPLIT);
    const float* __restrict__ Tm = g_PRE[2][b];
    const float* __restrict__ Pm = g_PRE[3][b];

    int tid = threadIdx.x;
    int wid = tid >> 5, lane = tid & 31;
    int g = lane >> 2, tig = lane & 3;
    int wm = (wid & 3) * 32, wn = (wid >> 2) * 32;

    int am = tid >> 1, ak = (tid & 1) * 16;
    int bn = tid >> 2, bk = (tid & 3) * 8;

    float4 sA[4], sB[2];
    float c[2][4][4] = {};

    auto loadT = [&](int k0) {
#pragma unroll
        for (int q = 0; q < 4; q++) sA[q] = *(const float4*)&Tm[am * NPIX + k0 + ak + q * 4];
#pragma unroll
        for (int q = 0; q < 2; q++) sB[q] = *(const float4*)&Pm[(n0 + bn) * NPIX + k0 + bk + q * 4];
    };
    auto storeT = [&]() {
#pragma unroll
        for (int q = 0; q < 4; q++) {
            uint32_t h0,l0,h1,l1;
            split_pack(sA[q].x, sA[q].y, h0, l0);
            split_pack(sA[q].z, sA[q].w, h1, l1);
            int k2 = (ak >> 1) + q * 2;
            Ah[am * 20 + k2] = h0; Ah[am * 20 + k2 + 1] = h1;
            Al[am * 20 + k2] = l0; Al[am * 20 + k2 + 1] = l1;
        }
#pragma unroll
        for (int q = 0; q < 2; q++) {
            uint32_t h0,l0,h1,l1;
            split_pack(sB[q].x, sB[q].y, h0, l0);
            split_pack(sB[q].z, sB[q].w, h1, l1);
            int k2 = (bk >> 1) + q * 2;
            Bh[bn * 20 + k2] = h0; Bh[bn * 20 + k2 + 1] = h1;
            Bl[bn * 20 + k2] = l0; Bl[bn * 20 + k2 + 1] = l1;
        }
    };

    loadT(kbeg); storeT(); __syncthreads();
    for (int t = 0; t < 4; t++) {
        if (t < 3) loadT(kbeg + (t + 1) * 32);
#pragma unroll
        for (int kk2 = 0; kk2 < 16; kk2 += 8) {
            uint32_t ah[2][4], al[2][4];
#pragma unroll
            for (int mi = 0; mi < 2; mi++) {
                int mr = wm + mi * 16;
                ah[mi][0]=Ah[(mr+g  )*20+kk2+tig  ]; ah[mi][1]=Ah[(mr+g+8)*20+kk2+tig  ];
                ah[mi][2]=Ah[(mr+g  )*20+kk2+tig+4]; ah[mi][3]=Ah[(mr+g+8)*20+kk2+tig+4];
                al[mi][0]=Al[(mr+g  )*20+kk2+tig  ]; al[mi][1]=Al[(mr+g+8)*20+kk2+tig  ];
                al[mi][2]=Al[(mr+g  )*20+kk2+tig+4]; al[mi][3]=Al[(mr+g+8)*20+kk2+tig+4];
            }
#pragma unroll
            for (int ni = 0; ni < 4; ni++) {
                int nr = wn + ni * 8 + g;
                uint32_t bh[2], bl[2];
                bh[0]=Bh[nr*20+kk2+tig]; bh[1]=Bh[nr*20+kk2+tig+4];
                bl[0]=Bl[nr*20+kk2+tig]; bl[1]=Bl[nr*20+kk2+tig+4];
#pragma unroll
                for (int mi = 0; mi < 2; mi++) {
                    mma16bf(c[mi][ni], ah[mi], bh);
                    mma16bf(c[mi][ni], ah[mi], bl);
                    mma16bf(c[mi][ni], al[mi], bh);
                }
            }
        }
        __syncthreads();
        if (t < 3) storeT();
        __syncthreads();
    }

    float* outp = g_ETpart[b][ks];
#pragma unroll
    for (int mi = 0; mi < 2; mi++) {
#pragma unroll
        for (int ni = 0; ni < 4; ni++) {
            int row = wm + mi * 16 + g;
            int col = n0 + wn + ni * 8 + tig * 2;
            *(float2*)&outp[row * CI + col]       = make_float2(c[mi][ni][0], c[mi][ni][1]);
            *(float2*)&outp[(row + 8) * CI + col] = make_float2(c[mi][ni][2], c[mi][ni][3]);
        }
    }
}

// ======================================================================
// espace body (R9)
// ======================================================================
__device__ __forceinline__ void espace_body(uint32_t* pool, int b, int row0, int col0)
{
    uint32_t* Ah = pool;
    uint32_t* Al = pool + 2176;
    uint32_t* Bh = pool + 4352;
    uint32_t* Bl = pool + 5504;
    const float* __restrict__ T = g_PRE[2][b];
    const float* __restrict__ P = g_PRE[3][b];

    int tid = threadIdx.x;
    int wid = tid >> 5, lane = tid & 31;
    int g = lane >> 2, tig = lane & 3;
    int wm = (wid & 3) * 32, wn = (wid >> 2) * 32;

    int ak2 = tid >> 5, an4 = (tid & 31) * 4;
    int bk2 = tid >> 4, bm4 = (tid & 15) * 4;

    float4 sAe[2], sAo[2], sBe, sBo;
    float c[2][4][4] = {};

    auto loadT = [&](int k0) {
#pragma unroll
        for (int it = 0; it < 2; it++) {
            const float* te = &T[(k0 + 2 * (ak2 + it * 8)) * NPIX + row0 + an4];
            sAe[it] = *(const float4*)te;
            sAo[it] = *(const float4*)(te + NPIX);
        }
        const float* pe = &P[(k0 + 2 * bk2) * NPIX + col0 + bm4];
        sBe = *(const float4*)pe;
        sBo = *(const float4*)(pe + NPIX);
    };
    auto storeT = [&]() {
#pragma unroll
        for (int it = 0; it < 2; it++) {
            uint32_t h0,l0,h1,l1,h2,l2,h3,l3;
            split_pack(sAe[it].x, sAo[it].x, h0, l0); split_pack(sAe[it].y, sAo[it].y, h1, l1);
            split_pack(sAe[it].z, sAo[it].z, h2, l2); split_pack(sAe[it].w, sAo[it].w, h3, l3);
            int r = ak2 + it * 8;
            *(uint4*)&Ah[r * 136 + an4] = make_uint4(h0, h1, h2, h3);
            *(uint4*)&Al[r * 136 + an4] = make_uint4(l0, l1, l2, l3);
        }
        uint32_t h0,l0,h1,l1,h2,l2,h3,l3;
        split_pack(sBe.x, sBo.x, h0, l0); split_pack(sBe.y, sBo.y, h1, l1);
        split_pack(sBe.z, sBo.z, h2, l2); split_pack(sBe.w, sBo.w, h3, l3);
        *(uint4*)&Bh[bk2 * 72 + bm4] = make_uint4(h0, h1, h2, h3);
        *(uint4*)&Bl[bk2 * 72 + bm4] = make_uint4(l0, l1, l2, l3);
    };

    loadT(0); storeT(); __syncthreads();
    for (int t = 0; t < 4; t++) {
        if (t < 3) loadT((t + 1) * 32);
#pragma unroll
        for (int kk2 = 0; kk2 < 16; kk2 += 8) {
            uint32_t ah[2][4], al[2][4];
#pragma unroll
            for (int mi = 0; mi < 2; mi++) {
                int mr = wm + mi * 16;
                ah[mi][0] = Ah[(kk2+tig  )*136 + mr + g    ];
                ah[mi][1] = Ah[(kk2+tig  )*136 + mr + g + 8];
                ah[mi][2] = Ah[(kk2+tig+4)*136 + mr + g    ];
                ah[mi][3] = Ah[(kk2+tig+4)*136 + mr + g + 8];
                al[mi][0] = Al[(kk2+tig  )*136 + mr + g    ];
                al[mi][1] = Al[(kk2+tig  )*136 + mr + g + 8];
                al[mi][2] = Al[(kk2+tig+4)*136 + mr + g    ];
                al[mi][3] = Al[(kk2+tig+4)*136 + mr + g + 8];
            }
#pragma unroll
            for (int ni = 0; ni < 4; ni++) {
                uint32_t bh[2], bl[2];
                bh[0] = Bh[(kk2+tig  )*72 + wn + ni*8 + g];
                bh[1] = Bh[(kk2+tig+4)*72 + wn + ni*8 + g];
                bl[0] = Bl[(kk2+tig  )*72 + wn + ni*8 + g];
                bl[1] = Bl[(kk2+tig+4)*72 + wn + ni*8 + g];
#pragma unroll
                for (int mi = 0; mi < 2; mi++) {
                    mma16bf(c[mi][ni], ah[mi], bh);
                    mma16bf(c[mi][ni], ah[mi], bl);
                    mma16bf(c[mi][ni], al[mi], bh);
                }
            }
        }
        __syncthreads();
        if (t < 3) storeT();
        __syncthreads();
    }

    float* Ep = g_E[b];
#pragma unroll
    for (int mi = 0; mi < 2; mi++) {
#pragma unroll
        for (int ni = 0; ni < 4; ni++) {
            int row = row0 + wm + mi * 16 + g;
            int col = col0 + wn + ni * 8 + tig * 2;
            *(float2*)&Ep[row * NPIX + col]       = make_float2(c[mi][ni][0], c[mi][ni][1]);
            *(float2*)&Ep[(row + 8) * NPIX + col] = make_float2(c[mi][ni][2], c[mi][ni][3]);
        }
    }
}

// ======================================================================
// BIG3: pre01 (288) | etime (144) | espace (2592)
// ======================================================================
__global__ void __launch_bounds__(256) k_big3(const float* __restrict__ x1,
                                              const float* __restrict__ x2)
{
    __shared__ uint32_t pool[7680];
    int bx = blockIdx.x;
    if (bx < 288) {
        int x = bx % 36, iz = bx / 36;
        pre_body(pool, iz >> 2, iz & 3, x * 64, x1, x2);
    } else if (bx < 432) {
        int idx = bx - 288;
        int x = idx % 2, ks = (idx / 2) % 18, b = idx / 36;
        etime_body(pool, b, ks, x * 64);
    } else {
        int idx = bx - 432;
        int x = idx % 36, y = (idx / 36) % 18, b = idx / 648;
        espace_body(pool, b, y * 128, x * 64);
    }
}

// ======================================================================
// k_softA: grid (32, BATCH): orient = bx&1, strip = bx>>1 (8 rows/cols)
// ======================================================================
__global__ void __launch_bounds__(256) k_softA()
{
    int b = blockIdx.y;
    int orient = blockIdx.x & 1;
    int strip = blockIdx.x >> 1;       // 0..15, 8 rows/cols each
    int tid = threadIdx.x, wid = tid >> 5, lane = tid & 31;
    __shared__ float ETs[128][9];

    if (orient == 0) {
        int t = strip * 8 + wid;
        float v[4];
#pragma unroll
        for (int j = 0; j < 4; j++) {
            int d = lane + j * 32;
            float s = 0.f;
#pragma unroll
            for (int p = 0; p < ETSPLIT; p++) s += g_ETpart[b][p][t * CI + d];
            v[j] = s;
        }
        float mx = fmaxf(fmaxf(v[0], v[1]), fmaxf(v[2], v[3]));
#pragma unroll
        for (int off = 16; off; off >>= 1) mx = fmaxf(mx, __shfl_xor_sync(0xffffffffu, mx, off));
        float e[4]; float sum = 0.f;
#pragma unroll
        for (int j = 0; j < 4; j++) { e[j] = __expf(v[j] - mx); sum += e[j]; }
#pragma unroll
        for (int off = 16; off; off >>= 1) sum += __shfl_xor_sync(0xffffffffu, sum, off);
        float rs = 1.f / sum;
#pragma unroll
        for (int j = 0; j < 4; j++) {
            float own = e[j] * rs;
            float part = __shfl_xor_sync(0xffffffffu, own, 1);
            if (!(lane & 1)) {
                float oh = bf_round(own), ph = bf_round(part);
                int k2 = (lane >> 1) + 16 * j;
                g_Apack[1][b][0][t * 64 + k2] = pack_bf(oh, ph);
                g_Apack[1][b][1][t * 64 + k2] = pack_bf(own - oh, part - ph);
            }
        }
    } else {
        int c0 = strip * 8;
        for (int idx = tid; idx < 128 * 8; idx += 256) {
            int d = idx >> 3, cc = idx & 7;
            float s = 0.f;
#pragma unroll
            for (int p = 0; p < ETSPLIT; p++) s += g_ETpart[b][p][d * CI + c0 + cc];
            ETs[d][cc] = s;
        }
        __syncthreads();
        int ccol = c0 + wid;
        float v[4];
#pragma unroll
        for (int j = 0; j < 4; j++) v[j] = ETs[lane + 32 * j][wid];
        float mx = fmaxf(fmaxf(v[0], v[1]), fmaxf(v[2], v[3]));
#pragma unroll
        for (int off = 16; off; off >>= 1) mx = fmaxf(mx, __shfl_xor_sync(0xffffffffu, mx, off));
        float e[4]; float sum = 0.f;
#pragma unroll
        for (int j = 0; j < 4; j++) { e[j] = __expf(v[j] - mx); sum += e[j]; }
#pragma unroll
        for (int off = 16; off; off >>= 1) sum += __shfl_xor_sync(0xffffffffu, sum, off);
        float rs = 1.f / sum;
#pragma unroll
        for (int j = 0; j < 4; j++) {
            float own = e[j] * rs;
            float part = __shfl_xor_sync(0xffffffffu, own, 1);
            if (!(lane & 1)) {
                float oh = bf_round(own), ph = bf_round(part);
                int k2 = (lane >> 1) + 16 * j;
                g_Apack[0][b][0][ccol * 64 + k2] = pack_bf(oh, ph);
                g_Apack[0][b][1][ccol * 64 + k2] = pack_bf(own - oh, part - ph);
            }
        }
    }
}

// ======================================================================
// zgemm body (R11)
// ======================================================================
__device__ __forceinline__ void zgemm_body(uint32_t* pool, int zi, int b, int n0)
{
    uint32_t* Ah = pool;
    uint32_t* Al = pool + 2560;
    uint32_t* Bh = pool + 5120;
    uint32_t* Bl = pool + 6272;
    const uint32_t* __restrict__ AhG = g_Apack[zi][b][0];
    const uint32_t* __restrict__ AlG = g_Apack[zi][b][1];
    const float* __restrict__ Bsrc = g_PRE[zi][b];

    int tid = threadIdx.x;
    int wid = tid >> 5, lane = tid & 31;
    int g = lane >> 2, tig = lane & 3;
    int wm = (wid & 3) * 32, wn = (wid >> 2) * 32;

    int am = tid >> 1, half8 = (tid & 1) * 8;
    int bk2 = tid >> 4, bn4 = (tid & 15) * 4;

    uint4 sAh0, sAh1, sAl0, sAl1;
    float4 sbe, sbo;
    float c[2][4][4] = {};

    auto loadT = [&](int k0) {
        int k2b = (k0 >> 1) + half8;
        sAh0 = *(const uint4*)&AhG[am * 64 + k2b];
        sAh1 = *(const uint4*)&AhG[am * 64 + k2b + 4];
        sAl0 = *(const uint4*)&AlG[am * 64 + k2b];
        sAl1 = *(const uint4*)&AlG[am * 64 + k2b + 4];
        const float* be = &Bsrc[(k0 + 2 * bk2) * NPIX + n0 + bn4];
        sbe = *(const float4*)be;
        sbo = *(const float4*)(be + NPIX);
    };
    auto storeT = [&]() {
        *(uint4*)&Ah[am * 20 + half8]     = sAh0;
        *(uint4*)&Ah[am * 20 + half8 + 4] = sAh1;
        *(uint4*)&Al[am * 20 + half8]     = sAl0;
        *(uint4*)&Al[am * 20 + half8 + 4] = sAl1;
        uint32_t h0,l0,h1,l1,h2,l2,h3,l3;
        split_pack(sbe.x, sbo.x, h0, l0); split_pack(sbe.y, sbo.y, h1, l1);
        split_pack(sbe.z, sbo.z, h2, l2); split_pack(sbe.w, sbo.w, h3, l3);
        *(uint4*)&Bh[bk2 * 72 + bn4] = make_uint4(h0, h1, h2, h3);
        *(uint4*)&Bl[bk2 * 72 + bn4] = make_uint4(l0, l1, l2, l3);
    };

    loadT(0); storeT(); __syncthreads();
    for (int t = 0; t < 4; t++) {
        if (t < 3) loadT((t + 1) * 32);
#pragma unroll
        for (int kk2 = 0; kk2 < 16; kk2 += 8) {
            uint32_t ah[2][4], al[2][4];
#pragma unroll
            for (int mi = 0; mi < 2; mi++) {
                int mr = wm + mi * 16;
                ah[mi][0]=Ah[(mr+g  )*20+kk2+tig  ]; ah[mi][1]=Ah[(mr+g+8)*20+kk2+tig  ];
                ah[mi][2]=Ah[(mr+g  )*20+kk2+tig+4]; ah[mi][3]=Ah[(mr+g+8)*20+kk2+tig+4];
                al[mi][0]=Al[(mr+g  )*20+kk2+tig  ]; al[mi][1]=Al[(mr+g+8)*20+kk2+tig  ];
                al[mi][2]=Al[(mr+g  )*20+kk2+tig+4]; al[mi][3]=Al[(mr+g+8)*20+kk2+tig+4];
            }
#pragma unroll
            for (int ni = 0; ni < 4; ni++) {
                uint32_t bh[2], bl[2];
                bh[0]=Bh[(kk2+tig  )*72+wn+ni*8+g]; bh[1]=Bh[(kk2+tig+4)*72+wn+ni*8+g];
                bl[0]=Bl[(kk2+tig  )*72+wn+ni*8+g]; bl[1]=Bl[(kk2+tig+4)*72+wn+ni*8+g];
#pragma unroll
                for (int mi = 0; mi < 2; mi++) {
                    mma16bf(c[mi][ni], ah[mi], bh);
                    mma16bf(c[mi][ni], ah[mi], bl);
                    mma16bf(c[mi][ni], al[mi], bh);
                }
            }
        }
        __syncthreads();
        if (t < 3) storeT();
        __syncthreads();
    }

    uint32_t* Zout = g_Zpack[zi][b];
#pragma unroll
    for (int mi = 0; mi < 2; mi++) {
#pragma unroll
        for (int ni = 0; ni < 4; ni++) {
            int row = wm + mi * 16 + g;
            int colh = ((n0 + wn + ni * 8) >> 1) + tig;
            Zout[row * NPK2 + colh]       = pack_bf(c[mi][ni][0], c[mi][ni][1]);
            Zout[(row + 8) * NPK2 + colh] = pack_bf(c[mi][ni][2], c[mi][ni][3]);
        }
    }
}

// ---------------- stats bodies ----------------
__device__ __forceinline__ void colpart_body(int b, int ch, int m)
{
    const float* Ep = g_E[b];
    float mx = -3.0e38f, s = 0.f;
    int n0 = ch * (NPIX / NCHUNK);
    for (int n = n0; n < n0 + NPIX / NCHUNK; n++) {
        float v = Ep[(size_t)n * NPIX + m];
        if (v > mx) { s = s * __expf(mx - v) + 1.f; mx = v; }
        else        { s += __expf(v - mx); }
    }
    g_pmax[b][ch][m] = mx;
    g_psum[b][ch][m] = s;
}

__device__ __forceinline__ void rowstats_body(int b, int n, int lane)
{
    const float* row = g_E[b] + (size_t)n * NPIX;
    float mx = -3.0e38f, s = 0.f;
    for (int m = lane; m < NPIX; m += 32) {
        float v = row[m];
        if (v > mx) { s = s * __expf(mx - v) + 1.f; mx = v; }
        else        { s += __expf(v - mx); }
    }
#pragma unroll
    for (int off = 16; off; off >>= 1) {
        float om = __shfl_xor_sync(0xffffffffu, mx, off);
        float os = __shfl_xor_sync(0xffffffffu, s, off);
        float nm = fmaxf(mx, om);
        s = s * __expf(mx - nm) + os * __expf(om - nm);
        mx = nm;
    }
    if (lane == 0) { g_rowmax[b][n] = mx; g_rowrsum[b][n] = 1.f / s; }
}

__global__ void __launch_bounds__(256) k_zps()
{
    __shared__ uint32_t pool[7424];
    int bx = blockIdx.x;
    if (bx < 288) {
        int x = bx % 36, iz = bx / 36;
        zgemm_body(pool, iz >> 2, iz & 3, x * 64);
    } else if (bx < 936) {
        int idx = bx - 288;
        int mb = idx % 9, ch = (idx / 9) % 18, b = idx / 162;
        colpart_body(b, ch, mb * 256 + threadIdx.x);
    } else {
        int idx = bx - 936;
        int xb = idx % 288, b = idx / 288;
        rowstats_body(b, xb * 8 + (threadIdx.x >> 5), threadIdx.x & 31);
    }
}

// ======================================================================
// k_ygemm_fused: double-buffered main loop (stage = 3840 words: A 2560 + B 1280),
// Ysf overlays stage1+ after loop. Post GEMM 3-term bf16 + residual.
// ======================================================================
__global__ void __launch_bounds__(256) k_ygemm_fused(const float* __restrict__ x1,
                                                     const float* __restrict__ x2,
                                                     float* __restrict__ out)
{
    __shared__ uint32_t pool[12032];
    __shared__ float s_max[64], s_rs[64];

    float*    Ysf = (float*)(pool + 3840);// [128][64]
    uint32_t* Ysh = pool + 3840;          // [64][64]
    uint32_t* Ysl = pool + 7936;          // [64][64]
    uint32_t* WAh = pool;                 // post: [128][10]
    uint32_t* WAl = pool + 1280;          // post: [128][10]

    int yi = blockIdx.z >> 2, b = blockIdx.z & 3;
    int n0 = blockIdx.x * 64;
    const uint32_t* __restrict__ Zp = g_Zpack[yi][b];
    const float* __restrict__ Ep = g_E[b];

    int tid = threadIdx.x;
    int wid = tid >> 5, lane = tid & 31;
    int g = lane >> 2, tig = lane & 3;
    int wm = (wid & 3) * 32, wn = (wid >> 2) * 32;

    if (tid < 64) {
        if (yi == 0) {
            int m = n0 + tid;
            float mx = -3.0e38f, s = 0.f;
#pragma unroll
            for (int ch = 0; ch < NCHUNK; ch++) {
                float pm = g_pmax[b][ch][m], ps = g_psum[b][ch][m];
                float nm = fmaxf(mx, pm);
                s = s * __expf(mx - nm) + ps * __expf(pm - nm);
                mx = nm;
            }
            s_max[tid] = mx; s_rs[tid] = 1.f / s;
        } else {
            s_max[tid] = g_rowmax[b][n0 + tid];
            s_rs[tid]  = g_rowrsum[b][n0 + tid];
        }
    }
    __syncthreads();

    int am = tid >> 1, half8 = (tid & 1) * 8;
    int bk2g = tid >> 4, bn4 = (tid & 15) * 4;   // yi=0
    int bj = tid >> 2, bkq = (tid & 3) * 8;      // yi=1

    uint4 sZ0, sZ1;
    float4 sB0, sB1;
    float c[2][4][4] = {};

    auto loadT = [&](int k0) {
        int k2b = (k0 >> 1) + half8;
        sZ0 = *(const uint4*)&Zp[am * NPK2 + k2b];
        sZ1 = *(const uint4*)&Zp[am * NPK2 + k2b + 4];
        if (yi == 0) {
            const float* be = &Ep[(size_t)(k0 + 2 * bk2g) * NPIX + n0 + bn4];
            sB0 = *(const float4*)be;
            sB1 = *(const float4*)(be + NPIX);
        } else {
            const float* be = &Ep[(size_t)(n0 + bj) * NPIX + k0 + bkq];
            sB0 = *(const float4*)be;
            sB1 = *(const float4*)(be + 4);
        }
    };
    auto storeT = [&](int s) {
        uint32_t* A2m = pool + s * 3840;
        uint32_t* Bs  = A2m + 2560;
        *(uint4*)&A2m[am * 20 + half8]     = sZ0;
        *(uint4*)&A2m[am * 20 + half8 + 4] = sZ1;
        if (yi == 0) {
            float m0v = s_max[bn4], m1v = s_max[bn4+1], m2v = s_max[bn4+2], m3v = s_max[bn4+3];
            *(uint4*)&Bs[bk2g * 72 + bn4] = make_uint4(
                pack_bf(__expf(sB0.x - m0v), __expf(sB1.x - m0v)),
                pack_bf(__expf(sB0.y - m1v), __expf(sB1.y - m1v)),
                pack_bf(__expf(sB0.z - m2v), __expf(sB1.z - m2v)),
                pack_bf(__expf(sB0.w - m3v), __expf(sB1.w - m3v)));
        } else {
            float mx = s_max[bj];
            *(uint4*)&Bs[bj * 20 + (bkq >> 1)] = make_uint4(
                pack_bf(__expf(sB0.x - mx), __expf(sB0.y - mx)),
                pack_bf(__expf(sB0.z - mx), __expf(sB0.w - mx)),
                pack_bf(__expf(sB1.x - mx), __expf(sB1.y - mx)),
                pack_bf(__expf(sB1.z - mx), __expf(sB1.w - mx)));
        }
    };

    loadT(0); storeT(0); __syncthreads();
    for (int t = 0; t < 72; t++) {
        int cur = t & 1;
        uint32_t* A2m = pool + cur * 3840;
        uint32_t* Bs  = A2m + 2560;
        if (t < 71) loadT((t + 1) * 32);
#pragma unroll
        for (int kk2 = 0; kk2 < 16; kk2 += 8) {
            uint32_t a[2][4];
#pragma unroll
            for (int mi = 0; mi < 2; mi++) {
                int mr = wm + mi * 16;
                a[mi][0]=A2m[(mr+g  )*20+kk2+tig  ]; a[mi][1]=A2m[(mr+g+8)*20+kk2+tig  ];
                a[mi][2]=A2m[(mr+g  )*20+kk2+tig+4]; a[mi][3]=A2m[(mr+g+8)*20+kk2+tig+4];
            }
#pragma unroll
            for (int ni = 0; ni < 4; ni++) {
                uint32_t bb[2];
                if (yi == 0) {
                    bb[0] = Bs[(kk2+tig  ) * 72 + wn + ni*8 + g];
                    bb[1] = Bs[(kk2+tig+4) * 72 + wn + ni*8 + g];
                } else {
                    int nr = wn + ni * 8 + g;
                    bb[0] = Bs[nr * 20 + kk2 + tig    ];
                    bb[1] = Bs[nr * 20 + kk2 + tig + 4];
                }
                mma16bf(c[0][ni], a[0], bb);
                mma16bf(c[1][ni], a[1], bb);
            }
        }
        if (t < 71) storeT(1 - cur);
        __syncthreads();
    }

    // Y tile -> smem fp32 (scaled)
#pragma unroll
    for (int mi = 0; mi < 2; mi++) {
#pragma unroll
        for (int ni = 0; ni < 4; ni++) {
            int row = wm + mi * 16 + g;
            int col = wn + ni * 8 + tig * 2;
            Ysf[row * 64 + col]           = c[mi][ni][0] * s_rs[col];
            Ysf[row * 64 + col + 1]       = c[mi][ni][1] * s_rs[col + 1];
            Ysf[(row + 8) * 64 + col]     = c[mi][ni][2] * s_rs[col];
            Ysf[(row + 8) * 64 + col + 1] = c[mi][ni][3] * s_rs[col + 1];
        }
    }
    __syncthreads();

    // pack Y in place
    {
        int n = tid & 63, kq = tid >> 6;
        float fe[16], fo[16];
#pragma unroll
        for (int e = 0; e < 16; e++) {
            int k2 = kq * 16 + e;
            fe[e] = Ysf[(2 * k2) * 64 + n];
            fo[e] = Ysf[(2 * k2 + 1) * 64 + n];
        }
        __syncthreads();
#pragma unroll
        for (int e = 0; e < 16; e++) {
            int k2 = kq * 16 + e;
            uint32_t hp, lp;
            split_pack(fe[e], fo[e], hp, lp);
            Ysh[k2 * 64 + n] = hp;
            Ysl[k2 * 64 + n] = lp;
        }
    }
    __syncthreads();

    // post GEMM + bias + residual
    const float* __restrict__ Wp = g_Wpost[yi];
    const float* xs = (yi ? x2 : x1) + b * CC * NPIX;
    float* op = out + (size_t)yi * BATCH * CC * NPIX + (size_t)b * CC * NPIX;
    int wm2 = tid >> 1, wsel = tid & 1;

    for (int hh = 0; hh < 2; hh++) {
        int m0 = hh * 128;
        float c2[2][4][4] = {};
        for (int kc = 0; kc < 8; kc++) {
            {
                const float* wr = &Wp[(m0 + wm2) * CI + kc * 16 + wsel * 8];
                float4 w0 = *(const float4*)wr;
                float4 w1 = *(const float4*)(wr + 4);
                uint32_t h0,l0,h1,l1,h2,l2,h3,l3;
                split_pack(w0.x, w0.y, h0, l0); split_pack(w0.z, w0.w, h1, l1);
                split_pack(w1.x, w1.y, h2, l2); split_pack(w1.z, w1.w, h3, l3);
                int base = wm2 * 10 + wsel * 4;
                WAh[base+0]=h0; WAh[base+1]=h1; WAh[base+2]=h2; WAh[base+3]=h3;
                WAl[base+0]=l0; WAl[base+1]=l1; WAl[base+2]=l2; WAl[base+3]=l3;
            }
            __syncthreads();
            uint32_t ah[2][4], al[2][4];
#pragma unroll
            for (int mi = 0; mi < 2; mi++) {
                int mr = wm + mi * 16;
                ah[mi][0]=WAh[(mr+g  )*10+tig  ]; ah[mi][1]=WAh[(mr+g+8)*10+tig  ];
                ah[mi][2]=WAh[(mr+g  )*10+tig+4]; ah[mi][3]=WAh[(mr+g+8)*10+tig+4];
                al[mi][0]=WAl[(mr+g  )*10+tig  ]; al[mi][1]=WAl[(mr+g+8)*10+tig  ];
                al[mi][2]=WAl[(mr+g  )*10+tig+4]; al[mi][3]=WAl[(mr+g+8)*10+tig+4];
            }
#pragma unroll
            for (int ni = 0; ni < 4; ni++) {
                uint32_t bh[2], bl[2];
                bh[0] = Ysh[(kc*8+tig  )*64 + wn + ni*8 + g];
                bh[1] = Ysh[(kc*8+tig+4)*64 + wn + ni*8 + g];
                bl[0] = Ysl[(kc*8+tig  )*64 + wn + ni*8 + g];
                bl[1] = Ysl[(kc*8+tig+4)*64 + wn + ni*8 + g];
#pragma unroll
                for (int mi = 0; mi < 2; mi++) {
                    mma16bf(c2[mi][ni], ah[mi], bh);
                    mma16bf(c2[mi][ni], ah[mi], bl);
                    mma16bf(c2[mi][ni], al[mi], bh);
                }
            }
            __syncthreads();
        }
#pragma unroll
        for (int mi = 0; mi < 2; mi++) {
#pragma unroll
            for (int ni = 0; ni < 4; ni++) {
                int row = m0 + wm + mi * 16 + g;
                int col = n0 + wn + ni * 8 + tig * 2;
                float b0 = g_bpost[yi][row], b1 = g_bpost[yi][row + 8];
                float2 r0 = *(const float2*)&xs[row * NPIX + col];
                float2 r1 = *(const float2*)&xs[(row + 8) * NPIX + col];
                *(float2*)&op[row * NPIX + col] =
                    make_float2(c2[mi][ni][0] + b0 + r0.x, c2[mi][ni][1] + b0 + r0.y);
                *(float2*)&op[(row + 8) * NPIX + col] =
                    make_float2(c2[mi][ni][2] + b1 + r1.x, c2[mi][ni][3] + b1 + r1.y);
            }
        }
    }
}

// ---------------- launcher ----------------
extern "C" void kernel_launch(void* const* d_in, const int* in_sizes, int n_in,
                              void* d_out, int out_size)
{
    const float* x1      = (const float*)d_in[0];
    const float* x2      = (const float*)d_in[1];
    const float* bn_pre  = (const float*)d_in[2];
    const float* w_pre   = (const float*)d_in[3];
    const float* b_pre   = (const float*)d_in[4];
    const float* w_post  = (const float*)d_in[5];
    const float* b_post  = (const float*)d_in[6];
    const float* bn_post = (const float*)d_in[7];
    float* out = (float*)d_out;

    k_fold<<<128, 256>>>(bn_pre, w_pre, b_pre, w_post, b_post, bn_post);
    k_pre23<<<dim3(36, 1, 8), 256>>>(x1, x2);
    k_big3<<<3024, 256>>>(x1, x2);
    k_softA<<<dim3(32, BATCH), 256>>>();
    k_zps<<<2088, 256>>>();
    k_ygemm_fused<<<dim3(36, 1, 8), 256>>>(x1, x2, out);
}

// round 14
// speedup vs baseline: 1.5155x; 1.1527x over previous
#include <cuda_runtime.h>
#include <cuda_bf16.h>
#include <math.h>
#include <stdint.h>

#define BATCH 4
#define CC 256
#define CI 128
#define NPIX 2304
#define NPK2 1152
#define BNEPS 1e-5f
#define NCHUNK 18
#define ETSPLIT 18

// ---------------- scratch ----------------
__device__ float g_PRE[4][BATCH][CI*NPIX];
__device__ float g_ETpart[BATCH][ETSPLIT][CI*CI];
__device__ uint32_t g_Apack[2][BATCH][2][CI*64];
__device__ float g_E[BATCH][NPIX*NPIX];
__device__ uint32_t g_Zpack[2][BATCH][CI*NPK2];
__device__ float g_rowmax[BATCH][NPIX];
__device__ float g_rowrsum[BATCH][NPIX];
__device__ float g_pmax[BATCH][NCHUNK][NPIX];
__device__ float g_psum[BATCH][NCHUNK][NPIX];
__device__ float g_rpmax[BATCH][36][NPIX];
__device__ float g_rpsum[BATCH][36][NPIX];
__device__ float g_WpreH[4][CI*CC];
__device__ float g_WpreL[4][CI*CC];
__device__ float g_bpre[4][CI];
__device__ float g_Wpost[2][CC*CI];
__device__ float g_bpost[2][CC];

// ---------------- helpers ----------------
__device__ __forceinline__ uint32_t pack_bf(float e, float o) {
    uint32_t r;
    asm("cvt.rn.bf16x2.f32 %0, %1, %2;" : "=r"(r) : "f"(o), "f"(e));
    return r;
}
__device__ __forceinline__ float bf_round(float x) {
    return __bfloat162float(__float2bfloat16(x));
}
__device__ __forceinline__ void mma16bf(float c[4], const uint32_t a[4], const uint32_t b[2]) {
    asm volatile(
        "mma.sync.aligned.m16n8k16.row.col.f32.bf16.bf16.f32 "
        "{%0,%1,%2,%3}, {%4,%5,%6,%7}, {%8,%9}, {%0,%1,%2,%3};"
        : "+f"(c[0]), "+f"(c[1]), "+f"(c[2]), "+f"(c[3])
        : "r"(a[0]), "r"(a[1]), "r"(a[2]), "r"(a[3]), "r"(b[0]), "r"(b[1]));
}
__device__ __forceinline__ void split_pack(float e, float o, uint32_t& hp, uint32_t& lp) {
    float eh = bf_round(e), oh = bf_round(o);
    hp = pack_bf(eh, oh);
    lp = pack_bf(e - eh, o - oh);
}
__device__ __forceinline__ void ms_merge(float& mx, float& s, float om, float os) {
    float nm = fmaxf(mx, om);
    s = s * __expf(mx - nm) + os * __expf(om - nm);
    mx = nm;
}

// ======================================================================
// k_fold
// ======================================================================
__global__ void __launch_bounds__(256) k_fold(
    const float* __restrict__ bn_pre, const float* __restrict__ w_pre,
    const float* __restrict__ b_pre, const float* __restrict__ w_post,
    const float* __restrict__ b_post, const float* __restrict__ bn_post)
{
    int w = blockIdx.x * 8 + (threadIdx.x >> 5);
    int lane = threadIdx.x & 31;
    if (w < 512) {
        int i = w >> 7, o = w & 127;
        const float* bp = bn_pre + i * 4 * CC;
        const float* wr = w_pre + (i * CI + o) * CC;
        float acc = 0.f;
        for (int c = lane; c < CC; c += 32) {
            float s = bp[c] * rsqrtf(bp[3 * CC + c] + BNEPS);
            float t = bp[CC + c] - bp[2 * CC + c] * s;
            float wv = wr[c] * s;
            float h = bf_round(wv);
            g_WpreH[i][o * CC + c] = h;
            g_WpreL[i][o * CC + c] = wv - h;
            acc = fmaf(wr[c], t, acc);
        }
#pragma unroll
        for (int off = 16; off; off >>= 1) acc += __shfl_xor_sync(0xffffffffu, acc, off);
        if (lane == 0) g_bpre[i][o] = acc + b_pre[i * CI + o];
    } else {
        int w2 = w - 512;
        int i = w2 >> 8, o = w2 & 255;
        const float* bp = bn_post + i * 4 * CC;
        float s = bp[o] * rsqrtf(bp[3 * CC + o] + BNEPS);
        const float* wr = w_post + (i * CC + o) * CI;
        for (int c = lane; c < CI; c += 32)
            g_Wpost[i][o * CI + c] = wr[c] * s;
        if (lane == 0)
            g_bpost[i][o] = b_post[i * CC + o] * s + bp[CC + o] - bp[2 * CC + o] * s;
    }
}

// ======================================================================
// pre body
// ======================================================================
__device__ __forceinline__ void pre_body(uint32_t* pool, int i, int b, int n0,
                                         const float* __restrict__ x1,
                                         const float* __restrict__ x2)
{
    uint32_t* Ah = pool;
    uint32_t* Al = pool + 2560;
    uint32_t* Bh = pool + 5120;
    uint32_t* Bl = pool + 6272;
    const float* __restrict__ AHf = g_WpreH[i];
    const float* __restrict__ ALf = g_WpreL[i];
    const float* __restrict__ Bsrc = ((i & 1) ? x2 : x1) + b * CC * NPIX;

    int tid = threadIdx.x;
    int wid = tid >> 5, lane = tid & 31;
    int g = lane >> 2, tig = lane & 3;
    int wm = (wid & 3) * 32, wn = (wid >> 2) * 32;

    int am = tid >> 2, akq = (tid & 3) * 8;
    int bk2 = tid >> 4, bn4 = (tid & 15) * 4;

    float4 sh0[2], sh1[2], sl0[2], sl1[2], sbe, sbo;
    float c[2][4][4] = {};

    auto loadT = [&](int k0) {
#pragma unroll
        for (int it = 0; it < 2; it++) {
            int m = am + it * 64;
            sh0[it] = *(const float4*)&AHf[m * CC + k0 + akq];
            sh1[it] = *(const float4*)&AHf[m * CC + k0 + akq + 4];
            sl0[it] = *(const float4*)&ALf[m * CC + k0 + akq];
            sl1[it] = *(const float4*)&ALf[m * CC + k0 + akq + 4];
        }
        const float* be = &Bsrc[(k0 + 2 * bk2) * NPIX + n0 + bn4];
        sbe = *(const float4*)be;
        sbo = *(const float4*)(be + NPIX);
    };
    auto storeT = [&]() {
#pragma unroll
        for (int it = 0; it < 2; it++) {
            int m = am + it * 64, kq2 = akq >> 1;
            *(uint4*)&Ah[m * 20 + kq2] = make_uint4(
                pack_bf(sh0[it].x, sh0[it].y), pack_bf(sh0[it].z, sh0[it].w),
                pack_bf(sh1[it].x, sh1[it].y), pack_bf(sh1[it].z, sh1[it].w));
            *(uint4*)&Al[m * 20 + kq2] = make_uint4(
                pack_bf(sl0[it].x, sl0[it].y), pack_bf(sl0[it].z, sl0[it].w),
                pack_bf(sl1[it].x, sl1[it].y), pack_bf(sl1[it].z, sl1[it].w));
        }
        uint32_t h0,l0,h1,l1,h2,l2,h3,l3;
        split_pack(sbe.x, sbo.x, h0, l0); split_pack(sbe.y, sbo.y, h1, l1);
        split_pack(sbe.z, sbo.z, h2, l2); split_pack(sbe.w, sbo.w, h3, l3);
        *(uint4*)&Bh[bk2 * 72 + bn4] = make_uint4(h0, h1, h2, h3);
        *(uint4*)&Bl[bk2 * 72 + bn4] = make_uint4(l0, l1, l2, l3);
    };

    loadT(0); storeT(); __syncthreads();
    for (int t = 0; t < 8; t++) {
        if (t < 7) loadT((t + 1) * 32);
#pragma unroll
        for (int kk2 = 0; kk2 < 16; kk2 += 8) {
            uint32_t ah[2][4], al[2][4];
#pragma unroll
            for (int mi = 0; mi < 2; mi++) {
                int mr = wm + mi * 16;
                ah[mi][0]=Ah[(mr+g  )*20+kk2+tig  ]; ah[mi][1]=Ah[(mr+g+8)*20+kk2+tig  ];
                ah[mi][2]=Ah[(mr+g  )*20+kk2+tig+4]; ah[mi][3]=Ah[(mr+g+8)*20+kk2+tig+4];
                al[mi][0]=Al[(mr+g  )*20+kk2+tig  ]; al[mi][1]=Al[(mr+g+8)*20+kk2+tig  ];
                al[mi][2]=Al[(mr+g  )*20+kk2+tig+4]; al[mi][3]=Al[(mr+g+8)*20+kk2+tig+4];
            }
#pragma unroll
            for (int ni = 0; ni < 4; ni++) {
                uint32_t bh[2], bl[2];
                bh[0]=Bh[(kk2+tig  )*72+wn+ni*8+g]; bh[1]=Bh[(kk2+tig+4)*72+wn+ni*8+g];
                bl[0]=Bl[(kk2+tig  )*72+wn+ni*8+g]; bl[1]=Bl[(kk2+tig+4)*72+wn+ni*8+g];
#pragma unroll
                for (int mi = 0; mi < 2; mi++) {
                    mma16bf(c[mi][ni], ah[mi], bh);
                    mma16bf(c[mi][ni], ah[mi], bl);
                    mma16bf(c[mi][ni], al[mi], bh);
                }
            }
        }
        __syncthreads();
        if (t < 7) storeT();
        __syncthreads();
    }

    float* Cout = g_PRE[i][b];
#pragma unroll
    for (int mi = 0; mi < 2; mi++) {
#pragma unroll
        for (int ni = 0; ni < 4; ni++) {
            int row = wm + mi * 16 + g;
            int col = n0 + wn + ni * 8 + tig * 2;
            float b0 = g_bpre[i][row], b1 = g_bpre[i][row + 8];
            *(float2*)&Cout[row * NPIX + col] =
                make_float2(c[mi][ni][0] + b0, c[mi][ni][1] + b0);
            *(float2*)&Cout[(row + 8) * NPIX + col] =
                make_float2(c[mi][ni][2] + b1, c[mi][ni][3] + b1);
        }
    }
}

__global__ void __launch_bounds__(256) k_pre23(const float* __restrict__ x1,
                                               const float* __restrict__ x2)
{
    __shared__ uint32_t pool[7424];
    int i = 2 + (blockIdx.z >> 2), b = blockIdx.z & 3;
    pre_body(pool, i, b, blockIdx.x * 64, x1, x2);
}

// ======================================================================
// etime body  (FIX: restored n0 offset in output column)
// ======================================================================
__device__ __forceinline__ void etime_body(uint32_t* pool, int b, int ks, int n0)
{
    uint32_t* Ah = pool;
    uint32_t* Al = pool + 2560;
    uint32_t* Bh = pool + 5120;
    uint32_t* Bl = pool + 6400;
    int kbeg = ks * (NPIX / ETSPLIT);
    const float* __restrict__ Tm = g_PRE[2][b];
    const float* __restrict__ Pm = g_PRE[3][b];

    int tid = threadIdx.x;
    int wid = tid >> 5, lane = tid & 31;
    int g = lane >> 2, tig = lane & 3;
    int wm = (wid & 3) * 32, wn = (wid >> 2) * 32;

    int am = tid >> 1, ak = (tid & 1) * 16;
    int bn = tid >> 2, bk = (tid & 3) * 8;

    float4 sA[4], sB[2];
    float c[2][4][4] = {};

    auto loadT = [&](int k0) {
#pragma unroll
        for (int q = 0; q < 4; q++) sA[q] = *(const float4*)&Tm[am * NPIX + k0 + ak + q * 4];
#pragma unroll
        for (int q = 0; q < 2; q++) sB[q] = *(const float4*)&Pm[(n0 + bn) * NPIX + k0 + bk + q * 4];
    };
    auto storeT = [&]() {
#pragma unroll
        for (int q = 0; q < 4; q++) {
            uint32_t h0,l0,h1,l1;
            split_pack(sA[q].x, sA[q].y, h0, l0);
            split_pack(sA[q].z, sA[q].w, h1, l1);
            int k2 = (ak >> 1) + q * 2;
            Ah[am * 20 + k2] = h0; Ah[am * 20 + k2 + 1] = h1;
            Al[am * 20 + k2] = l0; Al[am * 20 + k2 + 1] = l1;
        }
#pragma unroll
        for (int q = 0; q < 2; q++) {
            uint32_t h0,l0,h1,l1;
            split_pack(sB[q].x, sB[q].y, h0, l0);
            split_pack(sB[q].z, sB[q].w, h1, l1);
            int k2 = (bk >> 1) + q * 2;
            Bh[bn * 20 + k2] = h0; Bh[bn * 20 + k2 + 1] = h1;
            Bl[bn * 20 + k2] = l0; Bl[bn * 20 + k2 + 1] = l1;
        }
    };

    loadT(kbeg); storeT(); __syncthreads();
    for (int t = 0; t < 4; t++) {
        if (t < 3) loadT(kbeg + (t + 1) * 32);
#pragma unroll
        for (int kk2 = 0; kk2 < 16; kk2 += 8) {
            uint32_t ah[2][4], al[2][4];
#pragma unroll
            for (int mi = 0; mi < 2; mi++) {
                int mr = wm + mi * 16;
                ah[mi][0]=Ah[(mr+g  )*20+kk2+tig  ]; ah[mi][1]=Ah[(mr+g+8)*20+kk2+tig  ];
                ah[mi][2]=Ah[(mr+g  )*20+kk2+tig+4]; ah[mi][3]=Ah[(mr+g+8)*20+kk2+tig+4];
                al[mi][0]=Al[(mr+g  )*20+kk2+tig  ]; al[mi][1]=Al[(mr+g+8)*20+kk2+tig  ];
                al[mi][2]=Al[(mr+g  )*20+kk2+tig+4]; al[mi][3]=Al[(mr+g+8)*20+kk2+tig+4];
            }
#pragma unroll
            for (int ni = 0; ni < 4; ni++) {
                int nr = wn + ni * 8 + g;
                uint32_t bh[2], bl[2];
                bh[0]=Bh[nr*20+kk2+tig]; bh[1]=Bh[nr*20+kk2+tig+4];
                bl[0]=Bl[nr*20+kk2+tig]; bl[1]=Bl[nr*20+kk2+tig+4];
#pragma unroll
                for (int mi = 0; mi < 2; mi++) {
                    mma16bf(c[mi][ni], ah[mi], bh);
                    mma16bf(c[mi][ni], ah[mi], bl);
                    mma16bf(c[mi][ni], al[mi], bh);
                }
            }
        }
        __syncthreads();
        if (t < 3) storeT();
        __syncthreads();
    }

    float* outp = g_ETpart[b][ks];
#pragma unroll
    for (int mi = 0; mi < 2; mi++) {
#pragma unroll
        for (int ni = 0; ni < 4; ni++) {
            int row = wm + mi * 16 + g;
            int col = n0 + wn + ni * 8 + tig * 2;
            *(float2*)&outp[row * CI + col]       = make_float2(c[mi][ni][0], c[mi][ni][1]);
            *(float2*)&outp[(row + 8) * CI + col] = make_float2(c[mi][ni][2], c[mi][ni][3]);
        }
    }
}

// ======================================================================
// espace body + fused stats epilogue
// ======================================================================
__device__ __forceinline__ void espace_body(uint32_t* pool, int b, int row0, int col0)
{
    uint32_t* Ah = pool;
    uint32_t* Al = pool + 2176;
    uint32_t* Bh = pool + 4352;
    uint32_t* Bl = pool + 5504;
    const float* __restrict__ T = g_PRE[2][b];
    const float* __restrict__ P = g_PRE[3][b];

    int tid = threadIdx.x;
    int wid = tid >> 5, lane = tid & 31;
    int g = lane >> 2, tig = lane & 3;
    int wm = (wid & 3) * 32, wn = (wid >> 2) * 32;

    int ak2 = tid >> 5, an4 = (tid & 31) * 4;
    int bk2 = tid >> 4, bm4 = (tid & 15) * 4;

    float4 sAe[2], sAo[2], sBe, sBo;
    float c[2][4][4] = {};

    auto loadT = [&](int k0) {
#pragma unroll
        for (int it = 0; it < 2; it++) {
            const float* te = &T[(k0 + 2 * (ak2 + it * 8)) * NPIX + row0 + an4];
            sAe[it] = *(const float4*)te;
            sAo[it] = *(const float4*)(te + NPIX);
        }
        const float* pe = &P[(k0 + 2 * bk2) * NPIX + col0 + bm4];
        sBe = *(const float4*)pe;
        sBo = *(const float4*)(pe + NPIX);
    };
    auto storeT = [&]() {
#pragma unroll
        for (int it = 0; it < 2; it++) {
            uint32_t h0,l0,h1,l1,h2,l2,h3,l3;
            split_pack(sAe[it].x, sAo[it].x, h0, l0); split_pack(sAe[it].y, sAo[it].y, h1, l1);
            split_pack(sAe[it].z, sAo[it].z, h2, l2); split_pack(sAe[it].w, sAo[it].w, h3, l3);
            int r = ak2 + it * 8;
            *(uint4*)&Ah[r * 136 + an4] = make_uint4(h0, h1, h2, h3);
            *(uint4*)&Al[r * 136 + an4] = make_uint4(l0, l1, l2, l3);
        }
        uint32_t h0,l0,h1,l1,h2,l2,h3,l3;
        split_pack(sBe.x, sBo.x, h0, l0); split_pack(sBe.y, sBo.y, h1, l1);
        split_pack(sBe.z, sBo.z, h2, l2); split_pack(sBe.w, sBo.w, h3, l3);
        *(uint4*)&Bh[bk2 * 72 + bm4] = make_uint4(h0, h1, h2, h3);
        *(uint4*)&Bl[bk2 * 72 + bm4] = make_uint4(l0, l1, l2, l3);
    };

    loadT(0); storeT(); __syncthreads();
    for (int t = 0; t < 4; t++) {
        if (t < 3) loadT((t + 1) * 32);
#pragma unroll
        for (int kk2 = 0; kk2 < 16; kk2 += 8) {
            uint32_t ah[2][4], al[2][4];
#pragma unroll
            for (int mi = 0; mi < 2; mi++) {
                int mr = wm + mi * 16;
                ah[mi][0] = Ah[(kk2+tig  )*136 + mr + g    ];
                ah[mi][1] = Ah[(kk2+tig  )*136 + mr + g + 8];
                ah[mi][2] = Ah[(kk2+tig+4)*136 + mr + g    ];
                ah[mi][3] = Ah[(kk2+tig+4)*136 + mr + g + 8];
                al[mi][0] = Al[(kk2+tig  )*136 + mr + g    ];
                al[mi][1] = Al[(kk2+tig  )*136 + mr + g + 8];
                al[mi][2] = Al[(kk2+tig+4)*136 + mr + g    ];
                al[mi][3] = Al[(kk2+tig+4)*136 + mr + g + 8];
            }
#pragma unroll
            for (int ni = 0; ni < 4; ni++) {
                uint32_t bh[2], bl[2];
                bh[0] = Bh[(kk2+tig  )*72 + wn + ni*8 + g];
                bh[1] = Bh[(kk2+tig+4)*72 + wn + ni*8 + g];
                bl[0] = Bl[(kk2+tig  )*72 + wn + ni*8 + g];
                bl[1] = Bl[(kk2+tig+4)*72 + wn + ni*8 + g];
#pragma unroll
                for (int mi = 0; mi < 2; mi++) {
                    mma16bf(c[mi][ni], ah[mi], bh);
                    mma16bf(c[mi][ni], ah[mi], bl);
                    mma16bf(c[mi][ni], al[mi], bh);
                }
            }
        }
        __syncthreads();
        if (t < 3) storeT();
        __syncthreads();
    }

    float* Ep = g_E[b];
#pragma unroll
    for (int mi = 0; mi < 2; mi++) {
#pragma unroll
        for (int ni = 0; ni < 4; ni++) {
            int row = row0 + wm + mi * 16 + g;
            int col = col0 + wn + ni * 8 + tig * 2;
            *(float2*)&Ep[row * NPIX + col]       = make_float2(c[mi][ni][0], c[mi][ni][1]);
            *(float2*)&Ep[(row + 8) * NPIX + col] = make_float2(c[mi][ni][2], c[mi][ni][3]);
        }
    }

    // ---------- fused stats epilogue ----------
    __syncthreads();   // pool free for reuse
    float* scol = (float*)pool;          // [4 mwarp][64 col][2]
    float* srow = (float*)pool + 512;    // [2 nwarp][128 row][2]
    int mw = wid & 3, nw = wid >> 2;

    // column stats (over this block's 128 rows)
#pragma unroll
    for (int ni = 0; ni < 4; ni++) {
#pragma unroll
        for (int off = 0; off < 2; off++) {
            float v0 = c[0][ni][off], v1 = c[0][ni][off + 2];
            float v2 = c[1][ni][off], v3 = c[1][ni][off + 2];
            float mx = fmaxf(fmaxf(v0, v1), fmaxf(v2, v3));
            float s = __expf(v0 - mx) + __expf(v1 - mx) + __expf(v2 - mx) + __expf(v3 - mx);
#pragma unroll
            for (int sh = 4; sh <= 16; sh <<= 1) {
                float om = __shfl_xor_sync(0xffffffffu, mx, sh);
                float os = __shfl_xor_sync(0xffffffffu, s, sh);
                ms_merge(mx, s, om, os);
            }
            if (g == 0) {
                int lc = wn + ni * 8 + tig * 2 + off;
                scol[(mw * 64 + lc) * 2]     = mx;
                scol[(mw * 64 + lc) * 2 + 1] = s;
            }
        }
    }

    // row stats (over this block's 64 cols)
#pragma unroll
    for (int mi = 0; mi < 2; mi++) {
#pragma unroll
        for (int r8 = 0; r8 < 2; r8++) {
            float mx = -3.0e38f, s = 0.f;
#pragma unroll
            for (int ni = 0; ni < 4; ni++) {
                float v0 = c[mi][ni][r8 * 2], v1 = c[mi][ni][r8 * 2 + 1];
                float m2 = fmaxf(v0, v1);
                ms_merge(mx, s, m2, __expf(v0 - m2) + __expf(v1 - m2));
            }
#pragma unroll
            for (int sh = 1; sh <= 2; sh <<= 1) {
                float om = __shfl_xor_sync(0xffffffffu, mx, sh);
                float os = __shfl_xor_sync(0xffffffffu, s, sh);
                ms_merge(mx, s, om, os);
            }
            if (tig == 0) {
                int lr = wm + mi * 16 + g + r8 * 8;
                srow[(nw * 128 + lr) * 2]     = mx;
                srow[(nw * 128 + lr) * 2 + 1] = s;
            }
        }
    }
    __syncthreads();

    int y = row0 >> 7, x = col0 >> 6;
    if (tid < 64) {
        float mx = scol[tid * 2], s = scol[tid * 2 + 1];
#pragma unroll
        for (int m = 1; m < 4; m++)
            ms_merge(mx, s, scol[(m * 64 + tid) * 2], scol[(m * 64 + tid) * 2 + 1]);
        g_pmax[b][y][col0 + tid] = mx;
        g_psum[b][y][col0 + tid] = s;
    } else if (tid >= 128 && tid < 256) {
        int r = tid - 128;
        float mx = srow[r * 2], s = srow[r * 2 + 1];
        ms_merge(mx, s, srow[(128 + r) * 2], srow[(128 + r) * 2 + 1]);
        g_rpmax[b][x][row0 + r] = mx;
        g_rpsum[b][x][row0 + r] = s;
    }
}

// ======================================================================
// BIG3: pre01 (288) | etime (144) | espace (2592)
// ======================================================================
__global__ void __launch_bounds__(256) k_big3(const float* __restrict__ x1,
                                              const float* __restrict__ x2)
{
    __shared__ uint32_t pool[7680];
    int bx = blockIdx.x;
    if (bx < 288) {
        int x = bx % 36, iz = bx / 36;
        pre_body(pool, iz >> 2, iz & 3, x * 64, x1, x2);
    } else if (bx < 432) {
        int idx = bx - 288;
        int x = idx % 2, ks = (idx / 2) % 18, b = idx / 36;
        etime_body(pool, b, ks, x * 64);
    } else {
        int idx = bx - 432;
        int x = idx % 36, y = (idx / 36) % 18, b = idx / 648;
        espace_body(pool, b, y * 128, x * 64);
    }
}

// ======================================================================
// k_softA
// ======================================================================
__global__ void __launch_bounds__(256) k_softA()
{
    int b = blockIdx.y;
    int orient = blockIdx.x & 1;
    int strip = blockIdx.x >> 1;
    int tid = threadIdx.x, wid = tid >> 5, lane = tid & 31;
    __shared__ float ETs[128][9];

    if (orient == 0) {
        int t = strip * 8 + wid;
        float v[4];
#pragma unroll
        for (int j = 0; j < 4; j++) {
            int d = lane + j * 32;
            float s = 0.f;
#pragma unroll
            for (int p = 0; p < ETSPLIT; p++) s += g_ETpart[b][p][t * CI + d];
            v[j] = s;
        }
        float mx = fmaxf(fmaxf(v[0], v[1]), fmaxf(v[2], v[3]));
#pragma unroll
        for (int off = 16; off; off >>= 1) mx = fmaxf(mx, __shfl_xor_sync(0xffffffffu, mx, off));
        float e[4]; float sum = 0.f;
#pragma unroll
        for (int j = 0; j < 4; j++) { e[j] = __expf(v[j] - mx); sum += e[j]; }
#pragma unroll
        for (int off = 16; off; off >>= 1) sum += __shfl_xor_sync(0xffffffffu, sum, off);
        float rs = 1.f / sum;
#pragma unroll
        for (int j = 0; j < 4; j++) {
            float own = e[j] * rs;
            float part = __shfl_xor_sync(0xffffffffu, own, 1);
            if (!(lane & 1)) {
                float oh = bf_round(own), ph = bf_round(part);
                int k2 = (lane >> 1) + 16 * j;
                g_Apack[1][b][0][t * 64 + k2] = pack_bf(oh, ph);
                g_Apack[1][b][1][t * 64 + k2] = pack_bf(own - oh, part - ph);
            }
        }
    } else {
        int c0 = strip * 8;
        for (int idx = tid; idx < 128 * 8; idx += 256) {
            int d = idx >> 3, cc = idx & 7;
            float s = 0.f;
#pragma unroll
            for (int p = 0; p < ETSPLIT; p++) s += g_ETpart[b][p][d * CI + c0 + cc];
            ETs[d][cc] = s;
        }
        __syncthreads();
        int ccol = c0 + wid;
        float v[4];
#pragma unroll
        for (int j = 0; j < 4; j++) v[j] = ETs[lane + 32 * j][wid];
        float mx = fmaxf(fmaxf(v[0], v[1]), fmaxf(v[2], v[3]));
#pragma unroll
        for (int off = 16; off; off >>= 1) mx = fmaxf(mx, __shfl_xor_sync(0xffffffffu, mx, off));
        float e[4]; float sum = 0.f;
#pragma unroll
        for (int j = 0; j < 4; j++) { e[j] = __expf(v[j] - mx); sum += e[j]; }
#pragma unroll
        for (int off = 16; off; off >>= 1) sum += __shfl_xor_sync(0xffffffffu, sum, off);
        float rs = 1.f / sum;
#pragma unroll
        for (int j = 0; j < 4; j++) {
            float own = e[j] * rs;
            float part = __shfl_xor_sync(0xffffffffu, own, 1);
            if (!(lane & 1)) {
                float oh = bf_round(own), ph = bf_round(part);
                int k2 = (lane >> 1) + 16 * j;
                g_Apack[0][b][0][ccol * 64 + k2] = pack_bf(oh, ph);
                g_Apack[0][b][1][ccol * 64 + k2] = pack_bf(own - oh, part - ph);
            }
        }
    }
}

// ======================================================================
// zgemm body
// ======================================================================
__device__ __forceinline__ void zgemm_body(uint32_t* pool, int zi, int b, int n0)
{
    uint32_t* Ah = pool;
    uint32_t* Al = pool + 2560;
    uint32_t* Bh = pool + 5120;
    uint32_t* Bl = pool + 6272;
    const uint32_t* __restrict__ AhG = g_Apack[zi][b][0];
    const uint32_t* __restrict__ AlG = g_Apack[zi][b][1];
    const float* __restrict__ Bsrc = g_PRE[zi][b];

    int tid = threadIdx.x;
    int wid = tid >> 5, lane = tid & 31;
    int g = lane >> 2, tig = lane & 3;
    int wm = (wid & 3) * 32, wn = (wid >> 2) * 32;

    int am = tid >> 1, half8 = (tid & 1) * 8;
    int bk2 = tid >> 4, bn4 = (tid & 15) * 4;

    uint4 sAh0, sAh1, sAl0, sAl1;
    float4 sbe, sbo;
    float c[2][4][4] = {};

    auto loadT = [&](int k0) {
        int k2b = (k0 >> 1) + half8;
        sAh0 = *(const uint4*)&AhG[am * 64 + k2b];
        sAh1 = *(const uint4*)&AhG[am * 64 + k2b + 4];
        sAl0 = *(const uint4*)&AlG[am * 64 + k2b];
        sAl1 = *(const uint4*)&AlG[am * 64 + k2b + 4];
        const float* be = &Bsrc[(k0 + 2 * bk2) * NPIX + n0 + bn4];
        sbe = *(const float4*)be;
        sbo = *(const float4*)(be + NPIX);
    };
    auto storeT = [&]() {
        *(uint4*)&Ah[am * 20 + half8]     = sAh0;
        *(uint4*)&Ah[am * 20 + half8 + 4] = sAh1;
        *(uint4*)&Al[am * 20 + half8]     = sAl0;
        *(uint4*)&Al[am * 20 + half8 + 4] = sAl1;
        uint32_t h0,l0,h1,l1,h2,l2,h3,l3;
        split_pack(sbe.x, sbo.x, h0, l0); split_pack(sbe.y, sbo.y, h1, l1);
        split_pack(sbe.z, sbo.z, h2, l2); split_pack(sbe.w, sbo.w, h3, l3);
        *(uint4*)&Bh[bk2 * 72 + bn4] = make_uint4(h0, h1, h2, h3);
        *(uint4*)&Bl[bk2 * 72 + bn4] = make_uint4(l0, l1, l2, l3);
    };

    loadT(0); storeT(); __syncthreads();
    for (int t = 0; t < 4; t++) {
        if (t < 3) loadT((t + 1) * 32);
#pragma unroll
        for (int kk2 = 0; kk2 < 16; kk2 += 8) {
            uint32_t ah[2][4], al[2][4];
#pragma unroll
            for (int mi = 0; mi < 2; mi++) {
                int mr = wm + mi * 16;
                ah[mi][0]=Ah[(mr+g  )*20+kk2+tig  ]; ah[mi][1]=Ah[(mr+g+8)*20+kk2+tig  ];
                ah[mi][2]=Ah[(mr+g  )*20+kk2+tig+4]; ah[mi][3]=Ah[(mr+g+8)*20+kk2+tig+4];
                al[mi][0]=Al[(mr+g  )*20+kk2+tig  ]; al[mi][1]=Al[(mr+g+8)*20+kk2+tig  ];
                al[mi][2]=Al[(mr+g  )*20+kk2+tig+4]; al[mi][3]=Al[(mr+g+8)*20+kk2+tig+4];
            }
#pragma unroll
            for (int ni = 0; ni < 4; ni++) {
                uint32_t bh[2], bl[2];
                bh[0]=Bh[(kk2+tig  )*72+wn+ni*8+g]; bh[1]=Bh[(kk2+tig+4)*72+wn+ni*8+g];
                bl[0]=Bl[(kk2+tig  )*72+wn+ni*8+g]; bl[1]=Bl[(kk2+tig+4)*72+wn+ni*8+g];
#pragma unroll
                for (int mi = 0; mi < 2; mi++) {
                    mma16bf(c[mi][ni], ah[mi], bh);
                    mma16bf(c[mi][ni], ah[mi], bl);
                    mma16bf(c[mi][ni], al[mi], bh);
                }
            }
        }
        __syncthreads();
        if (t < 3) storeT();
        __syncthreads();
    }

    uint32_t* Zout = g_Zpack[zi][b];
#pragma unroll
    for (int mi = 0; mi < 2; mi++) {
#pragma unroll
        for (int ni = 0; ni < 4; ni++) {
            int row = wm + mi * 16 + g;
            int colh = ((n0 + wn + ni * 8) >> 1) + tig;
            Zout[row * NPK2 + colh]       = pack_bf(c[mi][ni][0], c[mi][ni][1]);
            Zout[(row + 8) * NPK2 + colh] = pack_bf(c[mi][ni][2], c[mi][ni][3]);
        }
    }
}

// ======================================================================
// ZPS: zgemm (288) | rowmerge (36)
// ======================================================================
__global__ void __launch_bounds__(256) k_zps()
{
    __shared__ uint32_t pool[7424];
    int bx = blockIdx.x;
    if (bx < 288) {
        int x = bx % 36, iz = bx / 36;
        zgemm_body(pool, iz >> 2, iz & 3, x * 64);
    } else {
        int t = (bx - 288) * 256 + threadIdx.x;   // 9216 = 4 * 2304
        int b = t / NPIX, row = t % NPIX;
        float mx = g_rpmax[b][0][row], s = g_rpsum[b][0][row];
#pragma unroll 5
        for (int x = 1; x < 36; x++)
            ms_merge(mx, s, g_rpmax[b][x][row], g_rpsum[b][x][row]);
        g_rowmax[b][row] = mx;
        g_rowrsum[b][row] = 1.f / s;
    }
}

// ======================================================================
// k_ygemm_fused
// ======================================================================
__global__ void __launch_bounds__(256) k_ygemm_fused(const float* __restrict__ x1,
                                                     const float* __restrict__ x2,
                                                     float* __restrict__ out)
{
    __shared__ uint32_t pool[12032];
    __shared__ float s_max[64], s_rs[64];

    float*    Ysf = (float*)(pool + 3840);
    uint32_t* Ysh = pool + 3840;
    uint32_t* Ysl = pool + 7936;
    uint32_t* WAh = pool;
    uint32_t* WAl = pool + 1280;

    int yi = blockIdx.z >> 2, b = blockIdx.z & 3;
    int n0 = blockIdx.x * 64;
    const uint32_t* __restrict__ Zp = g_Zpack[yi][b];
    const float* __restrict__ Ep = g_E[b];

    int tid = threadIdx.x;
    int wid = tid >> 5, lane = tid & 31;
    int g = lane >> 2, tig = lane & 3;
    int wm = (wid & 3) * 32, wn = (wid >> 2) * 32;

    if (tid < 64) {
        if (yi == 0) {
            int m = n0 + tid;
            float mx = g_pmax[b][0][m], s = g_psum[b][0][m];
#pragma unroll
            for (int ch = 1; ch < NCHUNK; ch++)
                ms_merge(mx, s, g_pmax[b][ch][m], g_psum[b][ch][m]);
            s_max[tid] = mx; s_rs[tid] = 1.f / s;
        } else {
            s_max[tid] = g_rowmax[b][n0 + tid];
            s_rs[tid]  = g_rowrsum[b][n0 + tid];
        }
    }
    __syncthreads();

    int am = tid >> 1, half8 = (tid & 1) * 8;
    int bk2g = tid >> 4, bn4 = (tid & 15) * 4;
    int bj = tid >> 2, bkq = (tid & 3) * 8;

    uint4 sZ0, sZ1;
    float4 sB0, sB1;
    float c[2][4][4] = {};

    auto loadT = [&](int k0) {
        int k2b = (k0 >> 1) + half8;
        sZ0 = *(const uint4*)&Zp[am * NPK2 + k2b];
        sZ1 = *(const uint4*)&Zp[am * NPK2 + k2b + 4];
        if (yi == 0) {
            const float* be = &Ep[(size_t)(k0 + 2 * bk2g) * NPIX + n0 + bn4];
            sB0 = *(const float4*)be;
            sB1 = *(const float4*)(be + NPIX);
        } else {
            const float* be = &Ep[(size_t)(n0 + bj) * NPIX + k0 + bkq];
            sB0 = *(const float4*)be;
            sB1 = *(const float4*)(be + 4);
        }
    };
    auto storeT = [&](int s) {
        uint32_t* A2m = pool + s * 3840;
        uint32_t* Bs  = A2m + 2560;
        *(uint4*)&A2m[am * 20 + half8]     = sZ0;
        *(uint4*)&A2m[am * 20 + half8 + 4] = sZ1;
        if (yi == 0) {
            float m0v = s_max[bn4], m1v = s_max[bn4+1], m2v = s_max[bn4+2], m3v = s_max[bn4+3];
            *(uint4*)&Bs[bk2g * 72 + bn4] = make_uint4(
                pack_bf(__expf(sB0.x - m0v), __expf(sB1.x - m0v)),
                pack_bf(__expf(sB0.y - m1v), __expf(sB1.y - m1v)),
                pack_bf(__expf(sB0.z - m2v), __expf(sB1.z - m2v)),
                pack_bf(__expf(sB0.w - m3v), __expf(sB1.w - m3v)));
        } else {
            float mx = s_max[bj];
            *(uint4*)&Bs[bj * 20 + (bkq >> 1)] = make_uint4(
                pack_bf(__expf(sB0.x - mx), __expf(sB0.y - mx)),
                pack_bf(__expf(sB0.z - mx), __expf(sB0.w - mx)),
                pack_bf(__expf(sB1.x - mx), __expf(sB1.y - mx)),
                pack_bf(__expf(sB1.z - mx), __expf(sB1.w - mx)));
        }
    };

    loadT(0); storeT(0); __syncthreads();
    for (int t = 0; t < 72; t++) {
        int cur = t & 1;
        uint32_t* A2m = pool + cur * 3840;
        uint32_t* Bs  = A2m + 2560;
        if (t < 71) loadT((t + 1) * 32);
#pragma unroll
        for (int kk2 = 0; kk2 < 16; kk2 += 8) {
            uint32_t a[2][4];
#pragma unroll
            for (int mi = 0; mi < 2; mi++) {
                int mr = wm + mi * 16;
                a[mi][0]=A2m[(mr+g  )*20+kk2+tig  ]; a[mi][1]=A2m[(mr+g+8)*20+kk2+tig  ];
                a[mi][2]=A2m[(mr+g  )*20+kk2+tig+4]; a[mi][3]=A2m[(mr+g+8)*20+kk2+tig+4];
            }
#pragma unroll
            for (int ni = 0; ni < 4; ni++) {
                uint32_t bb[2];
                if (yi == 0) {
                    bb[0] = Bs[(kk2+tig  ) * 72 + wn + ni*8 + g];
                    bb[1] = Bs[(kk2+tig+4) * 72 + wn + ni*8 + g];
                } else {
                    int nr = wn + ni * 8 + g;
                    bb[0] = Bs[nr * 20 + kk2 + tig    ];
                    bb[1] = Bs[nr * 20 + kk2 + tig + 4];
                }
                mma16bf(c[0][ni], a[0], bb);
                mma16bf(c[1][ni], a[1], bb);
            }
        }
        if (t < 71) storeT(1 - cur);
        __syncthreads();
    }

#pragma unroll
    for (int mi = 0; mi < 2; mi++) {
#pragma unroll
        for (int ni = 0; ni < 4; ni++) {
            int row = wm + mi * 16 + g;
            int col = wn + ni * 8 + tig * 2;
            Ysf[row * 64 + col]           = c[mi][ni][0] * s_rs[col];
            Ysf[row * 64 + col + 1]       = c[mi][ni][1] * s_rs[col + 1];
            Ysf[(row + 8) * 64 + col]     = c[mi][ni][2] * s_rs[col];
            Ysf[(row + 8) * 64 + col + 1] = c[mi][ni][3] * s_rs[col + 1];
        }
    }
    __syncthreads();

    {
        int n = tid & 63, kq = tid >> 6;
        float fe[16], fo[16];
#pragma unroll
        for (int e = 0; e < 16; e++) {
            int k2 = kq * 16 + e;
            fe[e] = Ysf[(2 * k2) * 64 + n];
            fo[e] = Ysf[(2 * k2 + 1) * 64 + n];
        }
        __syncthreads();
#pragma unroll
        for (int e = 0; e < 16; e++) {
            int k2 = kq * 16 + e;
            uint32_t hp, lp;
            split_pack(fe[e], fo[e], hp, lp);
            Ysh[k2 * 64 + n] = hp;
            Ysl[k2 * 64 + n] = lp;
        }
    }
    __syncthreads();

    const float* __restrict__ Wp = g_Wpost[yi];
    const float* xs = (yi ? x2 : x1) + b * CC * NPIX;
    float* op = out + (size_t)yi * BATCH * CC * NPIX + (size_t)b * CC * NPIX;
    int wm2 = tid >> 1, wsel = tid & 1;

    for (int hh = 0; hh < 2; hh++) {
        int m0 = hh * 128;
        float c2[2][4][4] = {};
        for (int kc = 0; kc < 8; kc++) {
            {
                const float* wr = &Wp[(m0 + wm2) * CI + kc * 16 + wsel * 8];
                float4 w0 = *(const float4*)wr;
                float4 w1 = *(const float4*)(wr + 4);
                uint32_t h0,l0,h1,l1,h2,l2,h3,l3;
                split_pack(w0.x, w0.y, h0, l0); split_pack(w0.z, w0.w, h1, l1);
                split_pack(w1.x, w1.y, h2, l2); split_pack(w1.z, w1.w, h3, l3);
                int base = wm2 * 10 + wsel * 4;
                WAh[base+0]=h0; WAh[base+1]=h1; WAh[base+2]=h2; WAh[base+3]=h3;
                WAl[base+0]=l0; WAl[base+1]=l1; WAl[base+2]=l2; WAl[base+3]=l3;
            }
            __syncthreads();
            uint32_t ah[2][4], al[2][4];
#pragma unroll
            for (int mi = 0; mi < 2; mi++) {
                int mr = wm + mi * 16;
                ah[mi][0]=WAh[(mr+g  )*10+tig  ]; ah[mi][1]=WAh[(mr+g+8)*10+tig  ];
                ah[mi][2]=WAh[(mr+g  )*10+tig+4]; ah[mi][3]=WAh[(mr+g+8)*10+tig+4];
                al[mi][0]=WAl[(mr+g  )*10+tig  ]; al[mi][1]=WAl[(mr+g+8)*10+tig  ];
                al[mi][2]=WAl[(mr+g  )*10+tig+4]; al[mi][3]=WAl[(mr+g+8)*10+tig+4];
            }
#pragma unroll
            for (int ni = 0; ni < 4; ni++) {
                uint32_t bh[2], bl[2];
                bh[0] = Ysh[(kc*8+tig  )*64 + wn + ni*8 + g];
                bh[1] = Ysh[(kc*8+tig+4)*64 + wn + ni*8 + g];
                bl[0] = Ysl[(kc*8+tig  )*64 + wn + ni*8 + g];
                bl[1] = Ysl[(kc*8+tig+4)*64 + wn + ni*8 + g];
#pragma unroll
                for (int mi = 0; mi < 2; mi++) {
                    mma16bf(c2[mi][ni], ah[mi], bh);
                    mma16bf(c2[mi][ni], ah[mi], bl);
                    mma16bf(c2[mi][ni], al[mi], bh);
                }
            }
            __syncthreads();
        }
#pragma unroll
        for (int mi = 0; mi < 2; mi++) {
#pragma unroll
            for (int ni = 0; ni < 4; ni++) {
                int row = m0 + wm + mi * 16 + g;
                int col = n0 + wn + ni * 8 + tig * 2;
                float b0 = g_bpost[yi][row], b1 = g_bpost[yi][row + 8];
                float2 r0 = *(const float2*)&xs[row * NPIX + col];
                float2 r1 = *(const float2*)&xs[(row + 8) * NPIX + col];
                *(float2*)&op[row * NPIX + col] =
                    make_float2(c2[mi][ni][0] + b0 + r0.x, c2[mi][ni][1] + b0 + r0.y);
                *(float2*)&op[(row + 8) * NPIX + col] =
                    make_float2(c2[mi][ni][2] + b1 + r1.x, c2[mi][ni][3] + b1 + r1.y);
            }
        }
    }
}

// ---------------- launcher ----------------
extern "C" void kernel_launch(void* const* d_in, const int* in_sizes, int n_in,
                              void* d_out, int out_size)
{
    const float* x1      = (const float*)d_in[0];
    const float* x2      = (const float*)d_in[1];
    const float* bn_pre  = (const float*)d_in[2];
    const float* w_pre   = (const float*)d_in[3];
    const float* b_pre   = (const float*)d_in[4];
    const float* w_post  = (const float*)d_in[5];
    const float* b_post  = (const float*)d_in[6];
    const float* bn_post = (const float*)d_in[7];
    float* out = (float*)d_out;

    k_fold<<<128, 256>>>(bn_pre, w_pre, b_pre, w_post, b_post, bn_post);
    k_pre23<<<dim3(36, 1, 8), 256>>>(x1, x2);
    k_big3<<<3024, 256>>>(x1, x2);
    k_softA<<<dim3(32, BATCH), 256>>>();
    k_zps<<<324, 256>>>();
    k_ygemm_fused<<<dim3(36, 1, 8), 256>>>(x1, x2, out);
}

// round 15
// speedup vs baseline: 1.5382x; 1.0150x over previous
#include <cuda_runtime.h>
#include <cuda_bf16.h>
#include <math.h>
#include <stdint.h>

#define BATCH 4
#define CC 256
#define CI 128
#define NPIX 2304
#define NPK2 1152
#define BNEPS 1e-5f
#define NCHUNK 18
#define ETSPLIT 18

// ---------------- scratch ----------------
__device__ float g_PRE[4][BATCH][CI*NPIX];
__device__ float g_ETpart[BATCH][ETSPLIT][CI*CI];
__device__ uint32_t g_Apack[2][BATCH][2][CI*64];
__device__ float g_E[BATCH][NPIX*NPIX];
__device__ uint32_t g_Zpack[2][BATCH][CI*NPK2];
__device__ float g_pmax[BATCH][NCHUNK][NPIX];
__device__ float g_psum[BATCH][NCHUNK][NPIX];
__device__ float g_rpmax[BATCH][36][NPIX];
__device__ float g_rpsum[BATCH][36][NPIX];
__device__ float g_WpreH[4][CI*CC];
__device__ float g_WpreL[4][CI*CC];
__device__ float g_bpre[4][CI];
__device__ float g_Wpost[2][CC*CI];
__device__ float g_bpost[2][CC];

// ---------------- helpers ----------------
__device__ __forceinline__ uint32_t pack_bf(float e, float o) {
    uint32_t r;
    asm("cvt.rn.bf16x2.f32 %0, %1, %2;" : "=r"(r) : "f"(o), "f"(e));
    return r;
}
__device__ __forceinline__ float bf_round(float x) {
    return __bfloat162float(__float2bfloat16(x));
}
__device__ __forceinline__ void mma16bf(float c[4], const uint32_t a[4], const uint32_t b[2]) {
    asm volatile(
        "mma.sync.aligned.m16n8k16.row.col.f32.bf16.bf16.f32 "
        "{%0,%1,%2,%3}, {%4,%5,%6,%7}, {%8,%9}, {%0,%1,%2,%3};"
        : "+f"(c[0]), "+f"(c[1]), "+f"(c[2]), "+f"(c[3])
        : "r"(a[0]), "r"(a[1]), "r"(a[2]), "r"(a[3]), "r"(b[0]), "r"(b[1]));
}
__device__ __forceinline__ void split_pack(float e, float o, uint32_t& hp, uint32_t& lp) {
    float eh = bf_round(e), oh = bf_round(o);
    hp = pack_bf(eh, oh);
    lp = pack_bf(e - eh, o - oh);
}
__device__ __forceinline__ void ms_merge(float& mx, float& s, float om, float os) {
    float nm = fmaxf(mx, om);
    s = s * __expf(mx - nm) + os * __expf(om - nm);
    mx = nm;
}

// ======================================================================
// k_fold
// ======================================================================
__global__ void __launch_bounds__(256) k_fold(
    const float* __restrict__ bn_pre, const float* __restrict__ w_pre,
    const float* __restrict__ b_pre, const float* __restrict__ w_post,
    const float* __restrict__ b_post, const float* __restrict__ bn_post)
{
    int w = blockIdx.x * 8 + (threadIdx.x >> 5);
    int lane = threadIdx.x & 31;
    if (w < 512) {
        int i = w >> 7, o = w & 127;
        const float* bp = bn_pre + i * 4 * CC;
        const float* wr = w_pre + (i * CI + o) * CC;
        float acc = 0.f;
        for (int c = lane; c < CC; c += 32) {
            float s = bp[c] * rsqrtf(bp[3 * CC + c] + BNEPS);
            float t = bp[CC + c] - bp[2 * CC + c] * s;
            float wv = wr[c] * s;
            float h = bf_round(wv);
            g_WpreH[i][o * CC + c] = h;
            g_WpreL[i][o * CC + c] = wv - h;
            acc = fmaf(wr[c], t, acc);
        }
#pragma unroll
        for (int off = 16; off; off >>= 1) acc += __shfl_xor_sync(0xffffffffu, acc, off);
        if (lane == 0) g_bpre[i][o] = acc + b_pre[i * CI + o];
    } else {
        int w2 = w - 512;
        int i = w2 >> 8, o = w2 & 255;
        const float* bp = bn_post + i * 4 * CC;
        float s = bp[o] * rsqrtf(bp[3 * CC + o] + BNEPS);
        const float* wr = w_post + (i * CC + o) * CI;
        for (int c = lane; c < CI; c += 32)
            g_Wpost[i][o * CI + c] = wr[c] * s;
        if (lane == 0)
            g_bpost[i][o] = b_post[i * CC + o] * s + bp[CC + o] - bp[2 * CC + o] * s;
    }
}

// ======================================================================
// pre body
// ======================================================================
__device__ __forceinline__ void pre_body(uint32_t* pool, int i, int b, int n0,
                                         const float* __restrict__ x1,
                                         const float* __restrict__ x2)
{
    uint32_t* Ah = pool;
    uint32_t* Al = pool + 2560;
    uint32_t* Bh = pool + 5120;
    uint32_t* Bl = pool + 6272;
    const float* __restrict__ AHf = g_WpreH[i];
    const float* __restrict__ ALf = g_WpreL[i];
    const float* __restrict__ Bsrc = ((i & 1) ? x2 : x1) + b * CC * NPIX;

    int tid = threadIdx.x;
    int wid = tid >> 5, lane = tid & 31;
    int g = lane >> 2, tig = lane & 3;
    int wm = (wid & 3) * 32, wn = (wid >> 2) * 32;

    int am = tid >> 2, akq = (tid & 3) * 8;
    int bk2 = tid >> 4, bn4 = (tid & 15) * 4;

    float4 sh0[2], sh1[2], sl0[2], sl1[2], sbe, sbo;
    float c[2][4][4] = {};

    auto loadT = [&](int k0) {
#pragma unroll
        for (int it = 0; it < 2; it++) {
            int m = am + it * 64;
            sh0[it] = *(const float4*)&AHf[m * CC + k0 + akq];
            sh1[it] = *(const float4*)&AHf[m * CC + k0 + akq + 4];
            sl0[it] = *(const float4*)&ALf[m * CC + k0 + akq];
            sl1[it] = *(const float4*)&ALf[m * CC + k0 + akq + 4];
        }
        const float* be = &Bsrc[(k0 + 2 * bk2) * NPIX + n0 + bn4];
        sbe = *(const float4*)be;
        sbo = *(const float4*)(be + NPIX);
    };
    auto storeT = [&]() {
#pragma unroll
        for (int it = 0; it < 2; it++) {
            int m = am + it * 64, kq2 = akq >> 1;
            *(uint4*)&Ah[m * 20 + kq2] = make_uint4(
                pack_bf(sh0[it].x, sh0[it].y), pack_bf(sh0[it].z, sh0[it].w),
                pack_bf(sh1[it].x, sh1[it].y), pack_bf(sh1[it].z, sh1[it].w));
            *(uint4*)&Al[m * 20 + kq2] = make_uint4(
                pack_bf(sl0[it].x, sl0[it].y), pack_bf(sl0[it].z, sl0[it].w),
                pack_bf(sl1[it].x, sl1[it].y), pack_bf(sl1[it].z, sl1[it].w));
        }
        uint32_t h0,l0,h1,l1,h2,l2,h3,l3;
        split_pack(sbe.x, sbo.x, h0, l0); split_pack(sbe.y, sbo.y, h1, l1);
        split_pack(sbe.z, sbo.z, h2, l2); split_pack(sbe.w, sbo.w, h3, l3);
        *(uint4*)&Bh[bk2 * 72 + bn4] = make_uint4(h0, h1, h2, h3);
        *(uint4*)&Bl[bk2 * 72 + bn4] = make_uint4(l0, l1, l2, l3);
    };

    loadT(0); storeT(); __syncthreads();
    for (int t = 0; t < 8; t++) {
        if (t < 7) loadT((t + 1) * 32);
#pragma unroll
        for (int kk2 = 0; kk2 < 16; kk2 += 8) {
            uint32_t ah[2][4], al[2][4];
#pragma unroll
            for (int mi = 0; mi < 2; mi++) {
                int mr = wm + mi * 16;
                ah[mi][0]=Ah[(mr+g  )*20+kk2+tig  ]; ah[mi][1]=Ah[(mr+g+8)*20+kk2+tig  ];
                ah[mi][2]=Ah[(mr+g  )*20+kk2+tig+4]; ah[mi][3]=Ah[(mr+g+8)*20+kk2+tig+4];
                al[mi][0]=Al[(mr+g  )*20+kk2+tig  ]; al[mi][1]=Al[(mr+g+8)*20+kk2+tig  ];
                al[mi][2]=Al[(mr+g  )*20+kk2+tig+4]; al[mi][3]=Al[(mr+g+8)*20+kk2+tig+4];
            }
#pragma unroll
            for (int ni = 0; ni < 4; ni++) {
                uint32_t bh[2], bl[2];
                bh[0]=Bh[(kk2+tig  )*72+wn+ni*8+g]; bh[1]=Bh[(kk2+tig+4)*72+wn+ni*8+g];
                bl[0]=Bl[(kk2+tig  )*72+wn+ni*8+g]; bl[1]=Bl[(kk2+tig+4)*72+wn+ni*8+g];
#pragma unroll
                for (int mi = 0; mi < 2; mi++) {
                    mma16bf(c[mi][ni], ah[mi], bh);
                    mma16bf(c[mi][ni], ah[mi], bl);
                    mma16bf(c[mi][ni], al[mi], bh);
                }
            }
        }
        __syncthreads();
        if (t < 7) storeT();
        __syncthreads();
    }

    float* Cout = g_PRE[i][b];
#pragma unroll
    for (int mi = 0; mi < 2; mi++) {
#pragma unroll
        for (int ni = 0; ni < 4; ni++) {
            int row = wm + mi * 16 + g;
            int col = n0 + wn + ni * 8 + tig * 2;
            float b0 = g_bpre[i][row], b1 = g_bpre[i][row + 8];
            *(float2*)&Cout[row * NPIX + col] =
                make_float2(c[mi][ni][0] + b0, c[mi][ni][1] + b0);
            *(float2*)&Cout[(row + 8) * NPIX + col] =
                make_float2(c[mi][ni][2] + b1, c[mi][ni][3] + b1);
        }
    }
}

__global__ void __launch_bounds__(256) k_pre23(const float* __restrict__ x1,
                                               const float* __restrict__ x2)
{
    __shared__ uint32_t pool[7424];
    int i = 2 + (blockIdx.z >> 2), b = blockIdx.z & 3;
    pre_body(pool, i, b, blockIdx.x * 64, x1, x2);
}

// ======================================================================
// etime body
// ======================================================================
__device__ __forceinline__ void etime_body(uint32_t* pool, int b, int ks, int n0)
{
    uint32_t* Ah = pool;
    uint32_t* Al = pool + 2560;
    uint32_t* Bh = pool + 5120;
    uint32_t* Bl = pool + 6400;
    int kbeg = ks * (NPIX / ETSPLIT);
    const float* __restrict__ Tm = g_PRE[2][b];
    const float* __restrict__ Pm = g_PRE[3][b];

    int tid = threadIdx.x;
    int wid = tid >> 5, lane = tid & 31;
    int g = lane >> 2, tig = lane & 3;
    int wm = (wid & 3) * 32, wn = (wid >> 2) * 32;

    int am = tid >> 1, ak = (tid & 1) * 16;
    int bn = tid >> 2, bk = (tid & 3) * 8;

    float4 sA[4], sB[2];
    float c[2][4][4] = {};

    auto loadT = [&](int k0) {
#pragma unroll
        for (int q = 0; q < 4; q++) sA[q] = *(const float4*)&Tm[am * NPIX + k0 + ak + q * 4];
#pragma unroll
        for (int q = 0; q < 2; q++) sB[q] = *(const float4*)&Pm[(n0 + bn) * NPIX + k0 + bk + q * 4];
    };
    auto storeT = [&]() {
#pragma unroll
        for (int q = 0; q < 4; q++) {
            uint32_t h0,l0,h1,l1;
            split_pack(sA[q].x, sA[q].y, h0, l0);
            split_pack(sA[q].z, sA[q].w, h1, l1);
            int k2 = (ak >> 1) + q * 2;
            Ah[am * 20 + k2] = h0; Ah[am * 20 + k2 + 1] = h1;
            Al[am * 20 + k2] = l0; Al[am * 20 + k2 + 1] = l1;
        }
#pragma unroll
        for (int q = 0; q < 2; q++) {
            uint32_t h0,l0,h1,l1;
            split_pack(sB[q].x, sB[q].y, h0, l0);
            split_pack(sB[q].z, sB[q].w, h1, l1);
            int k2 = (bk >> 1) + q * 2;
            Bh[bn * 20 + k2] = h0; Bh[bn * 20 + k2 + 1] = h1;
            Bl[bn * 20 + k2] = l0; Bl[bn * 20 + k2 + 1] = l1;
        }
    };

    loadT(kbeg); storeT(); __syncthreads();
    for (int t = 0; t < 4; t++) {
        if (t < 3) loadT(kbeg + (t + 1) * 32);
#pragma unroll
        for (int kk2 = 0; kk2 < 16; kk2 += 8) {
            uint32_t ah[2][4], al[2][4];
#pragma unroll
            for (int mi = 0; mi < 2; mi++) {
                int mr = wm + mi * 16;
                ah[mi][0]=Ah[(mr+g  )*20+kk2+tig  ]; ah[mi][1]=Ah[(mr+g+8)*20+kk2+tig  ];
                ah[mi][2]=Ah[(mr+g  )*20+kk2+tig+4]; ah[mi][3]=Ah[(mr+g+8)*20+kk2+tig+4];
                al[mi][0]=Al[(mr+g  )*20+kk2+tig  ]; al[mi][1]=Al[(mr+g+8)*20+kk2+tig  ];
                al[mi][2]=Al[(mr+g  )*20+kk2+tig+4]; al[mi][3]=Al[(mr+g+8)*20+kk2+tig+4];
            }
#pragma unroll
            for (int ni = 0; ni < 4; ni++) {
                int nr = wn + ni * 8 + g;
                uint32_t bh[2], bl[2];
                bh[0]=Bh[nr*20+kk2+tig]; bh[1]=Bh[nr*20+kk2+tig+4];
                bl[0]=Bl[nr*20+kk2+tig]; bl[1]=Bl[nr*20+kk2+tig+4];
#pragma unroll
                for (int mi = 0; mi < 2; mi++) {
                    mma16bf(c[mi][ni], ah[mi], bh);
                    mma16bf(c[mi][ni], ah[mi], bl);
                    mma16bf(c[mi][ni], al[mi], bh);
                }
            }
        }
        __syncthreads();
        if (t < 3) storeT();
        __syncthreads();
    }

    float* outp = g_ETpart[b][ks];
#pragma unroll
    for (int mi = 0; mi < 2; mi++) {
#pragma unroll
        for (int ni = 0; ni < 4; ni++) {
            int row = wm + mi * 16 + g;
            int col = n0 + wn + ni * 8 + tig * 2;
            *(float2*)&outp[row * CI + col]       = make_float2(c[mi][ni][0], c[mi][ni][1]);
            *(float2*)&outp[(row + 8) * CI + col] = make_float2(c[mi][ni][2], c[mi][ni][3]);
        }
    }
}

// ======================================================================
// k_ep: etime (144) | pre01 (288) = 432 blocks
// ======================================================================
__global__ void __launch_bounds__(256) k_ep(const float* __restrict__ x1,
                                            const float* __restrict__ x2)
{
    __shared__ uint32_t pool[7680];
    int bx = blockIdx.x;
    if (bx < 144) {
        int x = bx % 2, ks = (bx / 2) % 18, b = bx / 36;
        etime_body(pool, b, ks, x * 64);
    } else {
        int idx = bx - 144;
        int x = idx % 36, iz = idx / 36;
        pre_body(pool, iz >> 2, iz & 3, x * 64, x1, x2);
    }
}

// ======================================================================
// espace body + fused stats epilogue
// ======================================================================
__device__ __forceinline__ void espace_body(uint32_t* pool, int b, int row0, int col0)
{
    uint32_t* Ah = pool;
    uint32_t* Al = pool + 2176;
    uint32_t* Bh = pool + 4352;
    uint32_t* Bl = pool + 5504;
    const float* __restrict__ T = g_PRE[2][b];
    const float* __restrict__ P = g_PRE[3][b];

    int tid = threadIdx.x;
    int wid = tid >> 5, lane = tid & 31;
    int g = lane >> 2, tig = lane & 3;
    int wm = (wid & 3) * 32, wn = (wid >> 2) * 32;

    int ak2 = tid >> 5, an4 = (tid & 31) * 4;
    int bk2 = tid >> 4, bm4 = (tid & 15) * 4;

    float4 sAe[2], sAo[2], sBe, sBo;
    float c[2][4][4] = {};

    auto loadT = [&](int k0) {
#pragma unroll
        for (int it = 0; it < 2; it++) {
            const float* te = &T[(k0 + 2 * (ak2 + it * 8)) * NPIX + row0 + an4];
            sAe[it] = *(const float4*)te;
            sAo[it] = *(const float4*)(te + NPIX);
        }
        const float* pe = &P[(k0 + 2 * bk2) * NPIX + col0 + bm4];
        sBe = *(const float4*)pe;
        sBo = *(const float4*)(pe + NPIX);
    };
    auto storeT = [&]() {
#pragma unroll
        for (int it = 0; it < 2; it++) {
            uint32_t h0,l0,h1,l1,h2,l2,h3,l3;
            split_pack(sAe[it].x, sAo[it].x, h0, l0); split_pack(sAe[it].y, sAo[it].y, h1, l1);
            split_pack(sAe[it].z, sAo[it].z, h2, l2); split_pack(sAe[it].w, sAo[it].w, h3, l3);
            int r = ak2 + it * 8;
            *(uint4*)&Ah[r * 136 + an4] = make_uint4(h0, h1, h2, h3);
            *(uint4*)&Al[r * 136 + an4] = make_uint4(l0, l1, l2, l3);
        }
        uint32_t h0,l0,h1,l1,h2,l2,h3,l3;
        split_pack(sBe.x, sBo.x, h0, l0); split_pack(sBe.y, sBo.y, h1, l1);
        split_pack(sBe.z, sBo.z, h2, l2); split_pack(sBe.w, sBo.w, h3, l3);
        *(uint4*)&Bh[bk2 * 72 + bm4] = make_uint4(h0, h1, h2, h3);
        *(uint4*)&Bl[bk2 * 72 + bm4] = make_uint4(l0, l1, l2, l3);
    };

    loadT(0); storeT(); __syncthreads();
    for (int t = 0; t < 4; t++) {
        if (t < 3) loadT((t + 1) * 32);
#pragma unroll
        for (int kk2 = 0; kk2 < 16; kk2 += 8) {
            uint32_t ah[2][4], al[2][4];
#pragma unroll
            for (int mi = 0; mi < 2; mi++) {
                int mr = wm + mi * 16;
                ah[mi][0] = Ah[(kk2+tig  )*136 + mr + g    ];
                ah[mi][1] = Ah[(kk2+tig  )*136 + mr + g + 8];
                ah[mi][2] = Ah[(kk2+tig+4)*136 + mr + g    ];
                ah[mi][3] = Ah[(kk2+tig+4)*136 + mr + g + 8];
                al[mi][0] = Al[(kk2+tig  )*136 + mr + g    ];
                al[mi][1] = Al[(kk2+tig  )*136 + mr + g + 8];
                al[mi][2] = Al[(kk2+tig+4)*136 + mr + g    ];
                al[mi][3] = Al[(kk2+tig+4)*136 + mr + g + 8];
            }
#pragma unroll
            for (int ni = 0; ni < 4; ni++) {
                uint32_t bh[2], bl[2];
                bh[0] = Bh[(kk2+tig  )*72 + wn + ni*8 + g];
                bh[1] = Bh[(kk2+tig+4)*72 + wn + ni*8 + g];
                bl[0] = Bl[(kk2+tig  )*72 + wn + ni*8 + g];
                bl[1] = Bl[(kk2+tig+4)*72 + wn + ni*8 + g];
#pragma unroll
                for (int mi = 0; mi < 2; mi++) {
                    mma16bf(c[mi][ni], ah[mi], bh);
                    mma16bf(c[mi][ni], ah[mi], bl);
                    mma16bf(c[mi][ni], al[mi], bh);
                }
            }
        }
        __syncthreads();
        if (t < 3) storeT();
        __syncthreads();
    }

    float* Ep = g_E[b];
#pragma unroll
    for (int mi = 0; mi < 2; mi++) {
#pragma unroll
        for (int ni = 0; ni < 4; ni++) {
            int row = row0 + wm + mi * 16 + g;
            int col = col0 + wn + ni * 8 + tig * 2;
            *(float2*)&Ep[row * NPIX + col]       = make_float2(c[mi][ni][0], c[mi][ni][1]);
            *(float2*)&Ep[(row + 8) * NPIX + col] = make_float2(c[mi][ni][2], c[mi][ni][3]);
        }
    }

    // ---------- fused stats epilogue ----------
    __syncthreads();
    float* scol = (float*)pool;          // [4 mwarp][64 col][2]
    float* srow = (float*)pool + 512;    // [2 nwarp][128 row][2]
    int mw = wid & 3, nw = wid >> 2;

#pragma unroll
    for (int ni = 0; ni < 4; ni++) {
#pragma unroll
        for (int off = 0; off < 2; off++) {
            float v0 = c[0][ni][off], v1 = c[0][ni][off + 2];
            float v2 = c[1][ni][off], v3 = c[1][ni][off + 2];
            float mx = fmaxf(fmaxf(v0, v1), fmaxf(v2, v3));
            float s = __expf(v0 - mx) + __expf(v1 - mx) + __expf(v2 - mx) + __expf(v3 - mx);
#pragma unroll
            for (int sh = 4; sh <= 16; sh <<= 1) {
                float om = __shfl_xor_sync(0xffffffffu, mx, sh);
                float os = __shfl_xor_sync(0xffffffffu, s, sh);
                ms_merge(mx, s, om, os);
            }
            if (g == 0) {
                int lc = wn + ni * 8 + tig * 2 + off;
                scol[(mw * 64 + lc) * 2]     = mx;
                scol[(mw * 64 + lc) * 2 + 1] = s;
            }
        }
    }

#pragma unroll
    for (int mi = 0; mi < 2; mi++) {
#pragma unroll
        for (int r8 = 0; r8 < 2; r8++) {
            float mx = -3.0e38f, s = 0.f;
#pragma unroll
            for (int ni = 0; ni < 4; ni++) {
                float v0 = c[mi][ni][r8 * 2], v1 = c[mi][ni][r8 * 2 + 1];
                float m2 = fmaxf(v0, v1);
                ms_merge(mx, s, m2, __expf(v0 - m2) + __expf(v1 - m2));
            }
#pragma unroll
            for (int sh = 1; sh <= 2; sh <<= 1) {
                float om = __shfl_xor_sync(0xffffffffu, mx, sh);
                float os = __shfl_xor_sync(0xffffffffu, s, sh);
                ms_merge(mx, s, om, os);
            }
            if (tig == 0) {
                int lr = wm + mi * 16 + g + r8 * 8;
                srow[(nw * 128 + lr) * 2]     = mx;
                srow[(nw * 128 + lr) * 2 + 1] = s;
            }
        }
    }
    __syncthreads();

    int y = row0 >> 7, x = col0 >> 6;
    if (tid < 64) {
        float mx = scol[tid * 2], s = scol[tid * 2 + 1];
#pragma unroll
        for (int m = 1; m < 4; m++)
            ms_merge(mx, s, scol[(m * 64 + tid) * 2], scol[(m * 64 + tid) * 2 + 1]);
        g_pmax[b][y][col0 + tid] = mx;
        g_psum[b][y][col0 + tid] = s;
    } else if (tid >= 128 && tid < 256) {
        int r = tid - 128;
        float mx = srow[r * 2], s = srow[r * 2 + 1];
        ms_merge(mx, s, srow[(128 + r) * 2], srow[(128 + r) * 2 + 1]);
        g_rpmax[b][x][row0 + r] = mx;
        g_rpsum[b][x][row0 + r] = s;
    }
}

// ======================================================================
// k_softA
// ======================================================================
__global__ void __launch_bounds__(256) k_softA()
{
    int b = blockIdx.y;
    int orient = blockIdx.x & 1;
    int strip = blockIdx.x >> 1;
    int tid = threadIdx.x, wid = tid >> 5, lane = tid & 31;
    __shared__ float ETs[128][9];

    if (orient == 0) {
        int t = strip * 8 + wid;
        float v[4];
#pragma unroll
        for (int j = 0; j < 4; j++) {
            int d = lane + j * 32;
            float s = 0.f;
#pragma unroll
            for (int p = 0; p < ETSPLIT; p++) s += g_ETpart[b][p][t * CI + d];
            v[j] = s;
        }
        float mx = fmaxf(fmaxf(v[0], v[1]), fmaxf(v[2], v[3]));
#pragma unroll
        for (int off = 16; off; off >>= 1) mx = fmaxf(mx, __shfl_xor_sync(0xffffffffu, mx, off));
        float e[4]; float sum = 0.f;
#pragma unroll
        for (int j = 0; j < 4; j++) { e[j] = __expf(v[j] - mx); sum += e[j]; }
#pragma unroll
        for (int off = 16; off; off >>= 1) sum += __shfl_xor_sync(0xffffffffu, sum, off);
        float rs = 1.f / sum;
#pragma unroll
        for (int j = 0; j < 4; j++) {
            float own = e[j] * rs;
            float part = __shfl_xor_sync(0xffffffffu, own, 1);
            if (!(lane & 1)) {
                float oh = bf_round(own), ph = bf_round(part);
                int k2 = (lane >> 1) + 16 * j;
                g_Apack[1][b][0][t * 64 + k2] = pack_bf(oh, ph);
                g_Apack[1][b][1][t * 64 + k2] = pack_bf(own - oh, part - ph);
            }
        }
    } else {
        int c0 = strip * 8;
        for (int idx = tid; idx < 128 * 8; idx += 256) {
            int d = idx >> 3, cc = idx & 7;
            float s = 0.f;
#pragma unroll
            for (int p = 0; p < ETSPLIT; p++) s += g_ETpart[b][p][d * CI + c0 + cc];
            ETs[d][cc] = s;
        }
        __syncthreads();
        int ccol = c0 + wid;
        float v[4];
#pragma unroll
        for (int j = 0; j < 4; j++) v[j] = ETs[lane + 32 * j][wid];
        float mx = fmaxf(fmaxf(v[0], v[1]), fmaxf(v[2], v[3]));
#pragma unroll
        for (int off = 16; off; off >>= 1) mx = fmaxf(mx, __shfl_xor_sync(0xffffffffu, mx, off));
        float e[4]; float sum = 0.f;
#pragma unroll
        for (int j = 0; j < 4; j++) { e[j] = __expf(v[j] - mx); sum += e[j]; }
#pragma unroll
        for (int off = 16; off; off >>= 1) sum += __shfl_xor_sync(0xffffffffu, sum, off);
        float rs = 1.f / sum;
#pragma unroll
        for (int j = 0; j < 4; j++) {
            float own = e[j] * rs;
            float part = __shfl_xor_sync(0xffffffffu, own, 1);
            if (!(lane & 1)) {
                float oh = bf_round(own), ph = bf_round(part);
                int k2 = (lane >> 1) + 16 * j;
                g_Apack[0][b][0][ccol * 64 + k2] = pack_bf(oh, ph);
                g_Apack[0][b][1][ccol * 64 + k2] = pack_bf(own - oh, part - ph);
            }
        }
    }
}

// ======================================================================
// zgemm body
// ======================================================================
__device__ __forceinline__ void zgemm_body(uint32_t* pool, int zi, int b, int n0)
{
    uint32_t* Ah = pool;
    uint32_t* Al = pool + 2560;
    uint32_t* Bh = pool + 5120;
    uint32_t* Bl = pool + 6272;
    const uint32_t* __restrict__ AhG = g_Apack[zi][b][0];
    const uint32_t* __restrict__ AlG = g_Apack[zi][b][1];
    const float* __restrict__ Bsrc = g_PRE[zi][b];

    int tid = threadIdx.x;
    int wid = tid >> 5, lane = tid & 31;
    int g = lane >> 2, tig = lane & 3;
    int wm = (wid & 3) * 32, wn = (wid >> 2) * 32;

    int am = tid >> 1, half8 = (tid & 1) * 8;
    int bk2 = tid >> 4, bn4 = (tid & 15) * 4;

    uint4 sAh0, sAh1, sAl0, sAl1;
    float4 sbe, sbo;
    float c[2][4][4] = {};

    auto loadT = [&](int k0) {
        int k2b = (k0 >> 1) + half8;
        sAh0 = *(const uint4*)&AhG[am * 64 + k2b];
        sAh1 = *(const uint4*)&AhG[am * 64 + k2b + 4];
        sAl0 = *(const uint4*)&AlG[am * 64 + k2b];
        sAl1 = *(const uint4*)&AlG[am * 64 + k2b + 4];
        const float* be = &Bsrc[(k0 + 2 * bk2) * NPIX + n0 + bn4];
        sbe = *(const float4*)be;
        sbo = *(const float4*)(be + NPIX);
    };
    auto storeT = [&]() {
        *(uint4*)&Ah[am * 20 + half8]     = sAh0;
        *(uint4*)&Ah[am * 20 + half8 + 4] = sAh1;
        *(uint4*)&Al[am * 20 + half8]     = sAl0;
        *(uint4*)&Al[am * 20 + half8 + 4] = sAl1;
        uint32_t h0,l0,h1,l1,h2,l2,h3,l3;
        split_pack(sbe.x, sbo.x, h0, l0); split_pack(sbe.y, sbo.y, h1, l1);
        split_pack(sbe.z, sbo.z, h2, l2); split_pack(sbe.w, sbo.w, h3, l3);
        *(uint4*)&Bh[bk2 * 72 + bn4] = make_uint4(h0, h1, h2, h3);
        *(uint4*)&Bl[bk2 * 72 + bn4] = make_uint4(l0, l1, l2, l3);
    };

    loadT(0); storeT(); __syncthreads();
    for (int t = 0; t < 4; t++) {
        if (t < 3) loadT((t + 1) * 32);
#pragma unroll
        for (int kk2 = 0; kk2 < 16; kk2 += 8) {
            uint32_t ah[2][4], al[2][4];
#pragma unroll
            for (int mi = 0; mi < 2; mi++) {
                int mr = wm + mi * 16;
                ah[mi][0]=Ah[(mr+g  )*20+kk2+tig  ]; ah[mi][1]=Ah[(mr+g+8)*20+kk2+tig  ];
                ah[mi][2]=Ah[(mr+g  )*20+kk2+tig+4]; ah[mi][3]=Ah[(mr+g+8)*20+kk2+tig+4];
                al[mi][0]=Al[(mr+g  )*20+kk2+tig  ]; al[mi][1]=Al[(mr+g+8)*20+kk2+tig  ];
                al[mi][2]=Al[(mr+g  )*20+kk2+tig+4]; al[mi][3]=Al[(mr+g+8)*20+kk2+tig+4];
            }
#pragma unroll
            for (int ni = 0; ni < 4; ni++) {
                uint32_t bh[2], bl[2];
                bh[0]=Bh[(kk2+tig  )*72+wn+ni*8+g]; bh[1]=Bh[(kk2+tig+4)*72+wn+ni*8+g];
                bl[0]=Bl[(kk2+tig  )*72+wn+ni*8+g]; bl[1]=Bl[(kk2+tig+4)*72+wn+ni*8+g];
#pragma unroll
                for (int mi = 0; mi < 2; mi++) {
                    mma16bf(c[mi][ni], ah[mi], bh);
                    mma16bf(c[mi][ni], ah[mi], bl);
                    mma16bf(c[mi][ni], al[mi], bh);
                }
            }
        }
        __syncthreads();
        if (t < 3) storeT();
        __syncthreads();
    }

    uint32_t* Zout = g_Zpack[zi][b];
#pragma unroll
    for (int mi = 0; mi < 2; mi++) {
#pragma unroll
        for (int ni = 0; ni < 4; ni++) {
            int row = wm + mi * 16 + g;
            int colh = ((n0 + wn + ni * 8) >> 1) + tig;
            Zout[row * NPK2 + colh]       = pack_bf(c[mi][ni][0], c[mi][ni][1]);
            Zout[(row + 8) * NPK2 + colh] = pack_bf(c[mi][ni][2], c[mi][ni][3]);
        }
    }
}

// ======================================================================
// k_ez: espace (2592) | zgemm (288) = 2880 blocks
// ======================================================================
__global__ void __launch_bounds__(256) k_ez()
{
    __shared__ uint32_t pool[7424];
    int bx = blockIdx.x;
    if (bx < 2592) {
        int x = bx % 36, y = (bx / 36) % 18, b = bx / 648;
        espace_body(pool, b, y * 128, x * 64);
    } else {
        int idx = bx - 2592;
        int x = idx % 36, iz = idx / 36;
        zgemm_body(pool, iz >> 2, iz & 3, x * 64);
    }
}

// ======================================================================
// k_ygemm_fused (rowmerge inlined for yi==1)
// ======================================================================
__global__ void __launch_bounds__(256) k_ygemm_fused(const float* __restrict__ x1,
                                                     const float* __restrict__ x2,
                                                     float* __restrict__ out)
{
    __shared__ uint32_t pool[12032];
    __shared__ float s_max[64], s_rs[64];

    float*    Ysf = (float*)(pool + 3840);
    uint32_t* Ysh = pool + 3840;
    uint32_t* Ysl = pool + 7936;
    uint32_t* WAh = pool;
    uint32_t* WAl = pool + 1280;

    int yi = blockIdx.z >> 2, b = blockIdx.z & 3;
    int n0 = blockIdx.x * 64;
    const uint32_t* __restrict__ Zp = g_Zpack[yi][b];
    const float* __restrict__ Ep = g_E[b];

    int tid = threadIdx.x;
    int wid = tid >> 5, lane = tid & 31;
    int g = lane >> 2, tig = lane & 3;
    int wm = (wid & 3) * 32, wn = (wid >> 2) * 32;

    if (tid < 64) {
        int m = n0 + tid;
        if (yi == 0) {
            float mx = g_pmax[b][0][m], s = g_psum[b][0][m];
#pragma unroll
            for (int ch = 1; ch < NCHUNK; ch++)
                ms_merge(mx, s, g_pmax[b][ch][m], g_psum[b][ch][m]);
            s_max[tid] = mx; s_rs[tid] = 1.f / s;
        } else {
            float mx = g_rpmax[b][0][m], s = g_rpsum[b][0][m];
#pragma unroll 5
            for (int x = 1; x < 36; x++)
                ms_merge(mx, s, g_rpmax[b][x][m], g_rpsum[b][x][m]);
            s_max[tid] = mx; s_rs[tid] = 1.f / s;
        }
    }
    __syncthreads();

    int am = tid >> 1, half8 = (tid & 1) * 8;
    int bk2g = tid >> 4, bn4 = (tid & 15) * 4;
    int bj = tid >> 2, bkq = (tid & 3) * 8;

    uint4 sZ0, sZ1;
    float4 sB0, sB1;
    float c[2][4][4] = {};

    auto loadT = [&](int k0) {
        int k2b = (k0 >> 1) + half8;
        sZ0 = *(const uint4*)&Zp[am * NPK2 + k2b];
        sZ1 = *(const uint4*)&Zp[am * NPK2 + k2b + 4];
        if (yi == 0) {
            const float* be = &Ep[(size_t)(k0 + 2 * bk2g) * NPIX + n0 + bn4];
            sB0 = *(const float4*)be;
            sB1 = *(const float4*)(be + NPIX);
        } else {
            const float* be = &Ep[(size_t)(n0 + bj) * NPIX + k0 + bkq];
            sB0 = *(const float4*)be;
            sB1 = *(const float4*)(be + 4);
        }
    };
    auto storeT = [&](int s) {
        uint32_t* A2m = pool + s * 3840;
        uint32_t* Bs  = A2m + 2560;
        *(uint4*)&A2m[am * 20 + half8]     = sZ0;
        *(uint4*)&A2m[am * 20 + half8 + 4] = sZ1;
        if (yi == 0) {
            float m0v = s_max[bn4], m1v = s_max[bn4+1], m2v = s_max[bn4+2], m3v = s_max[bn4+3];
            *(uint4*)&Bs[bk2g * 72 + bn4] = make_uint4(
                pack_bf(__expf(sB0.x - m0v), __expf(sB1.x - m0v)),
                pack_bf(__expf(sB0.y - m1v), __expf(sB1.y - m1v)),
                pack_bf(__expf(sB0.z - m2v), __expf(sB1.z - m2v)),
                pack_bf(__expf(sB0.w - m3v), __expf(sB1.w - m3v)));
        } else {
            float mx = s_max[bj];
            *(uint4*)&Bs[bj * 20 + (bkq >> 1)] = make_uint4(
                pack_bf(__expf(sB0.x - mx), __expf(sB0.y - mx)),
                pack_bf(__expf(sB0.z - mx), __expf(sB0.w - mx)),
                pack_bf(__expf(sB1.x - mx), __expf(sB1.y - mx)),
                pack_bf(__expf(sB1.z - mx), __expf(sB1.w - mx)));
        }
    };

    loadT(0); storeT(0); __syncthreads();
    for (int t = 0; t < 72; t++) {
        int cur = t & 1;
        uint32_t* A2m = pool + cur * 3840;
        uint32_t* Bs  = A2m + 2560;
        if (t < 71) loadT((t + 1) * 32);
#pragma unroll
        for (int kk2 = 0; kk2 < 16; kk2 += 8) {
            uint32_t a[2][4];
#pragma unroll
            for (int mi = 0; mi < 2; mi++) {
                int mr = wm + mi * 16;
                a[mi][0]=A2m[(mr+g  )*20+kk2+tig  ]; a[mi][1]=A2m[(mr+g+8)*20+kk2+tig  ];
                a[mi][2]=A2m[(mr+g  )*20+kk2+tig+4]; a[mi][3]=A2m[(mr+g+8)*20+kk2+tig+4];
            }
#pragma unroll
            for (int ni = 0; ni < 4; ni++) {
                uint32_t bb[2];
                if (yi == 0) {
                    bb[0] = Bs[(kk2+tig  ) * 72 + wn + ni*8 + g];
                    bb[1] = Bs[(kk2+tig+4) * 72 + wn + ni*8 + g];
                } else {
                    int nr = wn + ni * 8 + g;
                    bb[0] = Bs[nr * 20 + kk2 + tig    ];
                    bb[1] = Bs[nr * 20 + kk2 + tig + 4];
                }
                mma16bf(c[0][ni], a[0], bb);
                mma16bf(c[1][ni], a[1], bb);
            }
        }
        if (t < 71) storeT(1 - cur);
        __syncthreads();
    }

#pragma unroll
    for (int mi = 0; mi < 2; mi++) {
#pragma unroll
        for (int ni = 0; ni < 4; ni++) {
            int row = wm + mi * 16 + g;
            int col = wn + ni * 8 + tig * 2;
            Ysf[row * 64 + col]           = c[mi][ni][0] * s_rs[col];
            Ysf[row * 64 + col + 1]       = c[mi][ni][1] * s_rs[col + 1];
            Ysf[(row + 8) * 64 + col]     = c[mi][ni][2] * s_rs[col];
            Ysf[(row + 8) * 64 + col + 1] = c[mi][ni][3] * s_rs[col + 1];
        }
    }
    __syncthreads();

    {
        int n = tid & 63, kq = tid >> 6;
        float fe[16], fo[16];
#pragma unroll
        for (int e = 0; e < 16; e++) {
            int k2 = kq * 16 + e;
            fe[e] = Ysf[(2 * k2) * 64 + n];
            fo[e] = Ysf[(2 * k2 + 1) * 64 + n];
        }
        __syncthreads();
#pragma unroll
        for (int e = 0; e < 16; e++) {
            int k2 = kq * 16 + e;
            uint32_t hp, lp;
            split_pack(fe[e], fo[e], hp, lp);
            Ysh[k2 * 64 + n] = hp;
            Ysl[k2 * 64 + n] = lp;
        }
    }
    __syncthreads();

    const float* __restrict__ Wp = g_Wpost[yi];
    const float* xs = (yi ? x2 : x1) + b * CC * NPIX;
    float* op = out + (size_t)yi * BATCH * CC * NPIX + (size_t)b * CC * NPIX;
    int wm2 = tid >> 1, wsel = tid & 1;

    for (int hh = 0; hh < 2; hh++) {
        int m0 = hh * 128;
        float c2[2][4][4] = {};
        for (int kc = 0; kc < 8; kc++) {
            {
                const float* wr = &Wp[(m0 + wm2) * CI + kc * 16 + wsel * 8];
                float4 w0 = *(const float4*)wr;
                float4 w1 = *(const float4*)(wr + 4);
                uint32_t h0,l0,h1,l1,h2,l2,h3,l3;
                split_pack(w0.x, w0.y, h0, l0); split_pack(w0.z, w0.w, h1, l1);
                split_pack(w1.x, w1.y, h2, l2); split_pack(w1.z, w1.w, h3, l3);
                int base = wm2 * 10 + wsel * 4;
                WAh[base+0]=h0; WAh[base+1]=h1; WAh[base+2]=h2; WAh[base+3]=h3;
                WAl[base+0]=l0; WAl[base+1]=l1; WAl[base+2]=l2; WAl[base+3]=l3;
            }
            __syncthreads();
            uint32_t ah[2][4], al[2][4];
#pragma unroll
            for (int mi = 0; mi < 2; mi++) {
                int mr = wm + mi * 16;
                ah[mi][0]=WAh[(mr+g  )*10+tig  ]; ah[mi][1]=WAh[(mr+g+8)*10+tig  ];
                ah[mi][2]=WAh[(mr+g  )*10+tig+4]; ah[mi][3]=WAh[(mr+g+8)*10+tig+4];
                al[mi][0]=WAl[(mr+g  )*10+tig  ]; al[mi][1]=WAl[(mr+g+8)*10+tig  ];
                al[mi][2]=WAl[(mr+g  )*10+tig+4]; al[mi][3]=WAl[(mr+g+8)*10+tig+4];
            }
#pragma unroll
            for (int ni = 0; ni < 4; ni++) {
                uint32_t bh[2], bl[2];
                bh[0] = Ysh[(kc*8+tig  )*64 + wn + ni*8 + g];
                bh[1] = Ysh[(kc*8+tig+4)*64 + wn + ni*8 + g];
                bl[0] = Ysl[(kc*8+tig  )*64 + wn + ni*8 + g];
                bl[1] = Ysl[(kc*8+tig+4)*64 + wn + ni*8 + g];
#pragma unroll
                for (int mi = 0; mi < 2; mi++) {
                    mma16bf(c2[mi][ni], ah[mi], bh);
                    mma16bf(c2[mi][ni], ah[mi], bl);
                    mma16bf(c2[mi][ni], al[mi], bh);
                }
            }
            __syncthreads();
        }
#pragma unroll
        for (int mi = 0; mi < 2; mi++) {
#pragma unroll
            for (int ni = 0; ni < 4; ni++) {
                int row = m0 + wm + mi * 16 + g;
                int col = n0 + wn + ni * 8 + tig * 2;
                float b0 = g_bpost[yi][row], b1 = g_bpost[yi][row + 8];
                float2 r0 = *(const float2*)&xs[row * NPIX + col];
                float2 r1 = *(const float2*)&xs[(row + 8) * NPIX + col];
                *(float2*)&op[row * NPIX + col] =
                    make_float2(c2[mi][ni][0] + b0 + r0.x, c2[mi][ni][1] + b0 + r0.y);
                *(float2*)&op[(row + 8) * NPIX + col] =
                    make_float2(c2[mi][ni][2] + b1 + r1.x, c2[mi][ni][3] + b1 + r1.y);
            }
        }
    }
}

// ---------------- launcher ----------------
extern "C" void kernel_launch(void* const* d_in, const int* in_sizes, int n_in,
                              void* d_out, int out_size)
{
    const float* x1      = (const float*)d_in[0];
    const float* x2      = (const float*)d_in[1];
    const float* bn_pre  = (const float*)d_in[2];
    const float* w_pre   = (const float*)d_in[3];
    const float* b_pre   = (const float*)d_in[4];
    const float* w_post  = (const float*)d_in[5];
    const float* b_post  = (const float*)d_in[6];
    const float* bn_post = (const float*)d_in[7];
    float* out = (float*)d_out;

    k_fold<<<128, 256>>>(bn_pre, w_pre, b_pre, w_post, b_post, bn_post);
    k_pre23<<<dim3(36, 1, 8), 256>>>(x1, x2);
    k_ep<<<432, 256>>>(x1, x2);
    k_softA<<<dim3(32, BATCH), 256>>>();
    k_ez<<<2880, 256>>>();
    k_ygemm_fused<<<dim3(36, 1, 8), 256>>>(x1, x2, out);
}

// round 17
// speedup vs baseline: 1.5689x; 1.0199x over previous
#include <cuda_runtime.h>
#include <cuda_bf16.h>
#include <math.h>
#include <stdint.h>

#define BATCH 4
#define CC 256
#define CI 128
#define NPIX 2304
#define NPK2 1152
#define BNEPS 1e-5f
#define NCHUNK 18
#define ETSPLIT 18

// ---------------- scratch ----------------
__device__ float g_PRE[4][BATCH][CI*NPIX];
__device__ float g_ETpart[BATCH][ETSPLIT][CI*CI];
__device__ uint32_t g_Apack[2][BATCH][2][CI*64];
__device__ float g_E[BATCH][NPIX*NPIX];
__device__ uint32_t g_Zpack[2][BATCH][CI*NPK2];
__device__ float g_pmax[BATCH][NCHUNK][NPIX];
__device__ float g_psum[BATCH][NCHUNK][NPIX];
__device__ float g_rpmax[BATCH][36][NPIX];
__device__ float g_rpsum[BATCH][36][NPIX];
__device__ float g_WpreH[4][CI*CC];
__device__ float g_WpreL[4][CI*CC];
__device__ float g_bpre[4][CI];
__device__ float g_Wpost[2][CC*CI];
__device__ float g_bpost[2][CC];

// ---------------- helpers ----------------
__device__ __forceinline__ uint32_t pack_bf(float e, float o) {
    uint32_t r;
    asm("cvt.rn.bf16x2.f32 %0, %1, %2;" : "=r"(r) : "f"(o), "f"(e));
    return r;
}
__device__ __forceinline__ float bf_round(float x) {
    return __bfloat162float(__float2bfloat16(x));
}
__device__ __forceinline__ void mma16bf(float c[4], const uint32_t a[4], const uint32_t b[2]) {
    asm volatile(
        "mma.sync.aligned.m16n8k16.row.col.f32.bf16.bf16.f32 "
        "{%0,%1,%2,%3}, {%4,%5,%6,%7}, {%8,%9}, {%0,%1,%2,%3};"
        : "+f"(c[0]), "+f"(c[1]), "+f"(c[2]), "+f"(c[3])
        : "r"(a[0]), "r"(a[1]), "r"(a[2]), "r"(a[3]), "r"(b[0]), "r"(b[1]));
}
__device__ __forceinline__ void split_pack(float e, float o, uint32_t& hp, uint32_t& lp) {
    float eh = bf_round(e), oh = bf_round(o);
    hp = pack_bf(eh, oh);
    lp = pack_bf(e - eh, o - oh);
}
__device__ __forceinline__ void ms_merge(float& mx, float& s, float om, float os) {
    float nm = fmaxf(mx, om);
    s = s * __expf(mx - nm) + os * __expf(om - nm);
    mx = nm;
}

// ======================================================================
// k_fold
// ======================================================================
__global__ void __launch_bounds__(256) k_fold(
    const float* __restrict__ bn_pre, const float* __restrict__ w_pre,
    const float* __restrict__ b_pre, const float* __restrict__ w_post,
    const float* __restrict__ b_post, const float* __restrict__ bn_post)
{
    int w = blockIdx.x * 8 + (threadIdx.x >> 5);
    int lane = threadIdx.x & 31;
    if (w < 512) {
        int i = w >> 7, o = w & 127;
        const float* bp = bn_pre + i * 4 * CC;
        const float* wr = w_pre + (i * CI + o) * CC;
        float acc = 0.f;
        for (int c = lane; c < CC; c += 32) {
            float s = bp[c] * rsqrtf(bp[3 * CC + c] + BNEPS);
            float t = bp[CC + c] - bp[2 * CC + c] * s;
            float wv = wr[c] * s;
            float h = bf_round(wv);
            g_WpreH[i][o * CC + c] = h;
            g_WpreL[i][o * CC + c] = wv - h;
            acc = fmaf(wr[c], t, acc);
        }
#pragma unroll
        for (int off = 16; off; off >>= 1) acc += __shfl_xor_sync(0xffffffffu, acc, off);
        if (lane == 0) g_bpre[i][o] = acc + b_pre[i * CI + o];
    } else {
        int w2 = w - 512;
        int i = w2 >> 8, o = w2 & 255;
        const float* bp = bn_post + i * 4 * CC;
        float s = bp[o] * rsqrtf(bp[3 * CC + o] + BNEPS);
        const float* wr = w_post + (i * CC + o) * CI;
        for (int c = lane; c < CI; c += 32)
            g_Wpost[i][o * CI + c] = wr[c] * s;
        if (lane == 0)
            g_bpost[i][o] = b_post[i * CC + o] * s + bp[CC + o] - bp[2 * CC + o] * s;
    }
}

// ======================================================================
// pre body (3-term, all i)
// ======================================================================
__device__ __forceinline__ void pre_body(uint32_t* pool, int i, int b, int n0,
                                         const float* __restrict__ x1,
                                         const float* __restrict__ x2)
{
    uint32_t* Ah = pool;
    uint32_t* Al = pool + 2560;
    uint32_t* Bh = pool + 5120;
    uint32_t* Bl = pool + 6272;
    const float* __restrict__ AHf = g_WpreH[i];
    const float* __restrict__ ALf = g_WpreL[i];
    const float* __restrict__ Bsrc = ((i & 1) ? x2 : x1) + b * CC * NPIX;

    int tid = threadIdx.x;
    int wid = tid >> 5, lane = tid & 31;
    int g = lane >> 2, tig = lane & 3;
    int wm = (wid & 3) * 32, wn = (wid >> 2) * 32;

    int am = tid >> 2, akq = (tid & 3) * 8;
    int bk2 = tid >> 4, bn4 = (tid & 15) * 4;

    float4 sh0[2], sh1[2], sl0[2], sl1[2], sbe, sbo;
    float c[2][4][4] = {};

    auto loadT = [&](int k0) {
#pragma unroll
        for (int it = 0; it < 2; it++) {
            int m = am + it * 64;
            sh0[it] = *(const float4*)&AHf[m * CC + k0 + akq];
            sh1[it] = *(const float4*)&AHf[m * CC + k0 + akq + 4];
            sl0[it] = *(const float4*)&ALf[m * CC + k0 + akq];
            sl1[it] = *(const float4*)&ALf[m * CC + k0 + akq + 4];
        }
        const float* be = &Bsrc[(k0 + 2 * bk2) * NPIX + n0 + bn4];
        sbe = *(const float4*)be;
        sbo = *(const float4*)(be + NPIX);
    };
    auto storeT = [&]() {
#pragma unroll
        for (int it = 0; it < 2; it++) {
            int m = am + it * 64, kq2 = akq >> 1;
            *(uint4*)&Ah[m * 20 + kq2] = make_uint4(
                pack_bf(sh0[it].x, sh0[it].y), pack_bf(sh0[it].z, sh0[it].w),
                pack_bf(sh1[it].x, sh1[it].y), pack_bf(sh1[it].z, sh1[it].w));
            *(uint4*)&Al[m * 20 + kq2] = make_uint4(
                pack_bf(sl0[it].x, sl0[it].y), pack_bf(sl0[it].z, sl0[it].w),
                pack_bf(sl1[it].x, sl1[it].y), pack_bf(sl1[it].z, sl1[it].w));
        }
        uint32_t h0,l0,h1,l1,h2,l2,h3,l3;
        split_pack(sbe.x, sbo.x, h0, l0); split_pack(sbe.y, sbo.y, h1, l1);
        split_pack(sbe.z, sbo.z, h2, l2); split_pack(sbe.w, sbo.w, h3, l3);
        *(uint4*)&Bh[bk2 * 72 + bn4] = make_uint4(h0, h1, h2, h3);
        *(uint4*)&Bl[bk2 * 72 + bn4] = make_uint4(l0, l1, l2, l3);
    };

    loadT(0); storeT(); __syncthreads();
    for (int t = 0; t < 8; t++) {
        if (t < 7) loadT((t + 1) * 32);
#pragma unroll
        for (int kk2 = 0; kk2 < 16; kk2 += 8) {
            uint32_t ah[2][4], al[2][4];
#pragma unroll
            for (int mi = 0; mi < 2; mi++) {
                int mr = wm + mi * 16;
                ah[mi][0]=Ah[(mr+g  )*20+kk2+tig  ]; ah[mi][1]=Ah[(mr+g+8)*20+kk2+tig  ];
                ah[mi][2]=Ah[(mr+g  )*20+kk2+tig+4]; ah[mi][3]=Ah[(mr+g+8)*20+kk2+tig+4];
                al[mi][0]=Al[(mr+g  )*20+kk2+tig  ]; al[mi][1]=Al[(mr+g+8)*20+kk2+tig  ];
                al[mi][2]=Al[(mr+g  )*20+kk2+tig+4]; al[mi][3]=Al[(mr+g+8)*20+kk2+tig+4];
            }
#pragma unroll
            for (int ni = 0; ni < 4; ni++) {
                uint32_t bh[2], bl[2];
                bh[0]=Bh[(kk2+tig  )*72+wn+ni*8+g]; bh[1]=Bh[(kk2+tig+4)*72+wn+ni*8+g];
                bl[0]=Bl[(kk2+tig  )*72+wn+ni*8+g]; bl[1]=Bl[(kk2+tig+4)*72+wn+ni*8+g];
#pragma unroll
                for (int mi = 0; mi < 2; mi++) {
                    mma16bf(c[mi][ni], ah[mi], bh);
                    mma16bf(c[mi][ni], ah[mi], bl);
                    mma16bf(c[mi][ni], al[mi], bh);
                }
            }
        }
        __syncthreads();
        if (t < 7) storeT();
        __syncthreads();
    }

    float* Cout = g_PRE[i][b];
#pragma unroll
    for (int mi = 0; mi < 2; mi++) {
#pragma unroll
        for (int ni = 0; ni < 4; ni++) {
            int row = wm + mi * 16 + g;
            int col = n0 + wn + ni * 8 + tig * 2;
            float b0 = g_bpre[i][row], b1 = g_bpre[i][row + 8];
            *(float2*)&Cout[row * NPIX + col] =
                make_float2(c[mi][ni][0] + b0, c[mi][ni][1] + b0);
            *(float2*)&Cout[(row + 8) * NPIX + col] =
                make_float2(c[mi][ni][2] + b1, c[mi][ni][3] + b1);
        }
    }
}

__global__ void __launch_bounds__(256) k_pre23(const float* __restrict__ x1,
                                               const float* __restrict__ x2)
{
    __shared__ uint32_t pool[7424];
    int i = 2 + (blockIdx.z >> 2), b = blockIdx.z & 3;
    pre_body(pool, i, b, blockIdx.x * 64, x1, x2);
}

// ======================================================================
// etime body (3-term)
// ======================================================================
__device__ __forceinline__ void etime_body(uint32_t* pool, int b, int ks, int n0)
{
    uint32_t* Ah = pool;
    uint32_t* Al = pool + 2560;
    uint32_t* Bh = pool + 5120;
    uint32_t* Bl = pool + 6400;
    int kbeg = ks * (NPIX / ETSPLIT);
    const float* __restrict__ Tm = g_PRE[2][b];
    const float* __restrict__ Pm = g_PRE[3][b];

    int tid = threadIdx.x;
    int wid = tid >> 5, lane = tid & 31;
    int g = lane >> 2, tig = lane & 3;
    int wm = (wid & 3) * 32, wn = (wid >> 2) * 32;

    int am = tid >> 1, ak = (tid & 1) * 16;
    int bn = tid >> 2, bk = (tid & 3) * 8;

    float4 sA[4], sB[2];
    float c[2][4][4] = {};

    auto loadT = [&](int k0) {
#pragma unroll
        for (int q = 0; q < 4; q++) sA[q] = *(const float4*)&Tm[am * NPIX + k0 + ak + q * 4];
#pragma unroll
        for (int q = 0; q < 2; q++) sB[q] = *(const float4*)&Pm[(n0 + bn) * NPIX + k0 + bk + q * 4];
    };
    auto storeT = [&]() {
#pragma unroll
        for (int q = 0; q < 4; q++) {
            uint32_t h0,l0,h1,l1;
            split_pack(sA[q].x, sA[q].y, h0, l0);
            split_pack(sA[q].z, sA[q].w, h1, l1);
            int k2 = (ak >> 1) + q * 2;
            Ah[am * 20 + k2] = h0; Ah[am * 20 + k2 + 1] = h1;
            Al[am * 20 + k2] = l0; Al[am * 20 + k2 + 1] = l1;
        }
#pragma unroll
        for (int q = 0; q < 2; q++) {
            uint32_t h0,l0,h1,l1;
            split_pack(sB[q].x, sB[q].y, h0, l0);
            split_pack(sB[q].z, sB[q].w, h1, l1);
            int k2 = (bk >> 1) + q * 2;
            Bh[bn * 20 + k2] = h0; Bh[bn * 20 + k2 + 1] = h1;
            Bl[bn * 20 + k2] = l0; Bl[bn * 20 + k2 + 1] = l1;
        }
    };

    loadT(kbeg); storeT(); __syncthreads();
    for (int t = 0; t < 4; t++) {
        if (t < 3) loadT(kbeg + (t + 1) * 32);
#pragma unroll
        for (int kk2 = 0; kk2 < 16; kk2 += 8) {
            uint32_t ah[2][4], al[2][4];
#pragma unroll
            for (int mi = 0; mi < 2; mi++) {
                int mr = wm + mi * 16;
                ah[mi][0]=Ah[(mr+g  )*20+kk2+tig  ]; ah[mi][1]=Ah[(mr+g+8)*20+kk2+tig  ];
                ah[mi][2]=Ah[(mr+g  )*20+kk2+tig+4]; ah[mi][3]=Ah[(mr+g+8)*20+kk2+tig+4];
                al[mi][0]=Al[(mr+g  )*20+kk2+tig  ]; al[mi][1]=Al[(mr+g+8)*20+kk2+tig  ];
                al[mi][2]=Al[(mr+g  )*20+kk2+tig+4]; al[mi][3]=Al[(mr+g+8)*20+kk2+tig+4];
            }
#pragma unroll
            for (int ni = 0; ni < 4; ni++) {
                int nr = wn + ni * 8 + g;
                uint32_t bh[2], bl[2];
                bh[0]=Bh[nr*20+kk2+tig]; bh[1]=Bh[nr*20+kk2+tig+4];
                bl[0]=Bl[nr*20+kk2+tig]; bl[1]=Bl[nr*20+kk2+tig+4];
#pragma unroll
                for (int mi = 0; mi < 2; mi++) {
                    mma16bf(c[mi][ni], ah[mi], bh);
                    mma16bf(c[mi][ni], ah[mi], bl);
                    mma16bf(c[mi][ni], al[mi], bh);
                }
            }
        }
        __syncthreads();
        if (t < 3) storeT();
        __syncthreads();
    }

    float* outp = g_ETpart[b][ks];
#pragma unroll
    for (int mi = 0; mi < 2; mi++) {
#pragma unroll
        for (int ni = 0; ni < 4; ni++) {
            int row = wm + mi * 16 + g;
            int col = n0 + wn + ni * 8 + tig * 2;
            *(float2*)&outp[row * CI + col]       = make_float2(c[mi][ni][0], c[mi][ni][1]);
            *(float2*)&outp[(row + 8) * CI + col] = make_float2(c[mi][ni][2], c[mi][ni][3]);
        }
    }
}

// ======================================================================
// k_ep: etime (144) | pre01 3-term (288) = 432 blocks
// ======================================================================
__global__ void __launch_bounds__(256) k_ep(const float* __restrict__ x1,
                                            const float* __restrict__ x2)
{
    __shared__ uint32_t pool[7680];
    int bx = blockIdx.x;
    if (bx < 144) {
        int x = bx % 2, ks = (bx / 2) % 18, b = bx / 36;
        etime_body(pool, b, ks, x * 64);
    } else {
        int idx = bx - 144;
        int x = idx % 36, iz = idx / 36;
        pre_body(pool, iz >> 2, iz & 3, x * 64, x1, x2);
    }
}

// ======================================================================
// espace body + fused stats epilogue (3-term)
// ======================================================================
__device__ __forceinline__ void espace_body(uint32_t* pool, int b, int row0, int col0)
{
    uint32_t* Ah = pool;
    uint32_t* Al = pool + 2176;
    uint32_t* Bh = pool + 4352;
    uint32_t* Bl = pool + 5504;
    const float* __restrict__ T = g_PRE[2][b];
    const float* __restrict__ P = g_PRE[3][b];

    int tid = threadIdx.x;
    int wid = tid >> 5, lane = tid & 31;
    int g = lane >> 2, tig = lane & 3;
    int wm = (wid & 3) * 32, wn = (wid >> 2) * 32;

    int ak2 = tid >> 5, an4 = (tid & 31) * 4;
    int bk2 = tid >> 4, bm4 = (tid & 15) * 4;

    float4 sAe[2], sAo[2], sBe, sBo;
    float c[2][4][4] = {};

    auto loadT = [&](int k0) {
#pragma unroll
        for (int it = 0; it < 2; it++) {
            const float* te = &T[(k0 + 2 * (ak2 + it * 8)) * NPIX + row0 + an4];
            sAe[it] = *(const float4*)te;
            sAo[it] = *(const float4*)(te + NPIX);
        }
        const float* pe = &P[(k0 + 2 * bk2) * NPIX + col0 + bm4];
        sBe = *(const float4*)pe;
        sBo = *(const float4*)(pe + NPIX);
    };
    auto storeT = [&]() {
#pragma unroll
        for (int it = 0; it < 2; it++) {
            uint32_t h0,l0,h1,l1,h2,l2,h3,l3;
            split_pack(sAe[it].x, sAo[it].x, h0, l0); split_pack(sAe[it].y, sAo[it].y, h1, l1);
            split_pack(sAe[it].z, sAo[it].z, h2, l2); split_pack(sAe[it].w, sAo[it].w, h3, l3);
            int r = ak2 + it * 8;
            *(uint4*)&Ah[r * 136 + an4] = make_uint4(h0, h1, h2, h3);
            *(uint4*)&Al[r * 136 + an4] = make_uint4(l0, l1, l2, l3);
        }
        uint32_t h0,l0,h1,l1,h2,l2,h3,l3;
        split_pack(sBe.x, sBo.x, h0, l0); split_pack(sBe.y, sBo.y, h1, l1);
        split_pack(sBe.z, sBo.z, h2, l2); split_pack(sBe.w, sBo.w, h3, l3);
        *(uint4*)&Bh[bk2 * 72 + bm4] = make_uint4(h0, h1, h2, h3);
        *(uint4*)&Bl[bk2 * 72 + bm4] = make_uint4(l0, l1, l2, l3);
    };

    loadT(0); storeT(); __syncthreads();
    for (int t = 0; t < 4; t++) {
        if (t < 3) loadT((t + 1) * 32);
#pragma unroll
        for (int kk2 = 0; kk2 < 16; kk2 += 8) {
            uint32_t ah[2][4], al[2][4];
#pragma unroll
            for (int mi = 0; mi < 2; mi++) {
                int mr = wm + mi * 16;
                ah[mi][0] = Ah[(kk2+tig  )*136 + mr + g    ];
                ah[mi][1] = Ah[(kk2+tig  )*136 + mr + g + 8];
                ah[mi][2] = Ah[(kk2+tig+4)*136 + mr + g    ];
                ah[mi][3] = Ah[(kk2+tig+4)*136 + mr + g + 8];
                al[mi][0] = Al[(kk2+tig  )*136 + mr + g    ];
                al[mi][1] = Al[(kk2+tig  )*136 + mr + g + 8];
                al[mi][2] = Al[(kk2+tig+4)*136 + mr + g    ];
                al[mi][3] = Al[(kk2+tig+4)*136 + mr + g + 8];
            }
#pragma unroll
            for (int ni = 0; ni < 4; ni++) {
                uint32_t bh[2], bl[2];
                bh[0] = Bh[(kk2+tig  )*72 + wn + ni*8 + g];
                bh[1] = Bh[(kk2+tig+4)*72 + wn + ni*8 + g];
                bl[0] = Bl[(kk2+tig  )*72 + wn + ni*8 + g];
                bl[1] = Bl[(kk2+tig+4)*72 + wn + ni*8 + g];
#pragma unroll
                for (int mi = 0; mi < 2; mi++) {
                    mma16bf(c[mi][ni], ah[mi], bh);
                    mma16bf(c[mi][ni], ah[mi], bl);
                    mma16bf(c[mi][ni], al[mi], bh);
                }
            }
        }
        __syncthreads();
        if (t < 3) storeT();
        __syncthreads();
    }

    float* Ep = g_E[b];
#pragma unroll
    for (int mi = 0; mi < 2; mi++) {
#pragma unroll
        for (int ni = 0; ni < 4; ni++) {
            int row = row0 + wm + mi * 16 + g;
            int col = col0 + wn + ni * 8 + tig * 2;
            *(float2*)&Ep[row * NPIX + col]       = make_float2(c[mi][ni][0], c[mi][ni][1]);
            *(float2*)&Ep[(row + 8) * NPIX + col] = make_float2(c[mi][ni][2], c[mi][ni][3]);
        }
    }

    // ---------- fused stats epilogue ----------
    __syncthreads();
    float* scol = (float*)pool;
    float* srow = (float*)pool + 512;
    int mw = wid & 3, nw = wid >> 2;

#pragma unroll
    for (int ni = 0; ni < 4; ni++) {
#pragma unroll
        for (int off = 0; off < 2; off++) {
            float v0 = c[0][ni][off], v1 = c[0][ni][off + 2];
            float v2 = c[1][ni][off], v3 = c[1][ni][off + 2];
            float mx = fmaxf(fmaxf(v0, v1), fmaxf(v2, v3));
            float s = __expf(v0 - mx) + __expf(v1 - mx) + __expf(v2 - mx) + __expf(v3 - mx);
#pragma unroll
            for (int sh = 4; sh <= 16; sh <<= 1) {
                float om = __shfl_xor_sync(0xffffffffu, mx, sh);
                float os = __shfl_xor_sync(0xffffffffu, s, sh);
                ms_merge(mx, s, om, os);
            }
            if (g == 0) {
                int lc = wn + ni * 8 + tig * 2 + off;
                scol[(mw * 64 + lc) * 2]     = mx;
                scol[(mw * 64 + lc) * 2 + 1] = s;
            }
        }
    }

#pragma unroll
    for (int mi = 0; mi < 2; mi++) {
#pragma unroll
        for (int r8 = 0; r8 < 2; r8++) {
            float mx = -3.0e38f, s = 0.f;
#pragma unroll
            for (int ni = 0; ni < 4; ni++) {
                float v0 = c[mi][ni][r8 * 2], v1 = c[mi][ni][r8 * 2 + 1];
                float m2 = fmaxf(v0, v1);
                ms_merge(mx, s, m2, __expf(v0 - m2) + __expf(v1 - m2));
            }
#pragma unroll
            for (int sh = 1; sh <= 2; sh <<= 1) {
                float om = __shfl_xor_sync(0xffffffffu, mx, sh);
                float os = __shfl_xor_sync(0xffffffffu, s, sh);
                ms_merge(mx, s, om, os);
            }
            if (tig == 0) {
                int lr = wm + mi * 16 + g + r8 * 8;
                srow[(nw * 128 + lr) * 2]     = mx;
                srow[(nw * 128 + lr) * 2 + 1] = s;
            }
        }
    }
    __syncthreads();

    int y = row0 >> 7, x = col0 >> 6;
    if (tid < 64) {
        float mx = scol[tid * 2], s = scol[tid * 2 + 1];
#pragma unroll
        for (int m = 1; m < 4; m++)
            ms_merge(mx, s, scol[(m * 64 + tid) * 2], scol[(m * 64 + tid) * 2 + 1]);
        g_pmax[b][y][col0 + tid] = mx;
        g_psum[b][y][col0 + tid] = s;
    } else if (tid >= 128 && tid < 256) {
        int r = tid - 128;
        float mx = srow[r * 2], s = srow[r * 2 + 1];
        ms_merge(mx, s, srow[(128 + r) * 2], srow[(128 + r) * 2 + 1]);
        g_rpmax[b][x][row0 + r] = mx;
        g_rpsum[b][x][row0 + r] = s;
    }
}

// ======================================================================
// k_softA
// ======================================================================
__global__ void __launch_bounds__(256) k_softA()
{
    int b = blockIdx.y;
    int orient = blockIdx.x & 1;
    int strip = blockIdx.x >> 1;
    int tid = threadIdx.x, wid = tid >> 5, lane = tid & 31;
    __shared__ float ETs[128][9];

    if (orient == 0) {
        int t = strip * 8 + wid;
        float v[4];
#pragma unroll
        for (int j = 0; j < 4; j++) {
            int d = lane + j * 32;
            float s = 0.f;
#pragma unroll
            for (int p = 0; p < ETSPLIT; p++) s += g_ETpart[b][p][t * CI + d];
            v[j] = s;
        }
        float mx = fmaxf(fmaxf(v[0], v[1]), fmaxf(v[2], v[3]));
#pragma unroll
        for (int off = 16; off; off >>= 1) mx = fmaxf(mx, __shfl_xor_sync(0xffffffffu, mx, off));
        float e[4]; float sum = 0.f;
#pragma unroll
        for (int j = 0; j < 4; j++) { e[j] = __expf(v[j] - mx); sum += e[j]; }
#pragma unroll
        for (int off = 16; off; off >>= 1) sum += __shfl_xor_sync(0xffffffffu, sum, off);
        float rs = 1.f / sum;
#pragma unroll
        for (int j = 0; j < 4; j++) {
            float own = e[j] * rs;
            float part = __shfl_xor_sync(0xffffffffu, own, 1);
            if (!(lane & 1)) {
                float oh = bf_round(own), ph = bf_round(part);
                int k2 = (lane >> 1) + 16 * j;
                g_Apack[1][b][0][t * 64 + k2] = pack_bf(oh, ph);
                g_Apack[1][b][1][t * 64 + k2] = pack_bf(own - oh, part - ph);
            }
        }
    } else {
        int c0 = strip * 8;
        for (int idx = tid; idx < 128 * 8; idx += 256) {
            int d = idx >> 3, cc = idx & 7;
            float s = 0.f;
#pragma unroll
            for (int p = 0; p < ETSPLIT; p++) s += g_ETpart[b][p][d * CI + c0 + cc];
            ETs[d][cc] = s;
        }
        __syncthreads();
        int ccol = c0 + wid;
        float v[4];
#pragma unroll
        for (int j = 0; j < 4; j++) v[j] = ETs[lane + 32 * j][wid];
        float mx = fmaxf(fmaxf(v[0], v[1]), fmaxf(v[2], v[3]));
#pragma unroll
        for (int off = 16; off; off >>= 1) mx = fmaxf(mx, __shfl_xor_sync(0xffffffffu, mx, off));
        float e[4]; float sum = 0.f;
#pragma unroll
        for (int j = 0; j < 4; j++) { e[j] = __expf(v[j] - mx); sum += e[j]; }
#pragma unroll
        for (int off = 16; off; off >>= 1) sum += __shfl_xor_sync(0xffffffffu, sum, off);
        float rs = 1.f / sum;
#pragma unroll
        for (int j = 0; j < 4; j++) {
            float own = e[j] * rs;
            float part = __shfl_xor_sync(0xffffffffu, own, 1);
            if (!(lane & 1)) {
                float oh = bf_round(own), ph = bf_round(part);
                int k2 = (lane >> 1) + 16 * j;
                g_Apack[0][b][0][ccol * 64 + k2] = pack_bf(oh, ph);
                g_Apack[0][b][1][ccol * 64 + k2] = pack_bf(own - oh, part - ph);
            }
        }
    }
}

// ======================================================================
// zgemm body (3-term, R15)
// ======================================================================
__device__ __forceinline__ void zgemm_body(uint32_t* pool, int zi, int b, int n0)
{
    uint32_t* Ah = pool;
    uint32_t* Al = pool + 2560;
    uint32_t* Bh = pool + 5120;
    uint32_t* Bl = pool + 6272;
    const uint32_t* __restrict__ AhG = g_Apack[zi][b][0];
    const uint32_t* __restrict__ AlG = g_Apack[zi][b][1];
    const float* __restrict__ Bsrc = g_PRE[zi][b];

    int tid = threadIdx.x;
    int wid = tid >> 5, lane = tid & 31;
    int g = lane >> 2, tig = lane & 3;
    int wm = (wid & 3) * 32, wn = (wid >> 2) * 32;

    int am = tid >> 1, half8 = (tid & 1) * 8;
    int bk2 = tid >> 4, bn4 = (tid & 15) * 4;

    uint4 sAh0, sAh1, sAl0, sAl1;
    float4 sbe, sbo;
    float c[2][4][4] = {};

    auto loadT = [&](int k0) {
        int k2b = (k0 >> 1) + half8;
        sAh0 = *(const uint4*)&AhG[am * 64 + k2b];
        sAh1 = *(const uint4*)&AhG[am * 64 + k2b + 4];
        sAl0 = *(const uint4*)&AlG[am * 64 + k2b];
        sAl1 = *(const uint4*)&AlG[am * 64 + k2b + 4];
        const float* be = &Bsrc[(k0 + 2 * bk2) * NPIX + n0 + bn4];
        sbe = *(const float4*)be;
        sbo = *(const float4*)(be + NPIX);
    };
    auto storeT = [&]() {
        *(uint4*)&Ah[am * 20 + half8]     = sAh0;
        *(uint4*)&Ah[am * 20 + half8 + 4] = sAh1;
        *(uint4*)&Al[am * 20 + half8]     = sAl0;
        *(uint4*)&Al[am * 20 + half8 + 4] = sAl1;
        uint32_t h0,l0,h1,l1,h2,l2,h3,l3;
        split_pack(sbe.x, sbo.x, h0, l0); split_pack(sbe.y, sbo.y, h1, l1);
        split_pack(sbe.z, sbo.z, h2, l2); split_pack(sbe.w, sbo.w, h3, l3);
        *(uint4*)&Bh[bk2 * 72 + bn4] = make_uint4(h0, h1, h2, h3);
        *(uint4*)&Bl[bk2 * 72 + bn4] = make_uint4(l0, l1, l2, l3);
    };

    loadT(0); storeT(); __syncthreads();
    for (int t = 0; t < 4; t++) {
        if (t < 3) loadT((t + 1) * 32);
#pragma unroll
        for (int kk2 = 0; kk2 < 16; kk2 += 8) {
            uint32_t ah[2][4], al[2][4];
#pragma unroll
            for (int mi = 0; mi < 2; mi++) {
                int mr = wm + mi * 16;
                ah[mi][0]=Ah[(mr+g  )*20+kk2+tig  ]; ah[mi][1]=Ah[(mr+g+8)*20+kk2+tig  ];
                ah[mi][2]=Ah[(mr+g  )*20+kk2+tig+4]; ah[mi][3]=Ah[(mr+g+8)*20+kk2+tig+4];
                al[mi][0]=Al[(mr+g  )*20+kk2+tig  ]; al[mi][1]=Al[(mr+g+8)*20+kk2+tig  ];
                al[mi][2]=Al[(mr+g  )*20+kk2+tig+4]; al[mi][3]=Al[(mr+g+8)*20+kk2+tig+4];
            }
#pragma unroll
            for (int ni = 0; ni < 4; ni++) {
                uint32_t bh[2], bl[2];
                bh[0]=Bh[(kk2+tig  )*72+wn+ni*8+g]; bh[1]=Bh[(kk2+tig+4)*72+wn+ni*8+g];
                bl[0]=Bl[(kk2+tig  )*72+wn+ni*8+g]; bl[1]=Bl[(kk2+tig+4)*72+wn+ni*8+g];
#pragma unroll
                for (int mi = 0; mi < 2; mi++) {
                    mma16bf(c[mi][ni], ah[mi], bh);
                    mma16bf(c[mi][ni], ah[mi], bl);
                    mma16bf(c[mi][ni], al[mi], bh);
                }
            }
        }
        __syncthreads();
        if (t < 3) storeT();
        __syncthreads();
    }

    uint32_t* Zout = g_Zpack[zi][b];
#pragma unroll
    for (int mi = 0; mi < 2; mi++) {
#pragma unroll
        for (int ni = 0; ni < 4; ni++) {
            int row = wm + mi * 16 + g;
            int colh = ((n0 + wn + ni * 8) >> 1) + tig;
            Zout[row * NPK2 + colh]       = pack_bf(c[mi][ni][0], c[mi][ni][1]);
            Zout[(row + 8) * NPK2 + colh] = pack_bf(c[mi][ni][2], c[mi][ni][3]);
        }
    }
}

// ======================================================================
// k_ez: espace (2592) | zgemm (288) = 2880 blocks
// ======================================================================
__global__ void __launch_bounds__(256) k_ez()
{
    __shared__ uint32_t pool[7424];
    int bx = blockIdx.x;
    if (bx < 2592) {
        int x = bx % 36, y = (bx / 36) % 18, b = bx / 648;
        espace_body(pool, b, y * 128, x * 64);
    } else {
        int idx = bx - 2592;
        int x = idx % 36, iz = idx / 36;
        zgemm_body(pool, iz >> 2, iz & 3, x * 64);
    }
}

// ======================================================================
// k_ygemm_fused: post phase now W(hi/lo) x Y(single bf16) = 2 MMAs.
// ======================================================================
__global__ void __launch_bounds__(256) k_ygemm_fused(const float* __restrict__ x1,
                                                     const float* __restrict__ x2,
                                                     float* __restrict__ out)
{
    __shared__ uint32_t pool[12032];
    __shared__ float s_max[64], s_rs[64];

    float*    Ysf = (float*)(pool + 3840);   // [128][64] fp32
    uint32_t* Ysh = pool + 3840;             // [64][64] packed bf16x2 (single)
    uint32_t* WAh = pool;                    // post: [128][10]
    uint32_t* WAl = pool + 1280;             // post: [128][10]

    int yi = blockIdx.z >> 2, b = blockIdx.z & 3;
    int n0 = blockIdx.x * 64;
    const uint32_t* __restrict__ Zp = g_Zpack[yi][b];
    const float* __restrict__ Ep = g_E[b];

    int tid = threadIdx.x;
    int wid = tid >> 5, lane = tid & 31;
    int g = lane >> 2, tig = lane & 3;
    int wm = (wid & 3) * 32, wn = (wid >> 2) * 32;

    if (tid < 64) {
        int m = n0 + tid;
        if (yi == 0) {
            float mx = g_pmax[b][0][m], s = g_psum[b][0][m];
#pragma unroll
            for (int ch = 1; ch < NCHUNK; ch++)
                ms_merge(mx, s, g_pmax[b][ch][m], g_psum[b][ch][m]);
            s_max[tid] = mx; s_rs[tid] = 1.f / s;
        } else {
            float mx = g_rpmax[b][0][m], s = g_rpsum[b][0][m];
#pragma unroll 5
            for (int x = 1; x < 36; x++)
                ms_merge(mx, s, g_rpmax[b][x][m], g_rpsum[b][x][m]);
            s_max[tid] = mx; s_rs[tid] = 1.f / s;
        }
    }
    __syncthreads();

    int am = tid >> 1, half8 = (tid & 1) * 8;
    int bk2g = tid >> 4, bn4 = (tid & 15) * 4;
    int bj = tid >> 2, bkq = (tid & 3) * 8;

    uint4 sZ0, sZ1;
    float4 sB0, sB1;
    float c[2][4][4] = {};

    auto loadT = [&](int k0) {
        int k2b = (k0 >> 1) + half8;
        sZ0 = *(const uint4*)&Zp[am * NPK2 + k2b];
        sZ1 = *(const uint4*)&Zp[am * NPK2 + k2b + 4];
        if (yi == 0) {
            const float* be = &Ep[(size_t)(k0 + 2 * bk2g) * NPIX + n0 + bn4];
            sB0 = *(const float4*)be;
            sB1 = *(const float4*)(be + NPIX);
        } else {
            const float* be = &Ep[(size_t)(n0 + bj) * NPIX + k0 + bkq];
            sB0 = *(const float4*)be;
            sB1 = *(const float4*)(be + 4);
        }
    };
    auto storeT = [&](int s) {
        uint32_t* A2m = pool + s * 3840;
        uint32_t* Bs  = A2m + 2560;
        *(uint4*)&A2m[am * 20 + half8]     = sZ0;
        *(uint4*)&A2m[am * 20 + half8 + 4] = sZ1;
        if (yi == 0) {
            float m0v = s_max[bn4], m1v = s_max[bn4+1], m2v = s_max[bn4+2], m3v = s_max[bn4+3];
            *(uint4*)&Bs[bk2g * 72 + bn4] = make_uint4(
                pack_bf(__expf(sB0.x - m0v), __expf(sB1.x - m0v)),
                pack_bf(__expf(sB0.y - m1v), __expf(sB1.y - m1v)),
                pack_bf(__expf(sB0.z - m2v), __expf(sB1.z - m2v)),
                pack_bf(__expf(sB0.w - m3v), __expf(sB1.w - m3v)));
        } else {
            float mx = s_max[bj];
            *(uint4*)&Bs[bj * 20 + (bkq >> 1)] = make_uint4(
                pack_bf(__expf(sB0.x - mx), __expf(sB0.y - mx)),
                pack_bf(__expf(sB0.z - mx), __expf(sB0.w - mx)),
                pack_bf(__expf(sB1.x - mx), __expf(sB1.y - mx)),
                pack_bf(__expf(sB1.z - mx), __expf(sB1.w - mx)));
        }
    };

    loadT(0); storeT(0); __syncthreads();
    for (int t = 0; t < 72; t++) {
        int cur = t & 1;
        uint32_t* A2m = pool + cur * 3840;
        uint32_t* Bs  = A2m + 2560;
        if (t < 71) loadT((t + 1) * 32);
#pragma unroll
        for (int kk2 = 0; kk2 < 16; kk2 += 8) {
            uint32_t a[2][4];
#pragma unroll
            for (int mi = 0; mi < 2; mi++) {
                int mr = wm + mi * 16;
                a[mi][0]=A2m[(mr+g  )*20+kk2+tig  ]; a[mi][1]=A2m[(mr+g+8)*20+kk2+tig  ];
                a[mi][2]=A2m[(mr+g  )*20+kk2+tig+4]; a[mi][3]=A2m[(mr+g+8)*20+kk2+tig+4];
            }
#pragma unroll
            for (int ni = 0; ni < 4; ni++) {
                uint32_t bb[2];
                if (yi == 0) {
                    bb[0] = Bs[(kk2+tig  ) * 72 + wn + ni*8 + g];
                    bb[1] = Bs[(kk2+tig+4) * 72 + wn + ni*8 + g];
                } else {
                    int nr = wn + ni * 8 + g;
                    bb[0] = Bs[nr * 20 + kk2 + tig    ];
                    bb[1] = Bs[nr * 20 + kk2 + tig + 4];
                }
                mma16bf(c[0][ni], a[0], bb);
                mma16bf(c[1][ni], a[1], bb);
            }
        }
        if (t < 71) storeT(1 - cur);
        __syncthreads();
    }

    // Y tile -> smem fp32 (scaled)
#pragma unroll
    for (int mi = 0; mi < 2; mi++) {
#pragma unroll
        for (int ni = 0; ni < 4; ni++) {
            int row = wm + mi * 16 + g;
            int col = wn + ni * 8 + tig * 2;
            Ysf[row * 64 + col]           = c[mi][ni][0] * s_rs[col];
            Ysf[row * 64 + col + 1]       = c[mi][ni][1] * s_rs[col + 1];
            Ysf[(row + 8) * 64 + col]     = c[mi][ni][2] * s_rs[col];
            Ysf[(row + 8) * 64 + col + 1] = c[mi][ni][3] * s_rs[col + 1];
        }
    }
    __syncthreads();

    // pack Y in place: fp32 [128][64] -> single bf16x2 [64][64]
    {
        int n = tid & 63, kq = tid >> 6;
        float fe[16], fo[16];
#pragma unroll
        for (int e = 0; e < 16; e++) {
            int k2 = kq * 16 + e;
            fe[e] = Ysf[(2 * k2) * 64 + n];
            fo[e] = Ysf[(2 * k2 + 1) * 64 + n];
        }
        __syncthreads();
#pragma unroll
        for (int e = 0; e < 16; e++) {
            int k2 = kq * 16 + e;
            Ysh[k2 * 64 + n] = pack_bf(fe[e], fo[e]);
        }
    }
    __syncthreads();

    // post GEMM: W 2-term x Y single + bias + residual
    const float* __restrict__ Wp = g_Wpost[yi];
    const float* xs = (yi ? x2 : x1) + b * CC * NPIX;
    float* op = out + (size_t)yi * BATCH * CC * NPIX + (size_t)b * CC * NPIX;
    int wm2 = tid >> 1, wsel = tid & 1;

    for (int hh = 0; hh < 2; hh++) {
        int m0 = hh * 128;
        float c2[2][4][4] = {};
        for (int kc = 0; kc < 8; kc++) {
            {
                const float* wr = &Wp[(m0 + wm2) * CI + kc * 16 + wsel * 8];
                float4 w0 = *(const float4*)wr;
                float4 w1 = *(const float4*)(wr + 4);
                uint32_t h0,l0,h1,l1,h2,l2,h3,l3;
                split_pack(w0.x, w0.y, h0, l0); split_pack(w0.z, w0.w, h1, l1);
                split_pack(w1.x, w1.y, h2, l2); split_pack(w1.z, w1.w, h3, l3);
                int base = wm2 * 10 + wsel * 4;
                WAh[base+0]=h0; WAh[base+1]=h1; WAh[base+2]=h2; WAh[base+3]=h3;
                WAl[base+0]=l0; WAl[base+1]=l1; WAl[base+2]=l2; WAl[base+3]=l3;
            }
            __syncthreads();
            uint32_t ah[2][4], al[2][4];
#pragma unroll
            for (int mi = 0; mi < 2; mi++) {
                int mr = wm + mi * 16;
                ah[mi][0]=WAh[(mr+g  )*10+tig  ]; ah[mi][1]=WAh[(mr+g+8)*10+tig  ];
                ah[mi][2]=WAh[(mr+g  )*10+tig+4]; ah[mi][3]=WAh[(mr+g+8)*10+tig+4];
                al[mi][0]=WAl[(mr+g  )*10+tig  ]; al[mi][1]=WAl[(mr+g+8)*10+tig  ];
                al[mi][2]=WAl[(mr+g  )*10+tig+4]; al[mi][3]=WAl[(mr+g+8)*10+tig+4];
            }
#pragma unroll
            for (int ni = 0; ni < 4; ni++) {
                uint32_t bh[2];
                bh[0] = Ysh[(kc*8+tig  )*64 + wn + ni*8 + g];
                bh[1] = Ysh[(kc*8+tig+4)*64 + wn + ni*8 + g];
#pragma unroll
                for (int mi = 0; mi < 2; mi++) {
                    mma16bf(c2[mi][ni], ah[mi], bh);
                    mma16bf(c2[mi][ni], al[mi], bh);
                }
            }
            __syncthreads();
        }
#pragma unroll
        for (int mi = 0; mi < 2; mi++) {
#pragma unroll
            for (int ni = 0; ni < 4; ni++) {
                int row = m0 + wm + mi * 16 + g;
                int col = n0 + wn + ni * 8 + tig * 2;
                float b0 = g_bpost[yi][row], b1 = g_bpost[yi][row + 8];
                float2 r0 = *(const float2*)&xs[row * NPIX + col];
                float2 r1 = *(const float2*)&xs[(row + 8) * NPIX + col];
                *(float2*)&op[row * NPIX + col] =
                    make_float2(c2[mi][ni][0] + b0 + r0.x, c2[mi][ni][1] + b0 + r0.y);
                *(float2*)&op[(row + 8) * NPIX + col] =
                    make_float2(c2[mi][ni][2] + b1 + r1.x, c2[mi][ni][3] + b1 + r1.y);
            }
        }
    }
}

// ---------------- launcher ----------------
extern "C" void kernel_launch(void* const* d_in, const int* in_sizes, int n_in,
                              void* d_out, int out_size)
{
    const float* x1      = (const float*)d_in[0];
    const float* x2      = (const float*)d_in[1];
    const float* bn_pre  = (const float*)d_in[2];
    const float* w_pre   = (const float*)d_in[3];
    const float* b_pre   = (const float*)d_in[4];
    const float* w_post  = (const float*)d_in[5];
    const float* b_post  = (const float*)d_in[6];
    const float* bn_post = (const float*)d_in[7];
    float* out = (float*)d_out;

    k_fold<<<128, 256>>>(bn_pre, w_pre, b_pre, w_post, b_post, bn_post);
    k_pre23<<<dim3(36, 1, 8), 256>>>(x1, x2);
    k_ep<<<432, 256>>>(x1, x2);
    k_softA<<<dim3(32, BATCH), 256>>>();
    k_ez<<<2880, 256>>>();
    k_ygemm_fused<<<dim3(36, 1, 8), 256>>>(x1, x2, out);
}